// round 3
// baseline (speedup 1.0000x reference)
#include <cuda_runtime.h>
#include <math.h>

// Problem constants
constexpr int CB  = 2048;   // batch
constexpr int CN  = 64;     // nodes (max_joints)
constexpr int CE  = 126;    // edges
constexpr int CD  = 128;    // node dim
constexpr int CED = 32;     // edge dim
constexpr int CF  = 2048;   // ffn dim
constexpr int CK1 = 2*CD + CED;  // 288

constexpr size_t MN = (size_t)CB * CN;      // 131072 node rows
constexpr size_t ME = (size_t)CB * CE;      // 258048 edge rows

constexpr size_t SZ_NORMED = MN * CD;
constexpr size_t SZ_HEDGE  = ME * 128;
constexpr size_t SZ_AGG    = MN * CED;
constexpr size_t SZ_RUC    = MN * CD;

// Scratch (device globals; total ~620 MB)
__device__ float g_normed[SZ_NORMED];
__device__ float g_hedge [SZ_HEDGE];
__device__ float g_agg   [SZ_AGG];
__device__ float g_counts[CN];
__device__ float g_proj  [SZ_RUC];
__device__ float g_r     [SZ_RUC];
__device__ float g_u     [SZ_RUC];
__device__ float g_cand  [SZ_RUC];
__device__ float g_x     [SZ_RUC];
__device__ float g_n2    [SZ_RUC];

// ---------------------------------------------------------------------------
// Generic tiled fp32 GEMM: C[M,N] = act(A[M,K] @ W[K,N] + bias[N])
// 64x64 tile, 4x4 register blocking. ACT: 0=none 1=relu 2=sigmoid 3=tanh
// ---------------------------------------------------------------------------
template<int ACT>
__global__ void __launch_bounds__(256) gemm_k(
    const float* __restrict__ A, const float* __restrict__ W,
    const float* __restrict__ bias,
    float* __restrict__ C, int M, int N, int K)
{
    __shared__ float As[16][68];
    __shared__ float Bs[16][64];

    const int tid = threadIdx.x;
    const int tx = tid & 15;
    const int ty = tid >> 4;
    const int rowBase = blockIdx.y * 64;
    const int colBase = blockIdx.x * 64;

    float acc[4][4];
#pragma unroll
    for (int i = 0; i < 4; i++)
#pragma unroll
        for (int j = 0; j < 4; j++) acc[i][j] = 0.f;

    for (int k0 = 0; k0 < K; k0 += 16) {
#pragma unroll
        for (int i = 0; i < 4; i++) {
            int e = tid + 256 * i;
            int r = e >> 4, c = e & 15;
            As[c][r] = A[(size_t)(rowBase + r) * K + (k0 + c)];
        }
#pragma unroll
        for (int i = 0; i < 4; i++) {
            int e = tid + 256 * i;
            int r = e >> 6, c = e & 63;
            int gc = colBase + c;
            Bs[r][c] = (gc < N) ? W[(size_t)(k0 + r) * N + gc] : 0.f;
        }
        __syncthreads();
#pragma unroll
        for (int k = 0; k < 16; k++) {
            float a[4], b[4];
#pragma unroll
            for (int i = 0; i < 4; i++) a[i] = As[k][ty + 16 * i];
#pragma unroll
            for (int j = 0; j < 4; j++) b[j] = Bs[k][tx + 16 * j];
#pragma unroll
            for (int i = 0; i < 4; i++)
#pragma unroll
                for (int j = 0; j < 4; j++)
                    acc[i][j] = fmaf(a[i], b[j], acc[i][j]);
        }
        __syncthreads();
    }

#pragma unroll
    for (int i = 0; i < 4; i++) {
        int r = rowBase + ty + 16 * i;
#pragma unroll
        for (int j = 0; j < 4; j++) {
            int c = colBase + tx + 16 * j;
            if (c < N) {
                float v = acc[i][j] + bias[c];
                if (ACT == 1) v = fmaxf(v, 0.f);
                else if (ACT == 2) v = 1.f / (1.f + expf(-v));
                else if (ACT == 3) v = tanhf(v);
                C[(size_t)r * N + c] = v;
            }
        }
    }
}

// ---------------------------------------------------------------------------
// Edge GEMM 1 with fused gather: A row (edge be=b*126+e) is
// [normed[b,src[e]] | normed[b,tgt[e]] | edge_attr[b,e]], K=288, N=128.
// K-region boundaries (128,256) are multiples of 16 -> uniform source per k0.
// ---------------------------------------------------------------------------
__global__ void __launch_bounds__(256) gemm_edge1_k(
    const float* __restrict__ normed, const float* __restrict__ edge_attr,
    const int* __restrict__ srcI, const int* __restrict__ tgtI,
    const float* __restrict__ W, const float* __restrict__ bias,
    float* __restrict__ C)
{
    __shared__ float As[16][68];
    __shared__ float Bs[16][64];
    __shared__ int srcb[64], tgtb[64], eab[64];

    const int tid = threadIdx.x;
    const int tx = tid & 15;
    const int ty = tid >> 4;
    const size_t rowBase = (size_t)blockIdx.y * 64;
    const int colBase = blockIdx.x * 64;

    if (tid < 64) {
        size_t row = rowBase + tid;
        int b = (int)(row / CE);
        int e = (int)(row - (size_t)b * CE);
        srcb[tid] = (b * CN + srcI[e]) * CD;
        tgtb[tid] = (b * CN + tgtI[e]) * CD;
        eab[tid]  = (int)row * CED;
    }
    __syncthreads();

    float acc[4][4];
#pragma unroll
    for (int i = 0; i < 4; i++)
#pragma unroll
        for (int j = 0; j < 4; j++) acc[i][j] = 0.f;

    for (int k0 = 0; k0 < CK1; k0 += 16) {
#pragma unroll
        for (int i = 0; i < 4; i++) {
            int e = tid + 256 * i;
            int r = e >> 4, c = e & 15;
            float v;
            if (k0 < 128)      v = normed[srcb[r] + k0 + c];
            else if (k0 < 256) v = normed[tgtb[r] + (k0 - 128) + c];
            else               v = edge_attr[eab[r] + (k0 - 256) + c];
            As[c][r] = v;
        }
#pragma unroll
        for (int i = 0; i < 4; i++) {
            int e = tid + 256 * i;
            int r = e >> 6, c = e & 63;
            Bs[r][c] = W[(size_t)(k0 + r) * CD + colBase + c];
        }
        __syncthreads();
#pragma unroll
        for (int k = 0; k < 16; k++) {
            float a[4], b[4];
#pragma unroll
            for (int i = 0; i < 4; i++) a[i] = As[k][ty + 16 * i];
#pragma unroll
            for (int j = 0; j < 4; j++) b[j] = Bs[k][tx + 16 * j];
#pragma unroll
            for (int i = 0; i < 4; i++)
#pragma unroll
                for (int j = 0; j < 4; j++)
                    acc[i][j] = fmaf(a[i], b[j], acc[i][j]);
        }
        __syncthreads();
    }

#pragma unroll
    for (int i = 0; i < 4; i++) {
        size_t r = rowBase + ty + 16 * i;
#pragma unroll
        for (int j = 0; j < 4; j++) {
            int c = colBase + tx + 16 * j;
            float v = acc[i][j] + bias[c];
            C[r * CD + c] = fmaxf(v, 0.f);   // relu
        }
    }
}

// ---------------------------------------------------------------------------
// GRU GEMM with fused concat A = [a1 (*a2 if MODE==2) | a3], K=256, N=128.
// MODE 1: [normed | proj]   MODE 2: [r*normed | proj]
// ACT: 2=sigmoid 3=tanh
// ---------------------------------------------------------------------------
template<int ACT, int MODE>
__global__ void __launch_bounds__(256) gemm_gru_k(
    const float* __restrict__ a1, const float* __restrict__ a2,
    const float* __restrict__ a3,
    const float* __restrict__ W, const float* __restrict__ bias,
    float* __restrict__ C)
{
    __shared__ float As[16][68];
    __shared__ float Bs[16][64];

    const int tid = threadIdx.x;
    const int tx = tid & 15;
    const int ty = tid >> 4;
    const size_t rowBase = (size_t)blockIdx.y * 64;
    const int colBase = blockIdx.x * 64;

    float acc[4][4];
#pragma unroll
    for (int i = 0; i < 4; i++)
#pragma unroll
        for (int j = 0; j < 4; j++) acc[i][j] = 0.f;

    for (int k0 = 0; k0 < 256; k0 += 16) {
#pragma unroll
        for (int i = 0; i < 4; i++) {
            int e = tid + 256 * i;
            int r = e >> 4, c = e & 15;
            size_t base = (rowBase + r) * 128;
            float v;
            if (k0 < 128) {
                v = a1[base + k0 + c];
                if (MODE == 2) v *= a2[base + k0 + c];
            } else {
                v = a3[base + (k0 - 128) + c];
            }
            As[c][r] = v;
        }
#pragma unroll
        for (int i = 0; i < 4; i++) {
            int e = tid + 256 * i;
            int r = e >> 6, c = e & 63;
            Bs[r][c] = W[(size_t)(k0 + r) * CD + colBase + c];
        }
        __syncthreads();
#pragma unroll
        for (int k = 0; k < 16; k++) {
            float a[4], b[4];
#pragma unroll
            for (int i = 0; i < 4; i++) a[i] = As[k][ty + 16 * i];
#pragma unroll
            for (int j = 0; j < 4; j++) b[j] = Bs[k][tx + 16 * j];
#pragma unroll
            for (int i = 0; i < 4; i++)
#pragma unroll
                for (int j = 0; j < 4; j++)
                    acc[i][j] = fmaf(a[i], b[j], acc[i][j]);
        }
        __syncthreads();
    }

#pragma unroll
    for (int i = 0; i < 4; i++) {
        size_t r = rowBase + ty + 16 * i;
#pragma unroll
        for (int j = 0; j < 4; j++) {
            int c = colBase + tx + 16 * j;
            float v = acc[i][j] + bias[c];
            if (ACT == 2) v = 1.f / (1.f + expf(-v));
            else if (ACT == 3) v = tanhf(v);
            C[r * CD + c] = v;
        }
    }
}

// ---------------------------------------------------------------------------
// proj GEMM with fused count-normalization: A[row,k] = agg[row,k]/max(cnt,1).
// Rows within a 64-tile map 1:1 to node index (N=64). K=32, N=128.
// ---------------------------------------------------------------------------
__global__ void __launch_bounds__(256) gemm_proj_k(
    const float* __restrict__ agg, const float* __restrict__ counts,
    const float* __restrict__ W, const float* __restrict__ bias,
    float* __restrict__ C)
{
    __shared__ float As[16][68];
    __shared__ float Bs[16][64];
    __shared__ float rcnt[64];

    const int tid = threadIdx.x;
    const int tx = tid & 15;
    const int ty = tid >> 4;
    const size_t rowBase = (size_t)blockIdx.y * 64;
    const int colBase = blockIdx.x * 64;

    if (tid < 64) rcnt[tid] = 1.f / fmaxf(counts[tid], 1.f);
    __syncthreads();

    float acc[4][4];
#pragma unroll
    for (int i = 0; i < 4; i++)
#pragma unroll
        for (int j = 0; j < 4; j++) acc[i][j] = 0.f;

    for (int k0 = 0; k0 < 32; k0 += 16) {
#pragma unroll
        for (int i = 0; i < 4; i++) {
            int e = tid + 256 * i;
            int r = e >> 4, c = e & 15;
            As[c][r] = agg[(rowBase + r) * 32 + k0 + c] * rcnt[r];
        }
#pragma unroll
        for (int i = 0; i < 4; i++) {
            int e = tid + 256 * i;
            int r = e >> 6, c = e & 63;
            Bs[r][c] = W[(size_t)(k0 + r) * CD + colBase + c];
        }
        __syncthreads();
#pragma unroll
        for (int k = 0; k < 16; k++) {
            float a[4], b[4];
#pragma unroll
            for (int i = 0; i < 4; i++) a[i] = As[k][ty + 16 * i];
#pragma unroll
            for (int j = 0; j < 4; j++) b[j] = Bs[k][tx + 16 * j];
#pragma unroll
            for (int i = 0; i < 4; i++)
#pragma unroll
                for (int j = 0; j < 4; j++)
                    acc[i][j] = fmaf(a[i], b[j], acc[i][j]);
        }
        __syncthreads();
    }

#pragma unroll
    for (int i = 0; i < 4; i++) {
        size_t r = rowBase + ty + 16 * i;
#pragma unroll
        for (int j = 0; j < 4; j++) {
            int c = colBase + tx + 16 * j;
            C[r * CD + c] = acc[i][j] + bias[c];
        }
    }
}

// ---------------------------------------------------------------------------
// Fused FFN: out = x + gelu(n2 @ W1 + b1) @ W2 + b2   (64 rows / block)
// ---------------------------------------------------------------------------
constexpr int FFN_SMEM = (128 * 68 + 64 * 68 + 8192) * 4;   // 84,224 B

__global__ void __launch_bounds__(256) ffn_fused_k(
    const float* __restrict__ n2, const float* __restrict__ w1,
    const float* __restrict__ b1, const float* __restrict__ w2,
    const float* __restrict__ b2, const float* __restrict__ xres,
    float* __restrict__ out)
{
    extern __shared__ float sm[];
    float* At = sm;               // [128][68]
    float* Hs = At + 128 * 68;    // [64][68]
    float* Ws = Hs + 64 * 68;     // 8192 floats

    const int tid = threadIdx.x;
    const int tx = tid & 15;
    const int ty = tid >> 4;
    const size_t rowBase = (size_t)blockIdx.x * 64;

#pragma unroll
    for (int i = 0; i < 32; i++) {
        int e = tid + 256 * i;
        int r = e >> 7, c = e & 127;
        At[c * 68 + r] = n2[(rowBase + r) * 128 + c];
    }

    float acc[4][8];
#pragma unroll
    for (int i = 0; i < 4; i++)
#pragma unroll
        for (int j = 0; j < 8; j++) acc[i][j] = 0.f;

    __syncthreads();

    for (int chunk = 0; chunk < 32; chunk++) {
#pragma unroll
        for (int i = 0; i < 8; i++) {
            int e = tid + 256 * i;
            int k = e >> 4, c4 = e & 15;
            reinterpret_cast<float4*>(Ws)[k * 16 + c4] =
                reinterpret_cast<const float4*>(w1 + (size_t)k * 2048 + chunk * 64)[c4];
        }
        __syncthreads();

        {
            float acc1[4][4];
#pragma unroll
            for (int i = 0; i < 4; i++)
#pragma unroll
                for (int j = 0; j < 4; j++) acc1[i][j] = 0.f;
#pragma unroll 4
            for (int k = 0; k < 128; k++) {
                float4 a = *reinterpret_cast<const float4*>(&At[k * 68 + 4 * ty]);
                float4 b = *reinterpret_cast<const float4*>(&Ws[k * 64 + 4 * tx]);
                float av[4] = {a.x, a.y, a.z, a.w};
                float bv[4] = {b.x, b.y, b.z, b.w};
#pragma unroll
                for (int i = 0; i < 4; i++)
#pragma unroll
                    for (int j = 0; j < 4; j++)
                        acc1[i][j] = fmaf(av[i], bv[j], acc1[i][j]);
            }
#pragma unroll
            for (int i = 0; i < 4; i++) {
                float4 hv;
                float* hp = &hv.x;
#pragma unroll
                for (int j = 0; j < 4; j++) {
                    float v = acc1[i][j] + b1[chunk * 64 + 4 * tx + j];
                    hp[j] = 0.5f * v * (1.f + erff(v * 0.70710678118654752f));
                }
                *reinterpret_cast<float4*>(&Hs[(4 * ty + i) * 68 + 4 * tx]) = hv;
            }
        }
        __syncthreads();

#pragma unroll
        for (int i = 0; i < 8; i++) {
            int e = tid + 256 * i;
            int r = e >> 5, c4 = e & 31;
            reinterpret_cast<float4*>(Ws)[r * 32 + c4] =
                reinterpret_cast<const float4*>(w2 + (size_t)(chunk * 64 + r) * 128)[c4];
        }
        __syncthreads();

#pragma unroll 2
        for (int kk = 0; kk < 64; kk++) {
            float a[4];
#pragma unroll
            for (int i = 0; i < 4; i++) a[i] = Hs[(4 * ty + i) * 68 + kk];
            float4 b0 = *reinterpret_cast<const float4*>(&Ws[kk * 128 + 8 * tx]);
            float4 b1v = *reinterpret_cast<const float4*>(&Ws[kk * 128 + 8 * tx + 4]);
            float bv[8] = {b0.x, b0.y, b0.z, b0.w, b1v.x, b1v.y, b1v.z, b1v.w};
#pragma unroll
            for (int i = 0; i < 4; i++)
#pragma unroll
                for (int j = 0; j < 8; j++)
                    acc[i][j] = fmaf(a[i], bv[j], acc[i][j]);
        }
        __syncthreads();
    }

#pragma unroll
    for (int i = 0; i < 4; i++) {
        size_t r = rowBase + 4 * ty + i;
#pragma unroll
        for (int jj = 0; jj < 2; jj++) {
            int c0 = 8 * tx + 4 * jj;
            float4 xr = *reinterpret_cast<const float4*>(&xres[r * 128 + c0]);
            float4 o;
            o.x = acc[i][4 * jj + 0] + b2[c0 + 0] + xr.x;
            o.y = acc[i][4 * jj + 1] + b2[c0 + 1] + xr.y;
            o.z = acc[i][4 * jj + 2] + b2[c0 + 2] + xr.z;
            o.w = acc[i][4 * jj + 3] + b2[c0 + 3] + xr.w;
            *reinterpret_cast<float4*>(&out[r * 128 + c0]) = o;
        }
    }
}

// ---------------------------------------------------------------------------
// LayerNorm (128-wide rows)
// ---------------------------------------------------------------------------
__global__ void ln_k(const float* __restrict__ in, const float* __restrict__ g,
                     const float* __restrict__ bb, float* __restrict__ out)
{
    const size_t row = blockIdx.x;
    const int d = threadIdx.x;
    float v = in[row * 128 + d];
    float s = v;
#pragma unroll
    for (int o = 16; o > 0; o >>= 1) s += __shfl_xor_sync(~0u, s, o);
    __shared__ float sm[4], sq[4];
    int w = d >> 5, l = d & 31;
    if (l == 0) sm[w] = s;
    __syncthreads();
    float mean = (sm[0] + sm[1] + sm[2] + sm[3]) * (1.f / 128.f);
    float dv = v - mean;
    float q = dv * dv;
#pragma unroll
    for (int o = 16; o > 0; o >>= 1) q += __shfl_xor_sync(~0u, q, o);
    if (l == 0) sq[w] = q;
    __syncthreads();
    float var = (sq[0] + sq[1] + sq[2] + sq[3]) * (1.f / 128.f);
    out[row * 128 + d] = dv * rsqrtf(var + 1e-5f) * g[d] + bb[d];
}

// GRU combine + LN2
__global__ void gru_ln2_k(const float* __restrict__ nf, const float* __restrict__ normed,
                          const float* __restrict__ u, const float* __restrict__ cand,
                          const float* __restrict__ g, const float* __restrict__ bb,
                          float* __restrict__ x_out, float* __restrict__ n2_out)
{
    const size_t row = blockIdx.x;
    const int d = threadIdx.x;
    size_t i = row * 128 + d;
    float uu = u[i];
    float xv = nf[i] + (1.f - uu) * normed[i] + uu * cand[i];
    x_out[i] = xv;
    float s = xv;
#pragma unroll
    for (int o = 16; o > 0; o >>= 1) s += __shfl_xor_sync(~0u, s, o);
    __shared__ float sm[4], sq[4];
    int w = d >> 5, l = d & 31;
    if (l == 0) sm[w] = s;
    __syncthreads();
    float mean = (sm[0] + sm[1] + sm[2] + sm[3]) * (1.f / 128.f);
    float dv = xv - mean;
    float q = dv * dv;
#pragma unroll
    for (int o = 16; o > 0; o >>= 1) q += __shfl_xor_sync(~0u, q, o);
    if (l == 0) sq[w] = q;
    __syncthreads();
    float var = (sq[0] + sq[1] + sq[2] + sq[3]) * (1.f / 128.f);
    n2_out[i] = dv * rsqrtf(var + 1e-5f) * g[d] + bb[d];
}

__global__ void counts_k(const int* __restrict__ tgt, float* __restrict__ counts)
{
    int e = threadIdx.x;
    if (e < CE) atomicAdd(&counts[tgt[e]], 1.f);
}

// mask-multiply (in place on out_msgs) + scatter into agg
__global__ void edge_post_k(float* __restrict__ msgs, const float* __restrict__ mask,
                            const int* __restrict__ tgt, float* __restrict__ agg)
{
    size_t idx = (size_t)blockIdx.x * blockDim.x + threadIdx.x;
    int c = (int)(idx & 31);
    size_t be = idx >> 5;
    int e = (int)(be % CE);
    size_t b = be / CE;
    float m = msgs[idx] * mask[be];
    msgs[idx] = m;
    atomicAdd(&agg[(b * CN + tgt[e]) * CED + c], m);
}

// ---------------------------------------------------------------------------
extern "C" void kernel_launch(void* const* d_in, const int* in_sizes, int n_in,
                              void* d_out, int out_size)
{
    const float* nf        = (const float*)d_in[0];
    const float* edge_attr = (const float*)d_in[1];
    const int*   src       = (const int*)  d_in[2];
    const int*   tgt       = (const int*)  d_in[3];
    const float* mask      = (const float*)d_in[4];
    // d_in[5] = max_joints scalar
    const float* e_w1   = (const float*)d_in[6];
    const float* e_b1   = (const float*)d_in[7];
    const float* e_w2   = (const float*)d_in[8];
    const float* e_b2   = (const float*)d_in[9];
    const float* proj_w = (const float*)d_in[10];
    const float* proj_b = (const float*)d_in[11];
    const float* r_w    = (const float*)d_in[12];
    const float* r_b    = (const float*)d_in[13];
    const float* u_w    = (const float*)d_in[14];
    const float* u_b    = (const float*)d_in[15];
    const float* c_w    = (const float*)d_in[16];
    const float* c_b    = (const float*)d_in[17];
    const float* n1_g   = (const float*)d_in[18];
    const float* n1_b   = (const float*)d_in[19];
    const float* n2_g   = (const float*)d_in[20];
    const float* n2_b   = (const float*)d_in[21];
    const float* f_w1   = (const float*)d_in[22];
    const float* f_b1   = (const float*)d_in[23];
    const float* f_w2   = (const float*)d_in[24];
    const float* f_b2   = (const float*)d_in[25];

    float* out_x    = (float*)d_out;
    float* out_msgs = out_x + SZ_NORMED;

    float *p_normed, *p_hedge, *p_agg, *p_counts, *p_proj,
          *p_r, *p_u, *p_cand, *p_x, *p_n2;
    cudaGetSymbolAddress((void**)&p_normed, g_normed);
    cudaGetSymbolAddress((void**)&p_hedge,  g_hedge);
    cudaGetSymbolAddress((void**)&p_agg,    g_agg);
    cudaGetSymbolAddress((void**)&p_counts, g_counts);
    cudaGetSymbolAddress((void**)&p_proj,   g_proj);
    cudaGetSymbolAddress((void**)&p_r,      g_r);
    cudaGetSymbolAddress((void**)&p_u,      g_u);
    cudaGetSymbolAddress((void**)&p_cand,   g_cand);
    cudaGetSymbolAddress((void**)&p_x,      g_x);
    cudaGetSymbolAddress((void**)&p_n2,     g_n2);

    cudaFuncSetAttribute(ffn_fused_k, cudaFuncAttributeMaxDynamicSharedMemorySize, FFN_SMEM);

    // Zero scatter targets each replay
    cudaMemsetAsync(p_agg, 0, SZ_AGG * sizeof(float));
    cudaMemsetAsync(p_counts, 0, CN * sizeof(float));

    // 1. LN1
    ln_k<<<(unsigned)MN, 128>>>(nf, n1_g, n1_b, p_normed);

    // 2. counts
    counts_k<<<1, 128>>>(tgt, p_counts);

    // 3. h = relu([normed_src|normed_tgt|edge_attr] @ e_w1 + e_b1)  (gather fused)
    gemm_edge1_k<<<dim3(2, (unsigned)(ME / 64)), 256>>>(
        p_normed, edge_attr, src, tgt, e_w1, e_b1, p_hedge);

    // 4. msgs_raw = h @ e_w2 + e_b2 -> out_msgs  (M=ME, N=32, K=128)
    gemm_k<0><<<dim3(1, (unsigned)(ME / 64)), 256>>>(
        p_hedge, e_w2, e_b2, out_msgs, (int)ME, 32, 128);

    // 5. mask multiply + scatter into agg
    edge_post_k<<<(unsigned)((ME * 32) / 256), 256>>>(out_msgs, mask, tgt, p_agg);

    // 6. proj = (agg/cnt) @ proj_w + proj_b  (count-norm fused)
    gemm_proj_k<<<dim3(2, (unsigned)(MN / 64)), 256>>>(
        p_agg, p_counts, proj_w, proj_b, p_proj);

    // 7. r = sigmoid([normed|proj] @ r_w + r_b); u likewise  (concat fused)
    gemm_gru_k<2, 1><<<dim3(2, (unsigned)(MN / 64)), 256>>>(
        p_normed, nullptr, p_proj, r_w, r_b, p_r);
    gemm_gru_k<2, 1><<<dim3(2, (unsigned)(MN / 64)), 256>>>(
        p_normed, nullptr, p_proj, u_w, u_b, p_u);

    // 8. cand = tanh([r*normed|proj] @ c_w + c_b)  (concat+mul fused)
    gemm_gru_k<3, 2><<<dim3(2, (unsigned)(MN / 64)), 256>>>(
        p_normed, p_r, p_proj, c_w, c_b, p_cand);

    // 9. x = nf + (1-u)*normed + u*cand ; n2 = LN(x)
    gru_ln2_k<<<(unsigned)MN, 128>>>(nf, p_normed, p_u, p_cand, n2_g, n2_b, p_x, p_n2);

    // 10. fused FFN: out_x = x + gelu(n2 @ f_w1 + f_b1) @ f_w2 + f_b2
    ffn_fused_k<<<(unsigned)(MN / 64), 256, FFN_SMEM>>>(
        p_n2, f_w1, f_b1, f_w2, f_b2, p_x, out_x);
}

// round 4
// speedup vs baseline: 1.5431x; 1.5431x over previous
#include <cuda_runtime.h>
#include <cuda_bf16.h>
#include <math.h>
#include <stdint.h>

// Problem constants
constexpr int CB  = 2048;
constexpr int CN  = 64;
constexpr int CE  = 126;
constexpr int CD  = 128;
constexpr int CED = 32;
constexpr int CF  = 2048;
constexpr int CK1 = 2*CD + CED;  // 288

constexpr size_t MN = (size_t)CB * CN;      // 131072
constexpr size_t ME = (size_t)CB * CE;      // 258048

constexpr size_t SZ_NORMED = MN * CD;
constexpr size_t SZ_AGG    = MN * CED;
constexpr size_t SZ_RUC    = MN * CD;

// Scratch (device globals; ~490 MB total)
__device__ float g_normed[SZ_NORMED];
__device__ float g_agg   [SZ_AGG];
__device__ float g_counts[CN];
__device__ float g_proj  [SZ_RUC];
__device__ float g_r     [SZ_RUC];
__device__ float g_u     [SZ_RUC];
__device__ float g_cand  [SZ_RUC];
__device__ float g_x     [SZ_RUC];
__device__ float g_n2    [SZ_RUC];

// ---------------------------------------------------------------------------
// Tensor-core helpers (mma.sync m16n8k16 bf16, fp32 accum) + split precision
// ---------------------------------------------------------------------------
__device__ __forceinline__ void ldsm4(uint32_t (&r)[4], const void* p) {
    uint32_t a = (uint32_t)__cvta_generic_to_shared(p);
    asm volatile("ldmatrix.sync.aligned.m8n8.x4.shared.b16 {%0,%1,%2,%3}, [%4];"
        : "=r"(r[0]), "=r"(r[1]), "=r"(r[2]), "=r"(r[3]) : "r"(a));
}

__device__ __forceinline__ void mma_bf16(float* d, const uint32_t* a,
                                         uint32_t b0, uint32_t b1) {
    asm volatile(
        "mma.sync.aligned.m16n8k16.row.col.f32.bf16.bf16.f32 "
        "{%0,%1,%2,%3},{%4,%5,%6,%7},{%8,%9},{%0,%1,%2,%3};"
        : "+f"(d[0]), "+f"(d[1]), "+f"(d[2]), "+f"(d[3])
        : "r"(a[0]), "r"(a[1]), "r"(a[2]), "r"(a[3]), "r"(b0), "r"(b1));
}

__device__ __forceinline__ void split_bf16(float f, __nv_bfloat16& h, __nv_bfloat16& l) {
    h = __float2bfloat16(f);
    l = __float2bfloat16(f - __bfloat162float(h));
}

__device__ __forceinline__ float gelu_f(float v) {
    return 0.5f * v * (1.f + erff(v * 0.70710678118654752f));
}

// ---------------------------------------------------------------------------
// Tensor-core fused FFN: out = xres + gelu(n2 @ W1 + b1) @ W2 + b2
// 128 rows/block, 512 threads (16 warps), 32 chunks of 64 FFN cols.
// Split-bf16 (hi+lo) 3-term MMA for ~fp32-grade accuracy.
// ---------------------------------------------------------------------------
constexpr int F_AS = 136;                   // A k-stride (bf16 elems), 272B rows
constexpr int F_HS = 72;                    // H/W2 k-stride, 144B rows
constexpr int F_ASZ = 128 * F_AS;           // 17408
constexpr int F_HSZ = 128 * F_HS;           // 9216
constexpr int F_WSZ = 128 * F_HS;           // 9216 (stage1 needs 64*136=8704 <= this)
constexpr size_t FFN_SMEM = (size_t)(2*F_ASZ + 2*F_HSZ + 2*F_WSZ) * 2;  // 143,360 B

__global__ void __launch_bounds__(512) ffn_tc_k(
    const float* __restrict__ n2, const float* __restrict__ w1,
    const float* __restrict__ b1, const float* __restrict__ w2,
    const float* __restrict__ b2, const float* __restrict__ xres,
    float* __restrict__ out)
{
    extern __shared__ __nv_bfloat16 sb[];
    __nv_bfloat16* Ah = sb;
    __nv_bfloat16* Al = Ah + F_ASZ;
    __nv_bfloat16* Hh = Al + F_ASZ;
    __nv_bfloat16* Hl = Hh + F_HSZ;
    __nv_bfloat16* Wh = Hl + F_HSZ;
    __nv_bfloat16* Wl = Wh + F_WSZ;

    const int tid  = threadIdx.x;
    const int lane = tid & 31;
    const int wrp  = tid >> 5;
    const int wm   = wrp & 7;        // m tile (16 rows)
    const int wn   = wrp >> 3;       // n half
    const int m0   = wm * 16;
    const size_t rowBase = (size_t)blockIdx.x * 128;

    // lane-derived ldmatrix offsets
    const int lr = lane & 15;        // row within 16
    const int lk = (lane >> 4) * 8;  // k half offset

    // Load A (n2 tile 128x128) once, split hi/lo
#pragma unroll
    for (int i = 0; i < 32; i++) {
        int e = tid + 512 * i;
        int r = e >> 7, k = e & 127;
        float f = n2[(rowBase + r) * 128 + k];
        __nv_bfloat16 h, l; split_bf16(f, h, l);
        Ah[r * F_AS + k] = h;
        Al[r * F_AS + k] = l;
    }

    float acc2[32];                  // stage2: 16 x 64 per warp (8 n8-tiles)
#pragma unroll
    for (int i = 0; i < 32; i++) acc2[i] = 0.f;

    const int n1base = wn * 32;      // stage1 warp n-origin (h is 128x64)
    const int n2base = wn * 64;      // stage2 warp n-origin (out is 128x128)

    __syncthreads();

    for (int ch = 0; ch < 32; ch++) {
        // ---- load W1 chunk [128k x 64n] -> Wh/Wl [n][k] stride F_AS ----
#pragma unroll
        for (int i = 0; i < 16; i++) {
            int e = tid + 512 * i;
            int k = e >> 6, n = e & 63;
            float f = w1[(size_t)k * 2048 + ch * 64 + n];
            __nv_bfloat16 h, l; split_bf16(f, h, l);
            Wh[n * F_AS + k] = h;
            Wl[n * F_AS + k] = l;
        }
        __syncthreads();

        // ---- stage 1: acc1 = A(128x128) @ W1chunk -> h(128x64) ----
        float acc1[16];
#pragma unroll
        for (int i = 0; i < 16; i++) acc1[i] = 0.f;

#pragma unroll
        for (int ks = 0; ks < 8; ks++) {
            uint32_t ah[4], al[4];
            ldsm4(ah, &Ah[(m0 + lr) * F_AS + ks * 16 + lk]);
            ldsm4(al, &Al[(m0 + lr) * F_AS + ks * 16 + lk]);
#pragma unroll
            for (int g = 0; g < 2; g++) {
                uint32_t bh[4], bl[4];
                ldsm4(bh, &Wh[(n1base + g * 16 + lr) * F_AS + ks * 16 + lk]);
                ldsm4(bl, &Wl[(n1base + g * 16 + lr) * F_AS + ks * 16 + lk]);
                float* d0 = &acc1[(g * 2 + 0) * 4];
                float* d1 = &acc1[(g * 2 + 1) * 4];
                mma_bf16(d0, ah, bh[0], bh[2]);
                mma_bf16(d0, ah, bl[0], bl[2]);
                mma_bf16(d0, al, bh[0], bh[2]);
                mma_bf16(d1, ah, bh[1], bh[3]);
                mma_bf16(d1, ah, bl[1], bl[3]);
                mma_bf16(d1, al, bh[1], bh[3]);
            }
        }

        // ---- h = gelu(acc1 + b1), split, store to Hh/Hl ----
        {
            int r0 = m0 + (lane >> 2);
#pragma unroll
            for (int t = 0; t < 4; t++) {
                int colb = n1base + t * 8 + 2 * (lane & 3);
                float bb0 = b1[ch * 64 + colb];
                float bb1 = b1[ch * 64 + colb + 1];
#pragma unroll
                for (int half = 0; half < 2; half++) {
                    int r = r0 + half * 8;
                    float v0 = gelu_f(acc1[t * 4 + half * 2 + 0] + bb0);
                    float v1 = gelu_f(acc1[t * 4 + half * 2 + 1] + bb1);
                    __nv_bfloat16 h0, l0, h1, l1;
                    split_bf16(v0, h0, l0);
                    split_bf16(v1, h1, l1);
                    __nv_bfloat162 ph; ph.x = h0; ph.y = h1;
                    __nv_bfloat162 pl; pl.x = l0; pl.y = l1;
                    *reinterpret_cast<__nv_bfloat162*>(&Hh[r * F_HS + colb]) = ph;
                    *reinterpret_cast<__nv_bfloat162*>(&Hl[r * F_HS + colb]) = pl;
                }
            }
        }
        __syncthreads();   // stage1 W reads + H writes done

        // ---- load W2 chunk [64k x 128n] -> Wh/Wl [n][k] stride F_HS ----
#pragma unroll
        for (int i = 0; i < 16; i++) {
            int e = tid + 512 * i;
            int k = e >> 7, n = e & 127;
            float f = w2[(size_t)(ch * 64 + k) * 128 + n];
            __nv_bfloat16 h, l; split_bf16(f, h, l);
            Wh[n * F_HS + k] = h;
            Wl[n * F_HS + k] = l;
        }
        __syncthreads();

        // ---- stage 2: acc2 += h(128x64) @ W2chunk(64x128) ----
#pragma unroll
        for (int ks = 0; ks < 4; ks++) {
            uint32_t ah[4], al[4];
            ldsm4(ah, &Hh[(m0 + lr) * F_HS + ks * 16 + lk]);
            ldsm4(al, &Hl[(m0 + lr) * F_HS + ks * 16 + lk]);
#pragma unroll
            for (int g = 0; g < 4; g++) {
                uint32_t bh[4], bl[4];
                ldsm4(bh, &Wh[(n2base + g * 16 + lr) * F_HS + ks * 16 + lk]);
                ldsm4(bl, &Wl[(n2base + g * 16 + lr) * F_HS + ks * 16 + lk]);
                float* d0 = &acc2[(g * 2 + 0) * 4];
                float* d1 = &acc2[(g * 2 + 1) * 4];
                mma_bf16(d0, ah, bh[0], bh[2]);
                mma_bf16(d0, ah, bl[0], bl[2]);
                mma_bf16(d0, al, bh[0], bh[2]);
                mma_bf16(d1, ah, bh[1], bh[3]);
                mma_bf16(d1, ah, bl[1], bl[3]);
                mma_bf16(d1, al, bh[1], bh[3]);
            }
        }
        __syncthreads();   // protect W/H for next chunk
    }

    // ---- epilogue: out = acc2 + b2 + xres ----
    {
        int r0 = m0 + (lane >> 2);
#pragma unroll
        for (int t = 0; t < 8; t++) {
            int col = n2base + t * 8 + 2 * (lane & 3);
            float bb0 = b2[col], bb1 = b2[col + 1];
#pragma unroll
            for (int half = 0; half < 2; half++) {
                size_t r = rowBase + r0 + half * 8;
                float2 xr = *reinterpret_cast<const float2*>(&xres[r * 128 + col]);
                float2 o;
                o.x = acc2[t * 4 + half * 2 + 0] + bb0 + xr.x;
                o.y = acc2[t * 4 + half * 2 + 1] + bb1 + xr.y;
                *reinterpret_cast<float2*>(&out[r * 128 + col]) = o;
            }
        }
    }
}

// ---------------------------------------------------------------------------
// Fused edge pipeline: per block = 64 edge rows.
//  h(64x128)   = relu([normed_src|normed_tgt|edge_attr] @ e_w1 + e_b1)
//  msgs(64x32) = (h @ e_w2 + e_b2) * mask  -> out_msgs + atomic scatter to agg
// ---------------------------------------------------------------------------
constexpr size_t EDGE_SMEM = (size_t)(16*68 + 16*132 + 64*132 + 128*32) * 4; // 62,976 B

__global__ void __launch_bounds__(256) edge_fused_k(
    const float* __restrict__ normed, const float* __restrict__ edge_attr,
    const int* __restrict__ srcI, const int* __restrict__ tgtI,
    const float* __restrict__ e_w1, const float* __restrict__ e_b1,
    const float* __restrict__ e_w2, const float* __restrict__ e_b2,
    const float* __restrict__ mask,
    float* __restrict__ msgs_out, float* __restrict__ agg)
{
    extern __shared__ float s[];
    float* As  = s;                   // [16][68]  (k-major transposed A tile)
    float* Bs  = As + 16 * 68;        // [16][132]
    float* Hs  = Bs + 16 * 132;       // [64][132]
    float* W2s = Hs + 64 * 132;       // [128][32]
    __shared__ int srcb[64], tgtb[64], tgtn_s[64];

    const int tid = threadIdx.x;
    const int tx = tid & 15;
    const int ty = tid >> 4;
    const size_t rowBase = (size_t)blockIdx.x * 64;

    if (tid < 64) {
        size_t row = rowBase + tid;
        int b = (int)(row / CE);
        int e = (int)(row - (size_t)b * CE);
        int sv = srcI[e], tv = tgtI[e];
        srcb[tid] = (b * CN + sv) * CD;
        tgtb[tid] = (b * CN + tv) * CD;
        tgtn_s[tid] = b * CN + tv;
    }
    // load e_w2 [128][32]
#pragma unroll
    for (int i = 0; i < 16; i++) W2s[tid + 256 * i] = e_w2[tid + 256 * i];
    __syncthreads();

    float acc[4][8];
#pragma unroll
    for (int i = 0; i < 4; i++)
#pragma unroll
        for (int j = 0; j < 8; j++) acc[i][j] = 0.f;

    for (int k0 = 0; k0 < CK1; k0 += 16) {
#pragma unroll
        for (int i = 0; i < 4; i++) {
            int e = tid + 256 * i;
            int r = e >> 4, c = e & 15;
            float v;
            if (k0 < 128)      v = normed[srcb[r] + k0 + c];
            else if (k0 < 256) v = normed[tgtb[r] + (k0 - 128) + c];
            else               v = edge_attr[(rowBase + r) * CED + (k0 - 256) + c];
            As[c * 68 + r] = v;
        }
#pragma unroll
        for (int i = 0; i < 8; i++) {
            int e = tid + 256 * i;
            int r = e >> 7, c = e & 127;
            Bs[r * 132 + c] = e_w1[(size_t)(k0 + r) * CD + c];
        }
        __syncthreads();
#pragma unroll
        for (int k = 0; k < 16; k++) {
            float a[4], b[8];
#pragma unroll
            for (int i = 0; i < 4; i++) a[i] = As[k * 68 + ty + 16 * i];
#pragma unroll
            for (int j = 0; j < 8; j++) b[j] = Bs[k * 132 + tx + 16 * j];
#pragma unroll
            for (int i = 0; i < 4; i++)
#pragma unroll
                for (int j = 0; j < 8; j++)
                    acc[i][j] = fmaf(a[i], b[j], acc[i][j]);
        }
        __syncthreads();
    }

    // h = relu(acc + b1) -> Hs
#pragma unroll
    for (int j = 0; j < 8; j++) {
        int c = tx + 16 * j;
        float bb = e_b1[c];
#pragma unroll
        for (int i = 0; i < 4; i++) {
            Hs[(ty + 16 * i) * 132 + c] = fmaxf(acc[i][j] + bb, 0.f);
        }
    }
    __syncthreads();

    // msgs = (h @ e_w2 + e_b2) * mask ; write + scatter
    {
        int r  = tid >> 2;
        int cg = (tid & 3) * 8;
        float m[8];
#pragma unroll
        for (int j = 0; j < 8; j++) m[j] = 0.f;
#pragma unroll 4
        for (int k = 0; k < 128; k++) {
            float av = Hs[r * 132 + k];
            float4 w0 = *reinterpret_cast<const float4*>(&W2s[k * 32 + cg]);
            float4 w1v = *reinterpret_cast<const float4*>(&W2s[k * 32 + cg + 4]);
            m[0] = fmaf(av, w0.x, m[0]);  m[1] = fmaf(av, w0.y, m[1]);
            m[2] = fmaf(av, w0.z, m[2]);  m[3] = fmaf(av, w0.w, m[3]);
            m[4] = fmaf(av, w1v.x, m[4]); m[5] = fmaf(av, w1v.y, m[5]);
            m[6] = fmaf(av, w1v.z, m[6]); m[7] = fmaf(av, w1v.w, m[7]);
        }
        size_t be = rowBase + r;
        float mk = mask[be];
        float* aggp = &agg[(size_t)tgtn_s[r] * CED + cg];
        float* outp = &msgs_out[be * 32 + cg];
#pragma unroll
        for (int j = 0; j < 8; j++) {
            float v = (m[j] + e_b2[cg + j]) * mk;
            outp[j] = v;
            atomicAdd(&aggp[j], v);
        }
    }
}

// ---------------------------------------------------------------------------
// GRU GEMM with fused concat A = [a1 (*a2 if MODE==2) | a3], K=256, N=128.
// ---------------------------------------------------------------------------
template<int ACT, int MODE>
__global__ void __launch_bounds__(256) gemm_gru_k(
    const float* __restrict__ a1, const float* __restrict__ a2,
    const float* __restrict__ a3,
    const float* __restrict__ W, const float* __restrict__ bias,
    float* __restrict__ C)
{
    __shared__ float As[16][68];
    __shared__ float Bs[16][64];

    const int tid = threadIdx.x;
    const int tx = tid & 15;
    const int ty = tid >> 4;
    const size_t rowBase = (size_t)blockIdx.y * 64;
    const int colBase = blockIdx.x * 64;

    float acc[4][4];
#pragma unroll
    for (int i = 0; i < 4; i++)
#pragma unroll
        for (int j = 0; j < 4; j++) acc[i][j] = 0.f;

    for (int k0 = 0; k0 < 256; k0 += 16) {
#pragma unroll
        for (int i = 0; i < 4; i++) {
            int e = tid + 256 * i;
            int r = e >> 4, c = e & 15;
            size_t base = (rowBase + r) * 128;
            float v;
            if (k0 < 128) {
                v = a1[base + k0 + c];
                if (MODE == 2) v *= a2[base + k0 + c];
            } else {
                v = a3[base + (k0 - 128) + c];
            }
            As[c][r] = v;
        }
#pragma unroll
        for (int i = 0; i < 4; i++) {
            int e = tid + 256 * i;
            int r = e >> 6, c = e & 63;
            Bs[r][c] = W[(size_t)(k0 + r) * CD + colBase + c];
        }
        __syncthreads();
#pragma unroll
        for (int k = 0; k < 16; k++) {
            float a[4], b[4];
#pragma unroll
            for (int i = 0; i < 4; i++) a[i] = As[k][ty + 16 * i];
#pragma unroll
            for (int j = 0; j < 4; j++) b[j] = Bs[k][tx + 16 * j];
#pragma unroll
            for (int i = 0; i < 4; i++)
#pragma unroll
                for (int j = 0; j < 4; j++)
                    acc[i][j] = fmaf(a[i], b[j], acc[i][j]);
        }
        __syncthreads();
    }

#pragma unroll
    for (int i = 0; i < 4; i++) {
        size_t r = rowBase + ty + 16 * i;
#pragma unroll
        for (int j = 0; j < 4; j++) {
            int c = colBase + tx + 16 * j;
            float v = acc[i][j] + bias[c];
            if (ACT == 2) v = 1.f / (1.f + expf(-v));
            else if (ACT == 3) v = tanhf(v);
            C[r * CD + c] = v;
        }
    }
}

// ---------------------------------------------------------------------------
// proj GEMM with fused count-normalization. K=32, N=128.
// ---------------------------------------------------------------------------
__global__ void __launch_bounds__(256) gemm_proj_k(
    const float* __restrict__ agg, const float* __restrict__ counts,
    const float* __restrict__ W, const float* __restrict__ bias,
    float* __restrict__ C)
{
    __shared__ float As[16][68];
    __shared__ float Bs[16][64];
    __shared__ float rcnt[64];

    const int tid = threadIdx.x;
    const int tx = tid & 15;
    const int ty = tid >> 4;
    const size_t rowBase = (size_t)blockIdx.y * 64;
    const int colBase = blockIdx.x * 64;

    if (tid < 64) rcnt[tid] = 1.f / fmaxf(counts[tid], 1.f);
    __syncthreads();

    float acc[4][4];
#pragma unroll
    for (int i = 0; i < 4; i++)
#pragma unroll
        for (int j = 0; j < 4; j++) acc[i][j] = 0.f;

    for (int k0 = 0; k0 < 32; k0 += 16) {
#pragma unroll
        for (int i = 0; i < 4; i++) {
            int e = tid + 256 * i;
            int r = e >> 4, c = e & 15;
            As[c][r] = agg[(rowBase + r) * 32 + k0 + c] * rcnt[r];
        }
#pragma unroll
        for (int i = 0; i < 4; i++) {
            int e = tid + 256 * i;
            int r = e >> 6, c = e & 63;
            Bs[r][c] = W[(size_t)(k0 + r) * CD + colBase + c];
        }
        __syncthreads();
#pragma unroll
        for (int k = 0; k < 16; k++) {
            float a[4], b[4];
#pragma unroll
            for (int i = 0; i < 4; i++) a[i] = As[k][ty + 16 * i];
#pragma unroll
            for (int j = 0; j < 4; j++) b[j] = Bs[k][tx + 16 * j];
#pragma unroll
            for (int i = 0; i < 4; i++)
#pragma unroll
                for (int j = 0; j < 4; j++)
                    acc[i][j] = fmaf(a[i], b[j], acc[i][j]);
        }
        __syncthreads();
    }

#pragma unroll
    for (int i = 0; i < 4; i++) {
        size_t r = rowBase + ty + 16 * i;
#pragma unroll
        for (int j = 0; j < 4; j++) {
            int c = colBase + tx + 16 * j;
            C[r * CD + c] = acc[i][j] + bias[c];
        }
    }
}

// ---------------------------------------------------------------------------
// Elementwise kernels
// ---------------------------------------------------------------------------
__global__ void ln_k(const float* __restrict__ in, const float* __restrict__ g,
                     const float* __restrict__ bb, float* __restrict__ out)
{
    const size_t row = blockIdx.x;
    const int d = threadIdx.x;
    float v = in[row * 128 + d];
    float s = v;
#pragma unroll
    for (int o = 16; o > 0; o >>= 1) s += __shfl_xor_sync(~0u, s, o);
    __shared__ float sm[4], sq[4];
    int w = d >> 5, l = d & 31;
    if (l == 0) sm[w] = s;
    __syncthreads();
    float mean = (sm[0] + sm[1] + sm[2] + sm[3]) * (1.f / 128.f);
    float dv = v - mean;
    float q = dv * dv;
#pragma unroll
    for (int o = 16; o > 0; o >>= 1) q += __shfl_xor_sync(~0u, q, o);
    if (l == 0) sq[w] = q;
    __syncthreads();
    float var = (sq[0] + sq[1] + sq[2] + sq[3]) * (1.f / 128.f);
    out[row * 128 + d] = dv * rsqrtf(var + 1e-5f) * g[d] + bb[d];
}

__global__ void gru_ln2_k(const float* __restrict__ nf, const float* __restrict__ normed,
                          const float* __restrict__ u, const float* __restrict__ cand,
                          const float* __restrict__ g, const float* __restrict__ bb,
                          float* __restrict__ x_out, float* __restrict__ n2_out)
{
    const size_t row = blockIdx.x;
    const int d = threadIdx.x;
    size_t i = row * 128 + d;
    float uu = u[i];
    float xv = nf[i] + (1.f - uu) * normed[i] + uu * cand[i];
    x_out[i] = xv;
    float s = xv;
#pragma unroll
    for (int o = 16; o > 0; o >>= 1) s += __shfl_xor_sync(~0u, s, o);
    __shared__ float sm[4], sq[4];
    int w = d >> 5, l = d & 31;
    if (l == 0) sm[w] = s;
    __syncthreads();
    float mean = (sm[0] + sm[1] + sm[2] + sm[3]) * (1.f / 128.f);
    float dv = xv - mean;
    float q = dv * dv;
#pragma unroll
    for (int o = 16; o > 0; o >>= 1) q += __shfl_xor_sync(~0u, q, o);
    if (l == 0) sq[w] = q;
    __syncthreads();
    float var = (sq[0] + sq[1] + sq[2] + sq[3]) * (1.f / 128.f);
    n2_out[i] = dv * rsqrtf(var + 1e-5f) * g[d] + bb[d];
}

__global__ void counts_k(const int* __restrict__ tgt, float* __restrict__ counts)
{
    int e = threadIdx.x;
    if (e < CE) atomicAdd(&counts[tgt[e]], 1.f);
}

// ---------------------------------------------------------------------------
extern "C" void kernel_launch(void* const* d_in, const int* in_sizes, int n_in,
                              void* d_out, int out_size)
{
    const float* nf        = (const float*)d_in[0];
    const float* edge_attr = (const float*)d_in[1];
    const int*   src       = (const int*)  d_in[2];
    const int*   tgt       = (const int*)  d_in[3];
    const float* mask      = (const float*)d_in[4];
    const float* e_w1   = (const float*)d_in[6];
    const float* e_b1   = (const float*)d_in[7];
    const float* e_w2   = (const float*)d_in[8];
    const float* e_b2   = (const float*)d_in[9];
    const float* proj_w = (const float*)d_in[10];
    const float* proj_b = (const float*)d_in[11];
    const float* r_w    = (const float*)d_in[12];
    const float* r_b    = (const float*)d_in[13];
    const float* u_w    = (const float*)d_in[14];
    const float* u_b    = (const float*)d_in[15];
    const float* c_w    = (const float*)d_in[16];
    const float* c_b    = (const float*)d_in[17];
    const float* n1_g   = (const float*)d_in[18];
    const float* n1_b   = (const float*)d_in[19];
    const float* n2_g   = (const float*)d_in[20];
    const float* n2_b   = (const float*)d_in[21];
    const float* f_w1   = (const float*)d_in[22];
    const float* f_b1   = (const float*)d_in[23];
    const float* f_w2   = (const float*)d_in[24];
    const float* f_b2   = (const float*)d_in[25];

    float* out_x    = (float*)d_out;
    float* out_msgs = out_x + SZ_NORMED;

    float *p_normed, *p_agg, *p_counts, *p_proj, *p_r, *p_u, *p_cand, *p_x, *p_n2;
    cudaGetSymbolAddress((void**)&p_normed, g_normed);
    cudaGetSymbolAddress((void**)&p_agg,    g_agg);
    cudaGetSymbolAddress((void**)&p_counts, g_counts);
    cudaGetSymbolAddress((void**)&p_proj,   g_proj);
    cudaGetSymbolAddress((void**)&p_r,      g_r);
    cudaGetSymbolAddress((void**)&p_u,      g_u);
    cudaGetSymbolAddress((void**)&p_cand,   g_cand);
    cudaGetSymbolAddress((void**)&p_x,      g_x);
    cudaGetSymbolAddress((void**)&p_n2,     g_n2);

    cudaFuncSetAttribute(ffn_tc_k, cudaFuncAttributeMaxDynamicSharedMemorySize, (int)FFN_SMEM);
    cudaFuncSetAttribute(edge_fused_k, cudaFuncAttributeMaxDynamicSharedMemorySize, (int)EDGE_SMEM);

    // Zero scatter targets each replay
    cudaMemsetAsync(p_agg, 0, SZ_AGG * sizeof(float));
    cudaMemsetAsync(p_counts, 0, CN * sizeof(float));

    // 1. LN1
    ln_k<<<(unsigned)MN, 128>>>(nf, n1_g, n1_b, p_normed);

    // 2. counts
    counts_k<<<1, 128>>>(tgt, p_counts);

    // 3. fused edge pipeline: h GEMM + msgs GEMM + mask + scatter
    edge_fused_k<<<(unsigned)(ME / 64), 256, EDGE_SMEM>>>(
        p_normed, edge_attr, src, tgt, e_w1, e_b1, e_w2, e_b2, mask,
        out_msgs, p_agg);

    // 4. proj = (agg/cnt) @ proj_w + proj_b
    gemm_proj_k<<<dim3(2, (unsigned)(MN / 64)), 256>>>(
        p_agg, p_counts, proj_w, proj_b, p_proj);

    // 5. r / u = sigmoid([normed|proj] @ W + b)
    gemm_gru_k<2, 1><<<dim3(2, (unsigned)(MN / 64)), 256>>>(
        p_normed, nullptr, p_proj, r_w, r_b, p_r);
    gemm_gru_k<2, 1><<<dim3(2, (unsigned)(MN / 64)), 256>>>(
        p_normed, nullptr, p_proj, u_w, u_b, p_u);

    // 6. cand = tanh([r*normed|proj] @ c_w + c_b)
    gemm_gru_k<3, 2><<<dim3(2, (unsigned)(MN / 64)), 256>>>(
        p_normed, p_r, p_proj, c_w, c_b, p_cand);

    // 7. x = nf + (1-u)*normed + u*cand ; n2 = LN(x)
    gru_ln2_k<<<(unsigned)MN, 128>>>(nf, p_normed, p_u, p_cand, n2_g, n2_b, p_x, p_n2);

    // 8. tensor-core fused FFN
    ffn_tc_k<<<(unsigned)(MN / 128), 512, FFN_SMEM>>>(
        p_n2, f_w1, f_b1, f_w2, f_b2, p_x, out_x);
}

// round 5
// speedup vs baseline: 1.7563x; 1.1382x over previous
#include <cuda_runtime.h>
#include <cuda_bf16.h>
#include <math.h>
#include <stdint.h>

constexpr int CB  = 2048;
constexpr int CN  = 64;
constexpr int CE  = 126;
constexpr int CD  = 128;
constexpr int CED = 32;
constexpr int CF  = 2048;
constexpr int CK1 = 2*CD + CED;  // 288

constexpr size_t MN = (size_t)CB * CN;      // 131072
constexpr size_t ME = (size_t)CB * CE;      // 258048

constexpr size_t SZ_NORMED = MN * CD;
constexpr size_t SZ_AGG    = MN * CED;
constexpr size_t SZ_RUC    = MN * CD;

__device__ float g_normed[SZ_NORMED];
__device__ float g_agg   [SZ_AGG];
__device__ float g_counts[CN];
__device__ float g_proj  [SZ_RUC];
__device__ float g_r     [SZ_RUC];
__device__ float g_u     [SZ_RUC];
__device__ float g_cand  [SZ_RUC];
__device__ float g_x     [SZ_RUC];
__device__ float g_n2    [SZ_RUC];

// ---------------------------------------------------------------------------
// Tensor-core helpers
// ---------------------------------------------------------------------------
__device__ __forceinline__ void ldsm4(uint32_t (&r)[4], const void* p) {
    uint32_t a = (uint32_t)__cvta_generic_to_shared(p);
    asm volatile("ldmatrix.sync.aligned.m8n8.x4.shared.b16 {%0,%1,%2,%3}, [%4];"
        : "=r"(r[0]), "=r"(r[1]), "=r"(r[2]), "=r"(r[3]) : "r"(a));
}

__device__ __forceinline__ void mma_bf16(float* d, const uint32_t* a,
                                         uint32_t b0, uint32_t b1) {
    asm volatile(
        "mma.sync.aligned.m16n8k16.row.col.f32.bf16.bf16.f32 "
        "{%0,%1,%2,%3},{%4,%5,%6,%7},{%8,%9},{%0,%1,%2,%3};"
        : "+f"(d[0]), "+f"(d[1]), "+f"(d[2]), "+f"(d[3])
        : "r"(a[0]), "r"(a[1]), "r"(a[2]), "r"(a[3]), "r"(b0), "r"(b1));
}

// 3-term split-precision mma: d += A_hi*B_hi + A_hi*B_lo + A_lo*B_hi
__device__ __forceinline__ void mma3(float* d0, float* d1,
                                     const uint32_t (&ah)[4], const uint32_t (&al)[4],
                                     const uint32_t (&bh)[4], const uint32_t (&bl)[4]) {
    mma_bf16(d0, ah, bh[0], bh[2]);
    mma_bf16(d0, ah, bl[0], bl[2]);
    mma_bf16(d0, al, bh[0], bh[2]);
    mma_bf16(d1, ah, bh[1], bh[3]);
    mma_bf16(d1, ah, bl[1], bl[3]);
    mma_bf16(d1, al, bh[1], bh[3]);
}

__device__ __forceinline__ void split_bf16(float f, __nv_bfloat16& h, __nv_bfloat16& l) {
    h = __float2bfloat16(f);
    l = __float2bfloat16(f - __bfloat162float(h));
}

__device__ __forceinline__ float gelu_f(float v) {
    return 0.5f * v * (1.f + erff(v * 0.70710678118654752f));
}

// ---------------------------------------------------------------------------
// Tensor-core fused FFN: out = xres + gelu(n2 @ W1 + b1) @ W2 + b2
// ---------------------------------------------------------------------------
constexpr int F_AS = 136;
constexpr int F_HS = 72;
constexpr int F_ASZ = 128 * F_AS;
constexpr int F_HSZ = 128 * F_HS;
constexpr int F_WSZ = 128 * F_HS;
constexpr size_t FFN_SMEM = (size_t)(2*F_ASZ + 2*F_HSZ + 2*F_WSZ) * 2;  // 143,360 B

__global__ void __launch_bounds__(512) ffn_tc_k(
    const float* __restrict__ n2, const float* __restrict__ w1,
    const float* __restrict__ b1, const float* __restrict__ w2,
    const float* __restrict__ b2, const float* __restrict__ xres,
    float* __restrict__ out)
{
    extern __shared__ __nv_bfloat16 sb[];
    __nv_bfloat16* Ah = sb;
    __nv_bfloat16* Al = Ah + F_ASZ;
    __nv_bfloat16* Hh = Al + F_ASZ;
    __nv_bfloat16* Hl = Hh + F_HSZ;
    __nv_bfloat16* Wh = Hl + F_HSZ;
    __nv_bfloat16* Wl = Wh + F_WSZ;

    const int tid  = threadIdx.x;
    const int lane = tid & 31;
    const int wrp  = tid >> 5;
    const int wm   = wrp & 7;
    const int wn   = wrp >> 3;
    const int m0   = wm * 16;
    const size_t rowBase = (size_t)blockIdx.x * 128;
    const int lr = lane & 15;
    const int lk = (lane >> 4) * 8;

#pragma unroll
    for (int i = 0; i < 32; i++) {
        int e = tid + 512 * i;
        int r = e >> 7, k = e & 127;
        float f = n2[(rowBase + r) * 128 + k];
        __nv_bfloat16 h, l; split_bf16(f, h, l);
        Ah[r * F_AS + k] = h;
        Al[r * F_AS + k] = l;
    }

    float acc2[32];
#pragma unroll
    for (int i = 0; i < 32; i++) acc2[i] = 0.f;

    const int n1base = wn * 32;
    const int n2base = wn * 64;

    __syncthreads();

    for (int ch = 0; ch < 32; ch++) {
#pragma unroll
        for (int i = 0; i < 16; i++) {
            int e = tid + 512 * i;
            int k = e >> 6, n = e & 63;
            float f = w1[(size_t)k * 2048 + ch * 64 + n];
            __nv_bfloat16 h, l; split_bf16(f, h, l);
            Wh[n * F_AS + k] = h;
            Wl[n * F_AS + k] = l;
        }
        __syncthreads();

        float acc1[16];
#pragma unroll
        for (int i = 0; i < 16; i++) acc1[i] = 0.f;

#pragma unroll
        for (int ks = 0; ks < 8; ks++) {
            uint32_t ah[4], al[4];
            ldsm4(ah, &Ah[(m0 + lr) * F_AS + ks * 16 + lk]);
            ldsm4(al, &Al[(m0 + lr) * F_AS + ks * 16 + lk]);
#pragma unroll
            for (int g = 0; g < 2; g++) {
                uint32_t bh[4], bl[4];
                ldsm4(bh, &Wh[(n1base + g * 16 + lr) * F_AS + ks * 16 + lk]);
                ldsm4(bl, &Wl[(n1base + g * 16 + lr) * F_AS + ks * 16 + lk]);
                mma3(&acc1[(g * 2 + 0) * 4], &acc1[(g * 2 + 1) * 4], ah, al, bh, bl);
            }
        }

        {
            int r0 = m0 + (lane >> 2);
#pragma unroll
            for (int t = 0; t < 4; t++) {
                int colb = n1base + t * 8 + 2 * (lane & 3);
                float bb0 = b1[ch * 64 + colb];
                float bb1 = b1[ch * 64 + colb + 1];
#pragma unroll
                for (int half = 0; half < 2; half++) {
                    int r = r0 + half * 8;
                    float v0 = gelu_f(acc1[t * 4 + half * 2 + 0] + bb0);
                    float v1 = gelu_f(acc1[t * 4 + half * 2 + 1] + bb1);
                    __nv_bfloat16 h0, l0, h1, l1;
                    split_bf16(v0, h0, l0);
                    split_bf16(v1, h1, l1);
                    __nv_bfloat162 ph; ph.x = h0; ph.y = h1;
                    __nv_bfloat162 pl; pl.x = l0; pl.y = l1;
                    *reinterpret_cast<__nv_bfloat162*>(&Hh[r * F_HS + colb]) = ph;
                    *reinterpret_cast<__nv_bfloat162*>(&Hl[r * F_HS + colb]) = pl;
                }
            }
        }
        __syncthreads();

#pragma unroll
        for (int i = 0; i < 16; i++) {
            int e = tid + 512 * i;
            int k = e >> 7, n = e & 127;
            float f = w2[(size_t)(ch * 64 + k) * 128 + n];
            __nv_bfloat16 h, l; split_bf16(f, h, l);
            Wh[n * F_HS + k] = h;
            Wl[n * F_HS + k] = l;
        }
        __syncthreads();

#pragma unroll
        for (int ks = 0; ks < 4; ks++) {
            uint32_t ah[4], al[4];
            ldsm4(ah, &Hh[(m0 + lr) * F_HS + ks * 16 + lk]);
            ldsm4(al, &Hl[(m0 + lr) * F_HS + ks * 16 + lk]);
#pragma unroll
            for (int g = 0; g < 4; g++) {
                uint32_t bh[4], bl[4];
                ldsm4(bh, &Wh[(n2base + g * 16 + lr) * F_HS + ks * 16 + lk]);
                ldsm4(bl, &Wl[(n2base + g * 16 + lr) * F_HS + ks * 16 + lk]);
                mma3(&acc2[(g * 2 + 0) * 4], &acc2[(g * 2 + 1) * 4], ah, al, bh, bl);
            }
        }
        __syncthreads();
    }

    {
        int r0 = m0 + (lane >> 2);
#pragma unroll
        for (int t = 0; t < 8; t++) {
            int col = n2base + t * 8 + 2 * (lane & 3);
            float bb0 = b2[col], bb1 = b2[col + 1];
#pragma unroll
            for (int half = 0; half < 2; half++) {
                size_t r = rowBase + r0 + half * 8;
                float2 xr = *reinterpret_cast<const float2*>(&xres[r * 128 + col]);
                float2 o;
                o.x = acc2[t * 4 + half * 2 + 0] + bb0 + xr.x;
                o.y = acc2[t * 4 + half * 2 + 1] + bb1 + xr.y;
                *reinterpret_cast<float2*>(&out[r * 128 + col]) = o;
            }
        }
    }
}

// ---------------------------------------------------------------------------
// Tensor-core fused edge pipeline: 128 edge rows / block, 512 threads.
//  stage1: h(128x128) = relu(A(128x288) @ e_w1 + e_b1), A gathered, K-chunks 96
//  stage2: msgs(128x32) = (h @ e_w2 + e_b2)*mask -> out + atomic scatter to agg
// ---------------------------------------------------------------------------
constexpr int E_AS = 104;   // stage1 A/W k-stride (chunk K=96 + pad)
constexpr int E_HS = 136;   // H / W2 k-stride
constexpr size_t EDGE_SMEM = (size_t)(4 * 128 * E_AS) * 2;   // 106,496 B

__global__ void __launch_bounds__(512) edge_tc_k(
    const float* __restrict__ normed, const float* __restrict__ edge_attr,
    const int* __restrict__ srcI, const int* __restrict__ tgtI,
    const float* __restrict__ e_w1, const float* __restrict__ e_b1,
    const float* __restrict__ e_w2, const float* __restrict__ e_b2,
    const float* __restrict__ mask,
    float* __restrict__ msgs_out, float* __restrict__ agg)
{
    extern __shared__ __nv_bfloat16 sb[];
    // phase 1 layout
    __nv_bfloat16* Ah = sb;
    __nv_bfloat16* Al = Ah + 128 * E_AS;
    __nv_bfloat16* Wh = Al + 128 * E_AS;
    __nv_bfloat16* Wl = Wh + 128 * E_AS;
    // phase 2 layout (aliased, used after sync)
    __nv_bfloat16* Hh  = sb;
    __nv_bfloat16* Hl  = Hh + 128 * E_HS;
    __nv_bfloat16* W2h = Hl + 128 * E_HS;
    __nv_bfloat16* W2l = W2h + 32 * E_HS;

    __shared__ int   srcb[128], tgtb[128], tgtn[128];
    __shared__ float mks[128];

    const int tid  = threadIdx.x;
    const int lane = tid & 31;
    const int wrp  = tid >> 5;
    const int wm   = wrp & 7;
    const int wn   = wrp >> 3;
    const int m0   = wm * 16;
    const size_t rowBase = (size_t)blockIdx.x * 128;
    const int lr = lane & 15;
    const int lk = (lane >> 4) * 8;

    if (tid < 128) {
        size_t row = rowBase + tid;
        int b = (int)(row / CE);
        int e = (int)(row - (size_t)b * CE);
        srcb[tid] = (b * CN + srcI[e]) * CD;
        tgtb[tid] = (b * CN + tgtI[e]) * CD;
        tgtn[tid] = b * CN + tgtI[e];
        mks[tid]  = mask[row];
    }
    __syncthreads();

    float acc1[32];
#pragma unroll
    for (int i = 0; i < 32; i++) acc1[i] = 0.f;

    for (int ch = 0; ch < 3; ch++) {
        const int k0 = ch * 96;
        // A chunk: 128 rows x 96 k, gathered
#pragma unroll
        for (int i = 0; i < 24; i++) {
            int e = tid + 512 * i;
            int r = e / 96, c = e % 96;
            int gk = k0 + c;
            float f;
            if (gk < 128)      f = normed[srcb[r] + gk];
            else if (gk < 256) f = normed[tgtb[r] + gk - 128];
            else               f = edge_attr[(rowBase + r) * CED + gk - 256];
            __nv_bfloat16 h, l; split_bf16(f, h, l);
            Ah[r * E_AS + c] = h;
            Al[r * E_AS + c] = l;
        }
        // W1 chunk: [n=128][k=96]
#pragma unroll
        for (int i = 0; i < 24; i++) {
            int e = tid + 512 * i;
            int n = e & 127, kl = e >> 7;
            float f = e_w1[(size_t)(k0 + kl) * CD + n];
            __nv_bfloat16 h, l; split_bf16(f, h, l);
            Wh[n * E_AS + kl] = h;
            Wl[n * E_AS + kl] = l;
        }
        __syncthreads();
#pragma unroll
        for (int ks = 0; ks < 6; ks++) {
            uint32_t ah[4], al[4];
            ldsm4(ah, &Ah[(m0 + lr) * E_AS + ks * 16 + lk]);
            ldsm4(al, &Al[(m0 + lr) * E_AS + ks * 16 + lk]);
#pragma unroll
            for (int g = 0; g < 4; g++) {
                uint32_t bh[4], bl[4];
                ldsm4(bh, &Wh[(wn * 64 + g * 16 + lr) * E_AS + ks * 16 + lk]);
                ldsm4(bl, &Wl[(wn * 64 + g * 16 + lr) * E_AS + ks * 16 + lk]);
                mma3(&acc1[(g * 2 + 0) * 4], &acc1[(g * 2 + 1) * 4], ah, al, bh, bl);
            }
        }
        __syncthreads();
    }

    // h = relu(acc1 + b1) -> Hh/Hl (aliased over phase-1 smem; all reads done)
    {
        int r0 = m0 + (lane >> 2);
#pragma unroll
        for (int t = 0; t < 8; t++) {
            int col = wn * 64 + t * 8 + 2 * (lane & 3);
            float bb0 = e_b1[col], bb1 = e_b1[col + 1];
#pragma unroll
            for (int half = 0; half < 2; half++) {
                int r = r0 + half * 8;
                float v0 = fmaxf(acc1[t * 4 + half * 2 + 0] + bb0, 0.f);
                float v1 = fmaxf(acc1[t * 4 + half * 2 + 1] + bb1, 0.f);
                __nv_bfloat16 h0, l0, h1, l1;
                split_bf16(v0, h0, l0);
                split_bf16(v1, h1, l1);
                __nv_bfloat162 ph; ph.x = h0; ph.y = h1;
                __nv_bfloat162 pl; pl.x = l0; pl.y = l1;
                *reinterpret_cast<__nv_bfloat162*>(&Hh[r * E_HS + col]) = ph;
                *reinterpret_cast<__nv_bfloat162*>(&Hl[r * E_HS + col]) = pl;
            }
        }
    }
    // W2: [n=32][k=128]
#pragma unroll
    for (int i = 0; i < 8; i++) {
        int e = tid + 512 * i;
        int k = e >> 5, n = e & 31;
        float f = e_w2[(size_t)k * CED + n];
        __nv_bfloat16 h, l; split_bf16(f, h, l);
        W2h[n * E_HS + k] = h;
        W2l[n * E_HS + k] = l;
    }
    __syncthreads();

    // stage 2: msgs = h @ e_w2  (each warp: 16 rows x 16 cols)
    float acc2[8];
#pragma unroll
    for (int i = 0; i < 8; i++) acc2[i] = 0.f;
#pragma unroll
    for (int ks = 0; ks < 8; ks++) {
        uint32_t ah[4], al[4];
        ldsm4(ah, &Hh[(m0 + lr) * E_HS + ks * 16 + lk]);
        ldsm4(al, &Hl[(m0 + lr) * E_HS + ks * 16 + lk]);
        uint32_t bh[4], bl[4];
        ldsm4(bh, &W2h[(wn * 16 + lr) * E_HS + ks * 16 + lk]);
        ldsm4(bl, &W2l[(wn * 16 + lr) * E_HS + ks * 16 + lk]);
        mma3(&acc2[0], &acc2[4], ah, al, bh, bl);
    }

    // epilogue: bias, mask, store msgs, scatter to agg
    {
        int r0 = m0 + (lane >> 2);
#pragma unroll
        for (int t = 0; t < 2; t++) {
            int col = wn * 16 + t * 8 + 2 * (lane & 3);
            float bb0 = e_b2[col], bb1 = e_b2[col + 1];
#pragma unroll
            for (int half = 0; half < 2; half++) {
                int r = r0 + half * 8;
                float mk = mks[r];
                float v0 = (acc2[t * 4 + half * 2 + 0] + bb0) * mk;
                float v1 = (acc2[t * 4 + half * 2 + 1] + bb1) * mk;
                size_t be = rowBase + r;
                msgs_out[be * 32 + col]     = v0;
                msgs_out[be * 32 + col + 1] = v1;
                float* ap = &agg[(size_t)tgtn[r] * CED + col];
                atomicAdd(ap, v0);
                atomicAdd(ap + 1, v1);
            }
        }
    }
}

// ---------------------------------------------------------------------------
// Tensor-core GRU GEMMs. A = [a1 (*a2 if !RU) | a3] (128 rows x 256 k).
// RU=true: two weight sets (r_w, u_w), sigmoid. RU=false: one (c_w), tanh.
// SMEM: A hi/lo full (stride 264) + W chunk hi/lo (stride 136) = 204,800 B
// ---------------------------------------------------------------------------
constexpr int G_AS = 264;
constexpr int G_WS = 136;
constexpr size_t GRU_SMEM = (size_t)(2 * 128 * G_AS + 2 * 128 * G_WS) * 2;  // 204,800 B

template<bool RU>
__global__ void __launch_bounds__(512) gru_tc_k(
    const float* __restrict__ a1, const float* __restrict__ a2,
    const float* __restrict__ a3,
    const float* __restrict__ w0p, const float* __restrict__ b0p,
    const float* __restrict__ w1p, const float* __restrict__ b1p,
    float* __restrict__ out0, float* __restrict__ out1)
{
    extern __shared__ __nv_bfloat16 sb[];
    __nv_bfloat16* Ah = sb;
    __nv_bfloat16* Al = Ah + 128 * G_AS;
    __nv_bfloat16* Wh = Al + 128 * G_AS;
    __nv_bfloat16* Wl = Wh + 128 * G_WS;

    const int tid  = threadIdx.x;
    const int lane = tid & 31;
    const int wrp  = tid >> 5;
    const int wm   = wrp & 7;
    const int wn   = wrp >> 3;
    const int m0   = wm * 16;
    const size_t rowBase = (size_t)blockIdx.x * 128;
    const int lr = lane & 15;
    const int lk = (lane >> 4) * 8;

    // Load A = [a1(*a2) | a3], split hi/lo
#pragma unroll
    for (int i = 0; i < 64; i++) {
        int e = tid + 512 * i;
        int r = e >> 8, k = e & 255;
        size_t base = (rowBase + r) * 128;
        float f;
        if (k < 128) {
            f = a1[base + k];
            if (!RU) f *= a2[base + k];
        } else {
            f = a3[base + k - 128];
        }
        __nv_bfloat16 h, l; split_bf16(f, h, l);
        Ah[r * G_AS + k] = h;
        Al[r * G_AS + k] = l;
    }
    __syncthreads();

    const int NW = RU ? 2 : 1;
    float acc[2][32];
#pragma unroll
    for (int s = 0; s < 2; s++)
#pragma unroll
        for (int i = 0; i < 32; i++) acc[s][i] = 0.f;

    for (int ws = 0; ws < NW; ws++) {
        const float* w = (ws == 0) ? w0p : w1p;
        for (int kc = 0; kc < 2; kc++) {
            // W chunk [n=128][k=128]
#pragma unroll
            for (int i = 0; i < 32; i++) {
                int e = tid + 512 * i;
                int n = e & 127, kl = e >> 7;
                float f = w[(size_t)(kc * 128 + kl) * CD + n];
                __nv_bfloat16 h, l; split_bf16(f, h, l);
                Wh[n * G_WS + kl] = h;
                Wl[n * G_WS + kl] = l;
            }
            __syncthreads();
#pragma unroll
            for (int ks = 0; ks < 8; ks++) {
                uint32_t ah[4], al[4];
                ldsm4(ah, &Ah[(m0 + lr) * G_AS + kc * 128 + ks * 16 + lk]);
                ldsm4(al, &Al[(m0 + lr) * G_AS + kc * 128 + ks * 16 + lk]);
#pragma unroll
                for (int g = 0; g < 4; g++) {
                    uint32_t bh[4], bl[4];
                    ldsm4(bh, &Wh[(wn * 64 + g * 16 + lr) * G_WS + ks * 16 + lk]);
                    ldsm4(bl, &Wl[(wn * 64 + g * 16 + lr) * G_WS + ks * 16 + lk]);
                    mma3(&acc[ws][(g * 2 + 0) * 4], &acc[ws][(g * 2 + 1) * 4],
                         ah, al, bh, bl);
                }
            }
            __syncthreads();
        }
    }

    // epilogue
    {
        int r0 = m0 + (lane >> 2);
#pragma unroll
        for (int s = 0; s < 2; s++) {
            if (s >= NW) break;
            const float* bias = (s == 0) ? b0p : b1p;
            float* outp = (s == 0) ? out0 : out1;
#pragma unroll
            for (int t = 0; t < 8; t++) {
                int col = wn * 64 + t * 8 + 2 * (lane & 3);
                float bb0 = bias[col], bb1 = bias[col + 1];
#pragma unroll
                for (int half = 0; half < 2; half++) {
                    size_t r = rowBase + r0 + half * 8;
                    float v0 = acc[s][t * 4 + half * 2 + 0] + bb0;
                    float v1 = acc[s][t * 4 + half * 2 + 1] + bb1;
                    if (RU) {
                        v0 = 1.f / (1.f + expf(-v0));
                        v1 = 1.f / (1.f + expf(-v1));
                    } else {
                        v0 = tanhf(v0);
                        v1 = tanhf(v1);
                    }
                    float2 o; o.x = v0; o.y = v1;
                    *reinterpret_cast<float2*>(&outp[r * 128 + col]) = o;
                }
            }
        }
    }
}

// ---------------------------------------------------------------------------
// proj GEMM with fused count-normalization. K=32, N=128. (small, scalar)
// ---------------------------------------------------------------------------
__global__ void __launch_bounds__(256) gemm_proj_k(
    const float* __restrict__ agg, const float* __restrict__ counts,
    const float* __restrict__ W, const float* __restrict__ bias,
    float* __restrict__ C)
{
    __shared__ float As[16][68];
    __shared__ float Bs[16][64];
    __shared__ float rcnt[64];

    const int tid = threadIdx.x;
    const int tx = tid & 15;
    const int ty = tid >> 4;
    const size_t rowBase = (size_t)blockIdx.y * 64;
    const int colBase = blockIdx.x * 64;

    if (tid < 64) rcnt[tid] = 1.f / fmaxf(counts[tid], 1.f);
    __syncthreads();

    float acc[4][4];
#pragma unroll
    for (int i = 0; i < 4; i++)
#pragma unroll
        for (int j = 0; j < 4; j++) acc[i][j] = 0.f;

    for (int k0 = 0; k0 < 32; k0 += 16) {
#pragma unroll
        for (int i = 0; i < 4; i++) {
            int e = tid + 256 * i;
            int r = e >> 4, c = e & 15;
            As[c][r] = agg[(rowBase + r) * 32 + k0 + c] * rcnt[r];
        }
#pragma unroll
        for (int i = 0; i < 4; i++) {
            int e = tid + 256 * i;
            int r = e >> 6, c = e & 63;
            Bs[r][c] = W[(size_t)(k0 + r) * CD + colBase + c];
        }
        __syncthreads();
#pragma unroll
        for (int k = 0; k < 16; k++) {
            float a[4], b[4];
#pragma unroll
            for (int i = 0; i < 4; i++) a[i] = As[k][ty + 16 * i];
#pragma unroll
            for (int j = 0; j < 4; j++) b[j] = Bs[k][tx + 16 * j];
#pragma unroll
            for (int i = 0; i < 4; i++)
#pragma unroll
                for (int j = 0; j < 4; j++)
                    acc[i][j] = fmaf(a[i], b[j], acc[i][j]);
        }
        __syncthreads();
    }

#pragma unroll
    for (int i = 0; i < 4; i++) {
        size_t r = rowBase + ty + 16 * i;
#pragma unroll
        for (int j = 0; j < 4; j++) {
            int c = colBase + tx + 16 * j;
            C[r * CD + c] = acc[i][j] + bias[c];
        }
    }
}

// ---------------------------------------------------------------------------
// Elementwise kernels
// ---------------------------------------------------------------------------
__global__ void ln_k(const float* __restrict__ in, const float* __restrict__ g,
                     const float* __restrict__ bb, float* __restrict__ out)
{
    const size_t row = blockIdx.x;
    const int d = threadIdx.x;
    float v = in[row * 128 + d];
    float s = v;
#pragma unroll
    for (int o = 16; o > 0; o >>= 1) s += __shfl_xor_sync(~0u, s, o);
    __shared__ float sm[4], sq[4];
    int w = d >> 5, l = d & 31;
    if (l == 0) sm[w] = s;
    __syncthreads();
    float mean = (sm[0] + sm[1] + sm[2] + sm[3]) * (1.f / 128.f);
    float dv = v - mean;
    float q = dv * dv;
#pragma unroll
    for (int o = 16; o > 0; o >>= 1) q += __shfl_xor_sync(~0u, q, o);
    if (l == 0) sq[w] = q;
    __syncthreads();
    float var = (sq[0] + sq[1] + sq[2] + sq[3]) * (1.f / 128.f);
    out[row * 128 + d] = dv * rsqrtf(var + 1e-5f) * g[d] + bb[d];
}

__global__ void gru_ln2_k(const float* __restrict__ nf, const float* __restrict__ normed,
                          const float* __restrict__ u, const float* __restrict__ cand,
                          const float* __restrict__ g, const float* __restrict__ bb,
                          float* __restrict__ x_out, float* __restrict__ n2_out)
{
    const size_t row = blockIdx.x;
    const int d = threadIdx.x;
    size_t i = row * 128 + d;
    float uu = u[i];
    float xv = nf[i] + (1.f - uu) * normed[i] + uu * cand[i];
    x_out[i] = xv;
    float s = xv;
#pragma unroll
    for (int o = 16; o > 0; o >>= 1) s += __shfl_xor_sync(~0u, s, o);
    __shared__ float sm[4], sq[4];
    int w = d >> 5, l = d & 31;
    if (l == 0) sm[w] = s;
    __syncthreads();
    float mean = (sm[0] + sm[1] + sm[2] + sm[3]) * (1.f / 128.f);
    float dv = xv - mean;
    float q = dv * dv;
#pragma unroll
    for (int o = 16; o > 0; o >>= 1) q += __shfl_xor_sync(~0u, q, o);
    if (l == 0) sq[w] = q;
    __syncthreads();
    float var = (sq[0] + sq[1] + sq[2] + sq[3]) * (1.f / 128.f);
    n2_out[i] = dv * rsqrtf(var + 1e-5f) * g[d] + bb[d];
}

__global__ void counts_k(const int* __restrict__ tgt, float* __restrict__ counts)
{
    int e = threadIdx.x;
    if (e < CE) atomicAdd(&counts[tgt[e]], 1.f);
}

// ---------------------------------------------------------------------------
extern "C" void kernel_launch(void* const* d_in, const int* in_sizes, int n_in,
                              void* d_out, int out_size)
{
    const float* nf        = (const float*)d_in[0];
    const float* edge_attr = (const float*)d_in[1];
    const int*   src       = (const int*)  d_in[2];
    const int*   tgt       = (const int*)  d_in[3];
    const float* mask      = (const float*)d_in[4];
    const float* e_w1   = (const float*)d_in[6];
    const float* e_b1   = (const float*)d_in[7];
    const float* e_w2   = (const float*)d_in[8];
    const float* e_b2   = (const float*)d_in[9];
    const float* proj_w = (const float*)d_in[10];
    const float* proj_b = (const float*)d_in[11];
    const float* r_w    = (const float*)d_in[12];
    const float* r_b    = (const float*)d_in[13];
    const float* u_w    = (const float*)d_in[14];
    const float* u_b    = (const float*)d_in[15];
    const float* c_w    = (const float*)d_in[16];
    const float* c_b    = (const float*)d_in[17];
    const float* n1_g   = (const float*)d_in[18];
    const float* n1_b   = (const float*)d_in[19];
    const float* n2_g   = (const float*)d_in[20];
    const float* n2_b   = (const float*)d_in[21];
    const float* f_w1   = (const float*)d_in[22];
    const float* f_b1   = (const float*)d_in[23];
    const float* f_w2   = (const float*)d_in[24];
    const float* f_b2   = (const float*)d_in[25];

    float* out_x    = (float*)d_out;
    float* out_msgs = out_x + SZ_NORMED;

    float *p_normed, *p_agg, *p_counts, *p_proj, *p_r, *p_u, *p_cand, *p_x, *p_n2;
    cudaGetSymbolAddress((void**)&p_normed, g_normed);
    cudaGetSymbolAddress((void**)&p_agg,    g_agg);
    cudaGetSymbolAddress((void**)&p_counts, g_counts);
    cudaGetSymbolAddress((void**)&p_proj,   g_proj);
    cudaGetSymbolAddress((void**)&p_r,      g_r);
    cudaGetSymbolAddress((void**)&p_u,      g_u);
    cudaGetSymbolAddress((void**)&p_cand,   g_cand);
    cudaGetSymbolAddress((void**)&p_x,      g_x);
    cudaGetSymbolAddress((void**)&p_n2,     g_n2);

    cudaFuncSetAttribute(ffn_tc_k,  cudaFuncAttributeMaxDynamicSharedMemorySize, (int)FFN_SMEM);
    cudaFuncSetAttribute(edge_tc_k, cudaFuncAttributeMaxDynamicSharedMemorySize, (int)EDGE_SMEM);
    cudaFuncSetAttribute(gru_tc_k<true>,  cudaFuncAttributeMaxDynamicSharedMemorySize, (int)GRU_SMEM);
    cudaFuncSetAttribute(gru_tc_k<false>, cudaFuncAttributeMaxDynamicSharedMemorySize, (int)GRU_SMEM);

    cudaMemsetAsync(p_agg, 0, SZ_AGG * sizeof(float));
    cudaMemsetAsync(p_counts, 0, CN * sizeof(float));

    // 1. LN1
    ln_k<<<(unsigned)MN, 128>>>(nf, n1_g, n1_b, p_normed);

    // 2. counts
    counts_k<<<1, 128>>>(tgt, p_counts);

    // 3. TC edge pipeline (gather + MLP + mask + scatter)
    edge_tc_k<<<(unsigned)(ME / 128), 512, EDGE_SMEM>>>(
        p_normed, edge_attr, src, tgt, e_w1, e_b1, e_w2, e_b2, mask,
        out_msgs, p_agg);

    // 4. proj = (agg/cnt) @ proj_w + proj_b
    gemm_proj_k<<<dim3(2, (unsigned)(MN / 64)), 256>>>(
        p_agg, p_counts, proj_w, proj_b, p_proj);

    // 5. r,u = sigmoid([normed|proj] @ {r_w,u_w} + b)  (one TC kernel)
    gru_tc_k<true><<<(unsigned)(MN / 128), 512, GRU_SMEM>>>(
        p_normed, nullptr, p_proj, r_w, r_b, u_w, u_b, p_r, p_u);

    // 6. cand = tanh([r*normed|proj] @ c_w + c_b)
    gru_tc_k<false><<<(unsigned)(MN / 128), 512, GRU_SMEM>>>(
        p_normed, p_r, p_proj, c_w, c_b, nullptr, nullptr, p_cand, nullptr);

    // 7. x = nf + (1-u)*normed + u*cand ; n2 = LN(x)
    gru_ln2_k<<<(unsigned)MN, 128>>>(nf, p_normed, p_u, p_cand, n2_g, n2_b, p_x, p_n2);

    // 8. TC fused FFN
    ffn_tc_k<<<(unsigned)(MN / 128), 512, FFN_SMEM>>>(
        p_n2, f_w1, f_b1, f_w2, f_b2, p_x, out_x);
}

// round 6
// speedup vs baseline: 2.0594x; 1.1726x over previous
#include <cuda_runtime.h>
#include <cuda_bf16.h>
#include <math.h>
#include <stdint.h>

constexpr int CB  = 2048;
constexpr int CN  = 64;
constexpr int CE  = 126;
constexpr int CD  = 128;
constexpr int CED = 32;
constexpr int CF  = 2048;
constexpr int CK1 = 2*CD + CED;  // 288

constexpr size_t MN = (size_t)CB * CN;      // 131072
constexpr size_t ME = (size_t)CB * CE;      // 258048

constexpr size_t SZ_NORMED = MN * CD;
constexpr size_t SZ_AGG    = MN * CED;
constexpr size_t SZ_RUC    = MN * CD;

__device__ float g_normed[SZ_NORMED];
__device__ float g_agg   [SZ_AGG];
__device__ float g_counts[CN];
__device__ float g_proj  [SZ_RUC];
__device__ float g_r     [SZ_RUC];
__device__ float g_u     [SZ_RUC];
__device__ float g_cand  [SZ_RUC];
__device__ float g_x     [SZ_RUC];
__device__ float g_n2    [SZ_RUC];

// ---------------------------------------------------------------------------
// TF32 tensor-core helpers (mma.sync m16n8k8, single pass)
// ---------------------------------------------------------------------------
__device__ __forceinline__ uint32_t tf32_of(float f) {
    uint32_t u;
    asm("cvt.rna.tf32.f32 %0, %1;" : "=r"(u) : "f"(f));
    return u;
}

__device__ __forceinline__ void mma_tf32(float* d,
    uint32_t a0, uint32_t a1, uint32_t a2, uint32_t a3,
    uint32_t b0, uint32_t b1)
{
    asm volatile(
        "mma.sync.aligned.m16n8k8.row.col.f32.tf32.tf32.f32 "
        "{%0,%1,%2,%3},{%4,%5,%6,%7},{%8,%9},{%0,%1,%2,%3};"
        : "+f"(d[0]), "+f"(d[1]), "+f"(d[2]), "+f"(d[3])
        : "r"(a0), "r"(a1), "r"(a2), "r"(a3), "r"(b0), "r"(b1));
}

// A fragment (m16 x k8) from SMEM [row][k], stride S (S % 32 == 4 -> conflict-free)
__device__ __forceinline__ void lda8(uint32_t (&a)[4], const float* A, int S,
                                     int row, int kb, int lane)
{
    int r = row + (lane >> 2);
    int c = kb + (lane & 3);
    a[0] = __float_as_uint(A[r * S + c]);
    a[1] = __float_as_uint(A[(r + 8) * S + c]);
    a[2] = __float_as_uint(A[r * S + c + 4]);
    a[3] = __float_as_uint(A[(r + 8) * S + c + 4]);
}

// B fragment (k8 x n8) from SMEM W stored [n][k], stride S
__device__ __forceinline__ void ldb8(uint32_t (&b)[2], const float* W, int S,
                                     int nb, int kb, int lane)
{
    int n = nb + (lane >> 2);
    int k = kb + (lane & 3);
    b[0] = __float_as_uint(W[n * S + k]);
    b[1] = __float_as_uint(W[n * S + k + 4]);
}

// k16 step for one n16 tile: 4 mma
__device__ __forceinline__ void mma_k16_n16(float* d0, float* d1,
    const uint32_t (&au)[4], const uint32_t (&av)[4],
    const float* W, int S, int nb, int kb, int lane)
{
    uint32_t b[2];
    ldb8(b, W, S, nb, kb, lane);          mma_tf32(d0, au[0], au[1], au[2], au[3], b[0], b[1]);
    ldb8(b, W, S, nb, kb + 8, lane);      mma_tf32(d0, av[0], av[1], av[2], av[3], b[0], b[1]);
    ldb8(b, W, S, nb + 8, kb, lane);      mma_tf32(d1, au[0], au[1], au[2], au[3], b[0], b[1]);
    ldb8(b, W, S, nb + 8, kb + 8, lane);  mma_tf32(d1, av[0], av[1], av[2], av[3], b[0], b[1]);
}

__device__ __forceinline__ float gelu_f(float v) {
    return 0.5f * v * (1.f + erff(v * 0.70710678118654752f));
}

// ---------------------------------------------------------------------------
// TF32 fused FFN: out = xres + gelu(n2 @ W1 + b1) @ W2 + b2
// 128 rows/block, 512 threads. SMEM fp32: A[128x132] H[128x68] W[8704]
// ---------------------------------------------------------------------------
constexpr int F_AS = 132;
constexpr int F_HS = 68;
constexpr size_t FFN_SMEM = (size_t)(128*F_AS + 128*F_HS + 128*F_HS) * 4;  // 137,216 B

__global__ void __launch_bounds__(512) ffn_tc_k(
    const float* __restrict__ n2, const float* __restrict__ w1,
    const float* __restrict__ b1, const float* __restrict__ w2,
    const float* __restrict__ b2, const float* __restrict__ xres,
    float* __restrict__ out)
{
    extern __shared__ float sf[];
    float* Af = sf;                    // [128][132]
    float* Hf = Af + 128 * F_AS;       // [128][68]
    float* Wf = Hf + 128 * F_HS;       // stage1 [64][132] / stage2 [128][68]

    const int tid  = threadIdx.x;
    const int lane = tid & 31;
    const int wrp  = tid >> 5;
    const int wm   = wrp & 7;
    const int wn   = wrp >> 3;
    const int m0   = wm * 16;
    const size_t rowBase = (size_t)blockIdx.x * 128;

#pragma unroll
    for (int i = 0; i < 32; i++) {
        int e = tid + 512 * i;
        int r = e >> 7, k = e & 127;
        Af[r * F_AS + k] = __uint_as_float(tf32_of(n2[(rowBase + r) * 128 + k]));
    }

    float acc2[32];
#pragma unroll
    for (int i = 0; i < 32; i++) acc2[i] = 0.f;

    const int n1base = wn * 32;
    const int n2base = wn * 64;

    __syncthreads();

    for (int ch = 0; ch < 32; ch++) {
        // ---- W1 chunk [k=128][n=64] -> Wf[n][k] stride F_AS ----
#pragma unroll
        for (int i = 0; i < 16; i++) {
            int e = tid + 512 * i;
            int k = e >> 6, n = e & 63;
            Wf[n * F_AS + k] = __uint_as_float(tf32_of(w1[(size_t)k * 2048 + ch * 64 + n]));
        }
        __syncthreads();

        // ---- stage 1: acc1 = A(128x128) @ W1chunk -> h(128x64) ----
        float acc1[16];
#pragma unroll
        for (int i = 0; i < 16; i++) acc1[i] = 0.f;

#pragma unroll
        for (int ks = 0; ks < 8; ks++) {
            int kb = ks * 16;
            uint32_t au[4], av[4];
            lda8(au, Af, F_AS, m0, kb, lane);
            lda8(av, Af, F_AS, m0, kb + 8, lane);
#pragma unroll
            for (int g = 0; g < 2; g++) {
                mma_k16_n16(&acc1[(g*2+0)*4], &acc1[(g*2+1)*4],
                            au, av, Wf, F_AS, n1base + g * 16, kb, lane);
            }
        }

        // ---- h = gelu(acc1 + b1) -> Hf (tf32-rounded) ----
        {
            int r0 = m0 + (lane >> 2);
#pragma unroll
            for (int t = 0; t < 4; t++) {
                int colb = n1base + t * 8 + 2 * (lane & 3);
                float bb0 = b1[ch * 64 + colb];
                float bb1 = b1[ch * 64 + colb + 1];
#pragma unroll
                for (int half = 0; half < 2; half++) {
                    int r = r0 + half * 8;
                    float v0 = gelu_f(acc1[t * 4 + half * 2 + 0] + bb0);
                    float v1 = gelu_f(acc1[t * 4 + half * 2 + 1] + bb1);
                    Hf[r * F_HS + colb]     = __uint_as_float(tf32_of(v0));
                    Hf[r * F_HS + colb + 1] = __uint_as_float(tf32_of(v1));
                }
            }
        }
        __syncthreads();

        // ---- W2 chunk [k=64][n=128] -> Wf[n][k] stride F_HS ----
#pragma unroll
        for (int i = 0; i < 16; i++) {
            int e = tid + 512 * i;
            int k = e >> 7, n = e & 127;
            Wf[n * F_HS + k] = __uint_as_float(tf32_of(w2[(size_t)(ch * 64 + k) * 128 + n]));
        }
        __syncthreads();

        // ---- stage 2: acc2 += h(128x64) @ W2chunk(64x128) ----
#pragma unroll
        for (int ks = 0; ks < 4; ks++) {
            int kb = ks * 16;
            uint32_t au[4], av[4];
            lda8(au, Hf, F_HS, m0, kb, lane);
            lda8(av, Hf, F_HS, m0, kb + 8, lane);
#pragma unroll
            for (int g = 0; g < 4; g++) {
                mma_k16_n16(&acc2[(g*2+0)*4], &acc2[(g*2+1)*4],
                            au, av, Wf, F_HS, n2base + g * 16, kb, lane);
            }
        }
        __syncthreads();
    }

    // ---- epilogue: out = acc2 + b2 + xres ----
    {
        int r0 = m0 + (lane >> 2);
#pragma unroll
        for (int t = 0; t < 8; t++) {
            int col = n2base + t * 8 + 2 * (lane & 3);
            float bb0 = b2[col], bb1 = b2[col + 1];
#pragma unroll
            for (int half = 0; half < 2; half++) {
                size_t r = rowBase + r0 + half * 8;
                float2 xr = *reinterpret_cast<const float2*>(&xres[r * 128 + col]);
                float2 o;
                o.x = acc2[t * 4 + half * 2 + 0] + bb0 + xr.x;
                o.y = acc2[t * 4 + half * 2 + 1] + bb1 + xr.y;
                *reinterpret_cast<float2*>(&out[r * 128 + col]) = o;
            }
        }
    }
}

// ---------------------------------------------------------------------------
// TF32 fused edge pipeline: 128 edge rows / block, 512 threads.
//  stage1: h(128x128) = relu(A(128x288) @ e_w1 + e_b1), gathered, chunks K=96
//  stage2: msgs(128x32) = (h @ e_w2 + e_b2)*mask -> out + atomic scatter
// SMEM fp32 (union): phase1 A[128x100]+W[128x100]=25600; phase2 H[128x132]+W2[32x132]
// ---------------------------------------------------------------------------
constexpr int E_AS = 100;
constexpr int E_HS = 132;
constexpr size_t EDGE_SMEM = (size_t)(2 * 128 * E_AS) * 4;   // 102,400 B

__global__ void __launch_bounds__(512) edge_tc_k(
    const float* __restrict__ normed, const float* __restrict__ edge_attr,
    const int* __restrict__ srcI, const int* __restrict__ tgtI,
    const float* __restrict__ e_w1, const float* __restrict__ e_b1,
    const float* __restrict__ e_w2, const float* __restrict__ e_b2,
    const float* __restrict__ mask,
    float* __restrict__ msgs_out, float* __restrict__ agg)
{
    extern __shared__ float sf[];
    // phase 1
    float* Af = sf;                    // [128][100]
    float* Wf = Af + 128 * E_AS;       // [128][100]
    // phase 2 (aliased)
    float* Hf  = sf;                   // [128][132]
    float* W2f = Hf + 128 * E_HS;      // [32][132]

    __shared__ int   srcb[128], tgtb[128], tgtn[128];
    __shared__ float mks[128];

    const int tid  = threadIdx.x;
    const int lane = tid & 31;
    const int wrp  = tid >> 5;
    const int wm   = wrp & 7;
    const int wn   = wrp >> 3;
    const int m0   = wm * 16;
    const size_t rowBase = (size_t)blockIdx.x * 128;

    if (tid < 128) {
        size_t row = rowBase + tid;
        int b = (int)(row / CE);
        int e = (int)(row - (size_t)b * CE);
        srcb[tid] = (b * CN + srcI[e]) * CD;
        tgtb[tid] = (b * CN + tgtI[e]) * CD;
        tgtn[tid] = b * CN + tgtI[e];
        mks[tid]  = mask[row];
    }
    __syncthreads();

    float acc1[32];
#pragma unroll
    for (int i = 0; i < 32; i++) acc1[i] = 0.f;

    for (int ch = 0; ch < 3; ch++) {
        const int k0 = ch * 96;
#pragma unroll
        for (int i = 0; i < 24; i++) {
            int e = tid + 512 * i;
            int r = e / 96, c = e % 96;
            int gk = k0 + c;
            float f;
            if (gk < 128)      f = normed[srcb[r] + gk];
            else if (gk < 256) f = normed[tgtb[r] + gk - 128];
            else               f = edge_attr[(rowBase + r) * CED + gk - 256];
            Af[r * E_AS + c] = __uint_as_float(tf32_of(f));
        }
#pragma unroll
        for (int i = 0; i < 24; i++) {
            int e = tid + 512 * i;
            int n = e & 127, kl = e >> 7;
            Wf[n * E_AS + kl] = __uint_as_float(tf32_of(e_w1[(size_t)(k0 + kl) * CD + n]));
        }
        __syncthreads();
#pragma unroll
        for (int ks = 0; ks < 6; ks++) {
            int kb = ks * 16;
            uint32_t au[4], av[4];
            lda8(au, Af, E_AS, m0, kb, lane);
            lda8(av, Af, E_AS, m0, kb + 8, lane);
#pragma unroll
            for (int g = 0; g < 4; g++) {
                mma_k16_n16(&acc1[(g*2+0)*4], &acc1[(g*2+1)*4],
                            au, av, Wf, E_AS, wn * 64 + g * 16, kb, lane);
            }
        }
        __syncthreads();
    }

    // h = relu(acc1 + b1) -> Hf (aliased; all phase-1 reads done)
    {
        int r0 = m0 + (lane >> 2);
#pragma unroll
        for (int t = 0; t < 8; t++) {
            int col = wn * 64 + t * 8 + 2 * (lane & 3);
            float bb0 = e_b1[col], bb1 = e_b1[col + 1];
#pragma unroll
            for (int half = 0; half < 2; half++) {
                int r = r0 + half * 8;
                float v0 = fmaxf(acc1[t * 4 + half * 2 + 0] + bb0, 0.f);
                float v1 = fmaxf(acc1[t * 4 + half * 2 + 1] + bb1, 0.f);
                Hf[r * E_HS + col]     = __uint_as_float(tf32_of(v0));
                Hf[r * E_HS + col + 1] = __uint_as_float(tf32_of(v1));
            }
        }
    }
    // W2 [k=128][n=32] -> W2f[n][k]
#pragma unroll
    for (int i = 0; i < 8; i++) {
        int e = tid + 512 * i;
        int k = e >> 5, n = e & 31;
        W2f[n * E_HS + k] = __uint_as_float(tf32_of(e_w2[(size_t)k * CED + n]));
    }
    __syncthreads();

    // stage 2: msgs = h @ e_w2  (warp: 16 rows x n16 at wn*16)
    float acc2[8];
#pragma unroll
    for (int i = 0; i < 8; i++) acc2[i] = 0.f;
#pragma unroll
    for (int ks = 0; ks < 8; ks++) {
        int kb = ks * 16;
        uint32_t au[4], av[4];
        lda8(au, Hf, E_HS, m0, kb, lane);
        lda8(av, Hf, E_HS, m0, kb + 8, lane);
        mma_k16_n16(&acc2[0], &acc2[4], au, av, W2f, E_HS, wn * 16, kb, lane);
    }

    // epilogue: bias, mask, store msgs, scatter
    {
        int r0 = m0 + (lane >> 2);
#pragma unroll
        for (int t = 0; t < 2; t++) {
            int col = wn * 16 + t * 8 + 2 * (lane & 3);
            float bb0 = e_b2[col], bb1 = e_b2[col + 1];
#pragma unroll
            for (int half = 0; half < 2; half++) {
                int r = r0 + half * 8;
                float mk = mks[r];
                float v0 = (acc2[t * 4 + half * 2 + 0] + bb0) * mk;
                float v1 = (acc2[t * 4 + half * 2 + 1] + bb1) * mk;
                size_t be = rowBase + r;
                msgs_out[be * 32 + col]     = v0;
                msgs_out[be * 32 + col + 1] = v1;
                float* ap = &agg[(size_t)tgtn[r] * CED + col];
                atomicAdd(ap, v0);
                atomicAdd(ap + 1, v1);
            }
        }
    }
}

// ---------------------------------------------------------------------------
// TF32 GRU GEMMs. A = [a1 (*a2 if !RU) | a3] (128 x 256).
// RU: two weights (r,u), sigmoid; else one (c), tanh.
// SMEM fp32: A[128x260] + W[128x132] = 200,704 B
// ---------------------------------------------------------------------------
constexpr int G_AS = 260;
constexpr int G_WS = 132;
constexpr size_t GRU_SMEM = (size_t)(128 * G_AS + 128 * G_WS) * 4;  // 200,704 B

template<bool RU>
__global__ void __launch_bounds__(512) gru_tc_k(
    const float* __restrict__ a1, const float* __restrict__ a2,
    const float* __restrict__ a3,
    const float* __restrict__ w0p, const float* __restrict__ b0p,
    const float* __restrict__ w1p, const float* __restrict__ b1p,
    float* __restrict__ out0, float* __restrict__ out1)
{
    extern __shared__ float sf[];
    float* Af = sf;                  // [128][260]
    float* Wf = Af + 128 * G_AS;     // [128][132]

    const int tid  = threadIdx.x;
    const int lane = tid & 31;
    const int wrp  = tid >> 5;
    const int wm   = wrp & 7;
    const int wn   = wrp >> 3;
    const int m0   = wm * 16;
    const size_t rowBase = (size_t)blockIdx.x * 128;

#pragma unroll
    for (int i = 0; i < 64; i++) {
        int e = tid + 512 * i;
        int r = e >> 8, k = e & 255;
        size_t base = (rowBase + r) * 128;
        float f;
        if (k < 128) {
            f = a1[base + k];
            if (!RU) f *= a2[base + k];
        } else {
            f = a3[base + k - 128];
        }
        Af[r * G_AS + k] = __uint_as_float(tf32_of(f));
    }
    __syncthreads();

    const int NW = RU ? 2 : 1;
    float acc[2][32];
#pragma unroll
    for (int s = 0; s < 2; s++)
#pragma unroll
        for (int i = 0; i < 32; i++) acc[s][i] = 0.f;

    for (int ws = 0; ws < NW; ws++) {
        const float* w = (ws == 0) ? w0p : w1p;
        for (int kc = 0; kc < 2; kc++) {
#pragma unroll
            for (int i = 0; i < 32; i++) {
                int e = tid + 512 * i;
                int n = e & 127, kl = e >> 7;
                Wf[n * G_WS + kl] = __uint_as_float(tf32_of(w[(size_t)(kc * 128 + kl) * CD + n]));
            }
            __syncthreads();
#pragma unroll
            for (int ks = 0; ks < 8; ks++) {
                int kb = ks * 16;
                uint32_t au[4], av[4];
                lda8(au, Af, G_AS, m0, kc * 128 + kb, lane);
                lda8(av, Af, G_AS, m0, kc * 128 + kb + 8, lane);
#pragma unroll
                for (int g = 0; g < 4; g++) {
                    mma_k16_n16(&acc[ws][(g*2+0)*4], &acc[ws][(g*2+1)*4],
                                au, av, Wf, G_WS, wn * 64 + g * 16, kb, lane);
                }
            }
            __syncthreads();
        }
    }

    {
        int r0 = m0 + (lane >> 2);
#pragma unroll
        for (int s = 0; s < 2; s++) {
            if (s >= NW) break;
            const float* bias = (s == 0) ? b0p : b1p;
            float* outp = (s == 0) ? out0 : out1;
#pragma unroll
            for (int t = 0; t < 8; t++) {
                int col = wn * 64 + t * 8 + 2 * (lane & 3);
                float bb0 = bias[col], bb1 = bias[col + 1];
#pragma unroll
                for (int half = 0; half < 2; half++) {
                    size_t r = rowBase + r0 + half * 8;
                    float v0 = acc[s][t * 4 + half * 2 + 0] + bb0;
                    float v1 = acc[s][t * 4 + half * 2 + 1] + bb1;
                    if (RU) {
                        v0 = 1.f / (1.f + expf(-v0));
                        v1 = 1.f / (1.f + expf(-v1));
                    } else {
                        v0 = tanhf(v0);
                        v1 = tanhf(v1);
                    }
                    float2 o; o.x = v0; o.y = v1;
                    *reinterpret_cast<float2*>(&outp[r * 128 + col]) = o;
                }
            }
        }
    }
}

// ---------------------------------------------------------------------------
// proj GEMM with fused count-normalization (small, scalar)
// ---------------------------------------------------------------------------
__global__ void __launch_bounds__(256) gemm_proj_k(
    const float* __restrict__ agg, const float* __restrict__ counts,
    const float* __restrict__ W, const float* __restrict__ bias,
    float* __restrict__ C)
{
    __shared__ float As[16][68];
    __shared__ float Bs[16][64];
    __shared__ float rcnt[64];

    const int tid = threadIdx.x;
    const int tx = tid & 15;
    const int ty = tid >> 4;
    const size_t rowBase = (size_t)blockIdx.y * 64;
    const int colBase = blockIdx.x * 64;

    if (tid < 64) rcnt[tid] = 1.f / fmaxf(counts[tid], 1.f);
    __syncthreads();

    float acc[4][4];
#pragma unroll
    for (int i = 0; i < 4; i++)
#pragma unroll
        for (int j = 0; j < 4; j++) acc[i][j] = 0.f;

    for (int k0 = 0; k0 < 32; k0 += 16) {
#pragma unroll
        for (int i = 0; i < 4; i++) {
            int e = tid + 256 * i;
            int r = e >> 4, c = e & 15;
            As[c][r] = agg[(rowBase + r) * 32 + k0 + c] * rcnt[r];
        }
#pragma unroll
        for (int i = 0; i < 4; i++) {
            int e = tid + 256 * i;
            int r = e >> 6, c = e & 63;
            Bs[r][c] = W[(size_t)(k0 + r) * CD + colBase + c];
        }
        __syncthreads();
#pragma unroll
        for (int k = 0; k < 16; k++) {
            float a[4], b[4];
#pragma unroll
            for (int i = 0; i < 4; i++) a[i] = As[k][ty + 16 * i];
#pragma unroll
            for (int j = 0; j < 4; j++) b[j] = Bs[k][tx + 16 * j];
#pragma unroll
            for (int i = 0; i < 4; i++)
#pragma unroll
                for (int j = 0; j < 4; j++)
                    acc[i][j] = fmaf(a[i], b[j], acc[i][j]);
        }
        __syncthreads();
    }

#pragma unroll
    for (int i = 0; i < 4; i++) {
        size_t r = rowBase + ty + 16 * i;
#pragma unroll
        for (int j = 0; j < 4; j++) {
            int c = colBase + tx + 16 * j;
            C[r * CD + c] = acc[i][j] + bias[c];
        }
    }
}

// ---------------------------------------------------------------------------
// Elementwise kernels
// ---------------------------------------------------------------------------
__global__ void ln_k(const float* __restrict__ in, const float* __restrict__ g,
                     const float* __restrict__ bb, float* __restrict__ out)
{
    const size_t row = blockIdx.x;
    const int d = threadIdx.x;
    float v = in[row * 128 + d];
    float s = v;
#pragma unroll
    for (int o = 16; o > 0; o >>= 1) s += __shfl_xor_sync(~0u, s, o);
    __shared__ float sm[4], sq[4];
    int w = d >> 5, l = d & 31;
    if (l == 0) sm[w] = s;
    __syncthreads();
    float mean = (sm[0] + sm[1] + sm[2] + sm[3]) * (1.f / 128.f);
    float dv = v - mean;
    float q = dv * dv;
#pragma unroll
    for (int o = 16; o > 0; o >>= 1) q += __shfl_xor_sync(~0u, q, o);
    if (l == 0) sq[w] = q;
    __syncthreads();
    float var = (sq[0] + sq[1] + sq[2] + sq[3]) * (1.f / 128.f);
    out[row * 128 + d] = dv * rsqrtf(var + 1e-5f) * g[d] + bb[d];
}

__global__ void gru_ln2_k(const float* __restrict__ nf, const float* __restrict__ normed,
                          const float* __restrict__ u, const float* __restrict__ cand,
                          const float* __restrict__ g, const float* __restrict__ bb,
                          float* __restrict__ x_out, float* __restrict__ n2_out)
{
    const size_t row = blockIdx.x;
    const int d = threadIdx.x;
    size_t i = row * 128 + d;
    float uu = u[i];
    float xv = nf[i] + (1.f - uu) * normed[i] + uu * cand[i];
    x_out[i] = xv;
    float s = xv;
#pragma unroll
    for (int o = 16; o > 0; o >>= 1) s += __shfl_xor_sync(~0u, s, o);
    __shared__ float sm[4], sq[4];
    int w = d >> 5, l = d & 31;
    if (l == 0) sm[w] = s;
    __syncthreads();
    float mean = (sm[0] + sm[1] + sm[2] + sm[3]) * (1.f / 128.f);
    float dv = xv - mean;
    float q = dv * dv;
#pragma unroll
    for (int o = 16; o > 0; o >>= 1) q += __shfl_xor_sync(~0u, q, o);
    if (l == 0) sq[w] = q;
    __syncthreads();
    float var = (sq[0] + sq[1] + sq[2] + sq[3]) * (1.f / 128.f);
    n2_out[i] = dv * rsqrtf(var + 1e-5f) * g[d] + bb[d];
}

__global__ void counts_k(const int* __restrict__ tgt, float* __restrict__ counts)
{
    int e = threadIdx.x;
    if (e < CE) atomicAdd(&counts[tgt[e]], 1.f);
}

// ---------------------------------------------------------------------------
extern "C" void kernel_launch(void* const* d_in, const int* in_sizes, int n_in,
                              void* d_out, int out_size)
{
    const float* nf        = (const float*)d_in[0];
    const float* edge_attr = (const float*)d_in[1];
    const int*   src       = (const int*)  d_in[2];
    const int*   tgt       = (const int*)  d_in[3];
    const float* mask      = (const float*)d_in[4];
    const float* e_w1   = (const float*)d_in[6];
    const float* e_b1   = (const float*)d_in[7];
    const float* e_w2   = (const float*)d_in[8];
    const float* e_b2   = (const float*)d_in[9];
    const float* proj_w = (const float*)d_in[10];
    const float* proj_b = (const float*)d_in[11];
    const float* r_w    = (const float*)d_in[12];
    const float* r_b    = (const float*)d_in[13];
    const float* u_w    = (const float*)d_in[14];
    const float* u_b    = (const float*)d_in[15];
    const float* c_w    = (const float*)d_in[16];
    const float* c_b    = (const float*)d_in[17];
    const float* n1_g   = (const float*)d_in[18];
    const float* n1_b   = (const float*)d_in[19];
    const float* n2_g   = (const float*)d_in[20];
    const float* n2_b   = (const float*)d_in[21];
    const float* f_w1   = (const float*)d_in[22];
    const float* f_b1   = (const float*)d_in[23];
    const float* f_w2   = (const float*)d_in[24];
    const float* f_b2   = (const float*)d_in[25];

    float* out_x    = (float*)d_out;
    float* out_msgs = out_x + SZ_NORMED;

    float *p_normed, *p_agg, *p_counts, *p_proj, *p_r, *p_u, *p_cand, *p_x, *p_n2;
    cudaGetSymbolAddress((void**)&p_normed, g_normed);
    cudaGetSymbolAddress((void**)&p_agg,    g_agg);
    cudaGetSymbolAddress((void**)&p_counts, g_counts);
    cudaGetSymbolAddress((void**)&p_proj,   g_proj);
    cudaGetSymbolAddress((void**)&p_r,      g_r);
    cudaGetSymbolAddress((void**)&p_u,      g_u);
    cudaGetSymbolAddress((void**)&p_cand,   g_cand);
    cudaGetSymbolAddress((void**)&p_x,      g_x);
    cudaGetSymbolAddress((void**)&p_n2,     g_n2);

    cudaFuncSetAttribute(ffn_tc_k,  cudaFuncAttributeMaxDynamicSharedMemorySize, (int)FFN_SMEM);
    cudaFuncSetAttribute(edge_tc_k, cudaFuncAttributeMaxDynamicSharedMemorySize, (int)EDGE_SMEM);
    cudaFuncSetAttribute(gru_tc_k<true>,  cudaFuncAttributeMaxDynamicSharedMemorySize, (int)GRU_SMEM);
    cudaFuncSetAttribute(gru_tc_k<false>, cudaFuncAttributeMaxDynamicSharedMemorySize, (int)GRU_SMEM);

    cudaMemsetAsync(p_agg, 0, SZ_AGG * sizeof(float));
    cudaMemsetAsync(p_counts, 0, CN * sizeof(float));

    // 1. LN1
    ln_k<<<(unsigned)MN, 128>>>(nf, n1_g, n1_b, p_normed);

    // 2. counts
    counts_k<<<1, 128>>>(tgt, p_counts);

    // 3. TF32 edge pipeline (gather + MLP + mask + scatter)
    edge_tc_k<<<(unsigned)(ME / 128), 512, EDGE_SMEM>>>(
        p_normed, edge_attr, src, tgt, e_w1, e_b1, e_w2, e_b2, mask,
        out_msgs, p_agg);

    // 4. proj = (agg/cnt) @ proj_w + proj_b
    gemm_proj_k<<<dim3(2, (unsigned)(MN / 64)), 256>>>(
        p_agg, p_counts, proj_w, proj_b, p_proj);

    // 5. r,u = sigmoid([normed|proj] @ {r_w,u_w} + b)
    gru_tc_k<true><<<(unsigned)(MN / 128), 512, GRU_SMEM>>>(
        p_normed, nullptr, p_proj, r_w, r_b, u_w, u_b, p_r, p_u);

    // 6. cand = tanh([r*normed|proj] @ c_w + c_b)
    gru_tc_k<false><<<(unsigned)(MN / 128), 512, GRU_SMEM>>>(
        p_normed, p_r, p_proj, c_w, c_b, nullptr, nullptr, p_cand, nullptr);

    // 7. x = nf + (1-u)*normed + u*cand ; n2 = LN(x)
    gru_ln2_k<<<(unsigned)MN, 128>>>(nf, p_normed, p_u, p_cand, n2_g, n2_b, p_x, p_n2);

    // 8. TF32 fused FFN
    ffn_tc_k<<<(unsigned)(MN / 128), 512, FFN_SMEM>>>(
        p_n2, f_w1, f_b1, f_w2, f_b2, p_x, out_x);
}

// round 8
// speedup vs baseline: 2.1486x; 1.0433x over previous
#include <cuda_runtime.h>
#include <cuda_bf16.h>
#include <math.h>
#include <stdint.h>

constexpr int CB  = 2048;
constexpr int CN  = 64;
constexpr int CE  = 126;
constexpr int CD  = 128;
constexpr int CED = 32;
constexpr int CF  = 2048;
constexpr int CK1 = 2*CD + CED;  // 288

constexpr size_t MN = (size_t)CB * CN;      // 131072
constexpr size_t ME = (size_t)CB * CE;      // 258048

constexpr size_t SZ_NORMED = MN * CD;
constexpr size_t SZ_AGG    = MN * CED;
constexpr size_t SZ_RUC    = MN * CD;

__device__ float g_normed[SZ_NORMED];
__device__ float g_agg   [SZ_AGG];
__device__ float g_counts[CN];
__device__ float g_proj  [SZ_RUC];
__device__ float g_r     [SZ_RUC];
__device__ float g_u     [SZ_RUC];
__device__ float g_x     [SZ_RUC];
__device__ float g_n2    [SZ_RUC];

// ---------------------------------------------------------------------------
// TF32 mma helpers with interleaved-k SMEM layout.
// Logical k within each 8-group stored at physical (k&3)*2 + (k>>2)&1, so the
// (k, k+4) pair every fragment lane needs is one aligned float2.
// All strides are ≡ 8 (mod 32) -> conflict-free LDS.64 phases.
// ---------------------------------------------------------------------------
__device__ __forceinline__ int perm_k(int k) {
    return (k & ~7) | ((k & 3) << 1) | ((k >> 2) & 1);
}

__device__ __forceinline__ uint32_t tf32_of(float f) {
    uint32_t u;
    asm("cvt.rna.tf32.f32 %0, %1;" : "=r"(u) : "f"(f));
    return u;
}

__device__ __forceinline__ void mma_tf32(float* d, const uint32_t (&a)[4],
                                         const uint32_t (&b)[2])
{
    asm volatile(
        "mma.sync.aligned.m16n8k8.row.col.f32.tf32.tf32.f32 "
        "{%0,%1,%2,%3},{%4,%5,%6,%7},{%8,%9},{%0,%1,%2,%3};"
        : "+f"(d[0]), "+f"(d[1]), "+f"(d[2]), "+f"(d[3])
        : "r"(a[0]), "r"(a[1]), "r"(a[2]), "r"(a[3]), "r"(b[0]), "r"(b[1]));
}

// A fragments for one m16 x k16 step: au (k8 low), av (k8 high). 4 LDS.64.
__device__ __forceinline__ void lda16v(uint32_t (&au)[4], uint32_t (&av)[4],
                                       const float* A, int S, int row, int kb, int lane)
{
    int r = row + (lane >> 2);
    int c = kb + ((lane & 3) << 1);
    float2 p0 = *reinterpret_cast<const float2*>(&A[r * S + c]);
    float2 q0 = *reinterpret_cast<const float2*>(&A[(r + 8) * S + c]);
    float2 p1 = *reinterpret_cast<const float2*>(&A[r * S + c + 8]);
    float2 q1 = *reinterpret_cast<const float2*>(&A[(r + 8) * S + c + 8]);
    au[0] = __float_as_uint(p0.x); au[2] = __float_as_uint(p0.y);
    au[1] = __float_as_uint(q0.x); au[3] = __float_as_uint(q0.y);
    av[0] = __float_as_uint(p1.x); av[2] = __float_as_uint(p1.y);
    av[1] = __float_as_uint(q1.x); av[3] = __float_as_uint(q1.y);
}

__device__ __forceinline__ void ldb8v(uint32_t (&b)[2], const float* W, int S,
                                      int nb, int kb, int lane)
{
    int n = nb + (lane >> 2);
    int c = kb + ((lane & 3) << 1);
    float2 p = *reinterpret_cast<const float2*>(&W[n * S + c]);
    b[0] = __float_as_uint(p.x); b[1] = __float_as_uint(p.y);
}

// one n16 x k16 tile for one m16 A-frag pair: 4 ldb8v + 4 mma
__device__ __forceinline__ void mma_k16_n16(float* d0, float* d1,
    const uint32_t (&au)[4], const uint32_t (&av)[4],
    const float* W, int S, int nb, int kb, int lane)
{
    uint32_t b[2];
    ldb8v(b, W, S, nb, kb, lane);         mma_tf32(d0, au, b);
    ldb8v(b, W, S, nb, kb + 8, lane);     mma_tf32(d0, av, b);
    ldb8v(b, W, S, nb + 8, kb, lane);     mma_tf32(d1, au, b);
    ldb8v(b, W, S, nb + 8, kb + 8, lane); mma_tf32(d1, av, b);
}

// one n16 x k16 tile for TWO m16 A-frag pairs (B loaded once): 4 ldb8v + 8 mma
__device__ __forceinline__ void mma_k16_n16_m32(float* d00, float* d01,
    float* d10, float* d11,
    const uint32_t (&a0u)[4], const uint32_t (&a0v)[4],
    const uint32_t (&a1u)[4], const uint32_t (&a1v)[4],
    const float* W, int S, int nb, int kb, int lane)
{
    uint32_t b[2];
    ldb8v(b, W, S, nb, kb, lane);         mma_tf32(d00, a0u, b); mma_tf32(d10, a1u, b);
    ldb8v(b, W, S, nb, kb + 8, lane);     mma_tf32(d00, a0v, b); mma_tf32(d10, a1v, b);
    ldb8v(b, W, S, nb + 8, kb, lane);     mma_tf32(d01, a0u, b); mma_tf32(d11, a1u, b);
    ldb8v(b, W, S, nb + 8, kb + 8, lane); mma_tf32(d01, a0v, b); mma_tf32(d11, a1v, b);
}

__device__ __forceinline__ float gelu_f(float v) {
    return 0.5f * v * (1.f + erff(v * 0.70710678118654752f));
}

// ---------------------------------------------------------------------------
// TF32 fused FFN: out = xres + gelu(n2 @ W1 + b1) @ W2 + b2
// 128 rows/block, 512 thr, 16 chunks of 128 FFN cols, warps m32n32.
// ---------------------------------------------------------------------------
constexpr int F_S = 136;                                   // 136 % 32 == 8
constexpr size_t FFN_SMEM = (size_t)3 * 128 * F_S * 4;     // 208,896 B

__global__ void __launch_bounds__(512) ffn_tc_k(
    const float* __restrict__ n2, const float* __restrict__ w1,
    const float* __restrict__ b1, const float* __restrict__ w2,
    const float* __restrict__ b2, const float* __restrict__ xres,
    float* __restrict__ out)
{
    extern __shared__ float sf[];
    float* Af = sf;                 // [128][136]
    float* Hf = Af + 128 * F_S;     // [128][136]
    float* Wf = Hf + 128 * F_S;     // [128][136]

    const int tid  = threadIdx.x;
    const int lane = tid & 31;
    const int wrp  = tid >> 5;
    const int m0   = (wrp & 3) * 32;
    const int n0   = (wrp >> 2) * 32;
    const size_t rowBase = (size_t)blockIdx.x * 128;

#pragma unroll
    for (int i = 0; i < 32; i++) {
        int e = tid + 512 * i;
        int r = e >> 7, k = e & 127;
        Af[r * F_S + perm_k(k)] = __uint_as_float(tf32_of(n2[(rowBase + r) * 128 + k]));
    }

    float acc2[32];                 // [mh][j][4]: (mh*4+j)*4+q
#pragma unroll
    for (int i = 0; i < 32; i++) acc2[i] = 0.f;

    __syncthreads();

    for (int ch = 0; ch < 16; ch++) {
        // W1 chunk [k=128][n=128] -> Wf[n][perm k]
#pragma unroll
        for (int i = 0; i < 32; i++) {
            int e = tid + 512 * i;
            int n = e & 127, k = e >> 7;
            Wf[n * F_S + perm_k(k)] =
                __uint_as_float(tf32_of(w1[(size_t)k * 2048 + ch * 128 + n]));
        }
        __syncthreads();

        // stage 1: acc1(m32 x n32) = A @ W1chunk
        float acc1[32];
#pragma unroll
        for (int i = 0; i < 32; i++) acc1[i] = 0.f;

#pragma unroll
        for (int ks = 0; ks < 8; ks++) {
            int kb = ks * 16;
            uint32_t a0u[4], a0v[4], a1u[4], a1v[4];
            lda16v(a0u, a0v, Af, F_S, m0,      kb, lane);
            lda16v(a1u, a1v, Af, F_S, m0 + 16, kb, lane);
#pragma unroll
            for (int nt = 0; nt < 2; nt++) {
                mma_k16_n16_m32(&acc1[(nt*2+0)*4], &acc1[(nt*2+1)*4],
                                &acc1[(4+nt*2+0)*4], &acc1[(4+nt*2+1)*4],
                                a0u, a0v, a1u, a1v, Wf, F_S, n0 + nt * 16, kb, lane);
            }
        }

        // h = gelu(acc1 + b1) -> Hf (interleaved-k for stage 2)
        {
            int r0 = lane >> 2;
#pragma unroll
            for (int mh = 0; mh < 2; mh++)
#pragma unroll
            for (int j = 0; j < 4; j++) {
                int col = n0 + j * 8 + 2 * (lane & 3);
                float bb0 = b1[ch * 128 + col];
                float bb1 = b1[ch * 128 + col + 1];
#pragma unroll
                for (int half = 0; half < 2; half++) {
                    int r = m0 + mh * 16 + r0 + half * 8;
                    float v0 = gelu_f(acc1[(mh*4+j)*4 + half*2 + 0] + bb0);
                    float v1 = gelu_f(acc1[(mh*4+j)*4 + half*2 + 1] + bb1);
                    Hf[r * F_S + perm_k(col)]     = __uint_as_float(tf32_of(v0));
                    Hf[r * F_S + perm_k(col + 1)] = __uint_as_float(tf32_of(v1));
                }
            }
        }
        __syncthreads();

        // W2 chunk [k=128][n=128] -> Wf[n][perm k]
#pragma unroll
        for (int i = 0; i < 32; i++) {
            int e = tid + 512 * i;
            int n = e & 127, k = e >> 7;
            Wf[n * F_S + perm_k(k)] =
                __uint_as_float(tf32_of(w2[(size_t)(ch * 128 + k) * 128 + n]));
        }
        __syncthreads();

        // stage 2: acc2(m32 x n32) += H @ W2chunk
#pragma unroll
        for (int ks = 0; ks < 8; ks++) {
            int kb = ks * 16;
            uint32_t a0u[4], a0v[4], a1u[4], a1v[4];
            lda16v(a0u, a0v, Hf, F_S, m0,      kb, lane);
            lda16v(a1u, a1v, Hf, F_S, m0 + 16, kb, lane);
#pragma unroll
            for (int nt = 0; nt < 2; nt++) {
                mma_k16_n16_m32(&acc2[(nt*2+0)*4], &acc2[(nt*2+1)*4],
                                &acc2[(4+nt*2+0)*4], &acc2[(4+nt*2+1)*4],
                                a0u, a0v, a1u, a1v, Wf, F_S, n0 + nt * 16, kb, lane);
            }
        }
        __syncthreads();
    }

    // epilogue: out = acc2 + b2 + xres
    {
        int r0 = lane >> 2;
#pragma unroll
        for (int mh = 0; mh < 2; mh++)
#pragma unroll
        for (int j = 0; j < 4; j++) {
            int col = n0 + j * 8 + 2 * (lane & 3);
            float bb0 = b2[col], bb1 = b2[col + 1];
#pragma unroll
            for (int half = 0; half < 2; half++) {
                size_t r = rowBase + m0 + mh * 16 + r0 + half * 8;
                float2 xr = *reinterpret_cast<const float2*>(&xres[r * 128 + col]);
                float2 o;
                o.x = acc2[(mh*4+j)*4 + half*2 + 0] + bb0 + xr.x;
                o.y = acc2[(mh*4+j)*4 + half*2 + 1] + bb1 + xr.y;
                *reinterpret_cast<float2*>(&out[r * 128 + col]) = o;
            }
        }
    }
}

// ---------------------------------------------------------------------------
// TF32 fused edge pipeline (interleaved-k), 128 rows/block, 512 thr.
// ---------------------------------------------------------------------------
constexpr int E_AS = 104;   // % 32 == 8
constexpr int E_HS = 136;
constexpr size_t EDGE_SMEM = (size_t)(2 * 128 * E_AS) * 4;   // 106,496 B

__global__ void __launch_bounds__(512) edge_tc_k(
    const float* __restrict__ normed, const float* __restrict__ edge_attr,
    const int* __restrict__ srcI, const int* __restrict__ tgtI,
    const float* __restrict__ e_w1, const float* __restrict__ e_b1,
    const float* __restrict__ e_w2, const float* __restrict__ e_b2,
    const float* __restrict__ mask,
    float* __restrict__ msgs_out, float* __restrict__ agg)
{
    extern __shared__ float sf[];
    float* Af = sf;                    // [128][104]
    float* Wf = Af + 128 * E_AS;       // [128][104]
    float* Hf  = sf;                   // [128][136]  (aliased phase 2)
    float* W2f = Hf + 128 * E_HS;      // [32][136]

    __shared__ int   srcb[128], tgtb[128], tgtn[128];
    __shared__ float mks[128];

    const int tid  = threadIdx.x;
    const int lane = tid & 31;
    const int wrp  = tid >> 5;
    const int wm   = wrp & 7;
    const int wn   = wrp >> 3;
    const int m0   = wm * 16;
    const size_t rowBase = (size_t)blockIdx.x * 128;

    if (tid < 128) {
        size_t row = rowBase + tid;
        int b = (int)(row / CE);
        int e = (int)(row - (size_t)b * CE);
        srcb[tid] = (b * CN + srcI[e]) * CD;
        tgtb[tid] = (b * CN + tgtI[e]) * CD;
        tgtn[tid] = b * CN + tgtI[e];
        mks[tid]  = mask[row];
    }
    __syncthreads();

    float acc1[32];
#pragma unroll
    for (int i = 0; i < 32; i++) acc1[i] = 0.f;

    for (int ch = 0; ch < 3; ch++) {
        const int k0 = ch * 96;
#pragma unroll
        for (int i = 0; i < 24; i++) {
            int e = tid + 512 * i;
            int r = e / 96, c = e % 96;
            int gk = k0 + c;
            float f;
            if (gk < 128)      f = normed[srcb[r] + gk];
            else if (gk < 256) f = normed[tgtb[r] + gk - 128];
            else               f = edge_attr[(rowBase + r) * CED + gk - 256];
            Af[r * E_AS + perm_k(c)] = __uint_as_float(tf32_of(f));
        }
#pragma unroll
        for (int i = 0; i < 24; i++) {
            int e = tid + 512 * i;
            int n = e & 127, kl = e >> 7;
            Wf[n * E_AS + perm_k(kl)] =
                __uint_as_float(tf32_of(e_w1[(size_t)(k0 + kl) * CD + n]));
        }
        __syncthreads();
#pragma unroll
        for (int ks = 0; ks < 6; ks++) {
            int kb = ks * 16;
            uint32_t au[4], av[4];
            lda16v(au, av, Af, E_AS, m0, kb, lane);
#pragma unroll
            for (int g = 0; g < 4; g++) {
                mma_k16_n16(&acc1[(g*2+0)*4], &acc1[(g*2+1)*4],
                            au, av, Wf, E_AS, wn * 64 + g * 16, kb, lane);
            }
        }
        __syncthreads();
    }

    // h = relu(acc1 + b1) -> Hf
    {
        int r0 = m0 + (lane >> 2);
#pragma unroll
        for (int t = 0; t < 8; t++) {
            int col = wn * 64 + t * 8 + 2 * (lane & 3);
            float bb0 = e_b1[col], bb1 = e_b1[col + 1];
#pragma unroll
            for (int half = 0; half < 2; half++) {
                int r = r0 + half * 8;
                float v0 = fmaxf(acc1[t * 4 + half * 2 + 0] + bb0, 0.f);
                float v1 = fmaxf(acc1[t * 4 + half * 2 + 1] + bb1, 0.f);
                Hf[r * E_HS + perm_k(col)]     = __uint_as_float(tf32_of(v0));
                Hf[r * E_HS + perm_k(col + 1)] = __uint_as_float(tf32_of(v1));
            }
        }
    }
#pragma unroll
    for (int i = 0; i < 8; i++) {
        int e = tid + 512 * i;
        int k = e >> 5, n = e & 31;
        W2f[n * E_HS + perm_k(k)] = __uint_as_float(tf32_of(e_w2[(size_t)k * CED + n]));
    }
    __syncthreads();

    float acc2[8];
#pragma unroll
    for (int i = 0; i < 8; i++) acc2[i] = 0.f;
#pragma unroll
    for (int ks = 0; ks < 8; ks++) {
        int kb = ks * 16;
        uint32_t au[4], av[4];
        lda16v(au, av, Hf, E_HS, m0, kb, lane);
        mma_k16_n16(&acc2[0], &acc2[4], au, av, W2f, E_HS, wn * 16, kb, lane);
    }

    {
        int r0 = m0 + (lane >> 2);
#pragma unroll
        for (int t = 0; t < 2; t++) {
            int col = wn * 16 + t * 8 + 2 * (lane & 3);
            float bb0 = e_b2[col], bb1 = e_b2[col + 1];
#pragma unroll
            for (int half = 0; half < 2; half++) {
                int r = r0 + half * 8;
                float mk = mks[r];
                float v0 = (acc2[t * 4 + half * 2 + 0] + bb0) * mk;
                float v1 = (acc2[t * 4 + half * 2 + 1] + bb1) * mk;
                size_t be = rowBase + r;
                msgs_out[be * 32 + col]     = v0;
                msgs_out[be * 32 + col + 1] = v1;
                float* ap = &agg[(size_t)tgtn[r] * CED + col];
                atomicAdd(ap, v0);
                atomicAdd(ap + 1, v1);
            }
        }
    }
}

// ---------------------------------------------------------------------------
// TF32 GRU GEMMs (interleaved-k). RU=true: r,u (sigmoid). RU=false: cand +
// fused GRU-combine + LN2 epilogue (writes x and n2; cand never hits HBM).
// ---------------------------------------------------------------------------
constexpr int G_AS = 264;   // % 32 == 8
constexpr int G_WS = 136;
constexpr size_t GRU_SMEM = (size_t)(128 * G_AS + 128 * G_WS) * 4;  // 204,800 B

template<bool RU>
__global__ void __launch_bounds__(512) gru_tc_k(
    const float* __restrict__ a1, const float* __restrict__ a2,
    const float* __restrict__ a3,
    const float* __restrict__ w0p, const float* __restrict__ b0p,
    const float* __restrict__ w1p, const float* __restrict__ b1p,
    float* __restrict__ out0, float* __restrict__ out1,
    const float* __restrict__ uu, const float* __restrict__ nfp,
    const float* __restrict__ g2, const float* __restrict__ bb2)
{
    extern __shared__ float sf[];
    float* Af = sf;                  // [128][264]
    float* Wf = Af + 128 * G_AS;     // [128][136]

    const int tid  = threadIdx.x;
    const int lane = tid & 31;
    const int wrp  = tid >> 5;
    const int wm   = wrp & 7;
    const int wn   = wrp >> 3;
    const int m0   = wm * 16;
    const size_t rowBase = (size_t)blockIdx.x * 128;

#pragma unroll
    for (int i = 0; i < 64; i++) {
        int e = tid + 512 * i;
        int r = e >> 8, k = e & 255;
        size_t base = (rowBase + r) * 128;
        float f;
        if (k < 128) {
            f = a1[base + k];
            if (!RU) f *= a2[base + k];
        } else {
            f = a3[base + k - 128];
        }
        Af[r * G_AS + perm_k(k)] = __uint_as_float(tf32_of(f));
    }
    __syncthreads();

    constexpr int NW = RU ? 2 : 1;
    float acc[NW][32];
#pragma unroll
    for (int s = 0; s < NW; s++)
#pragma unroll
        for (int i = 0; i < 32; i++) acc[s][i] = 0.f;

    for (int ws = 0; ws < NW; ws++) {
        const float* w = (ws == 0) ? w0p : w1p;
        for (int kc = 0; kc < 2; kc++) {
#pragma unroll
            for (int i = 0; i < 32; i++) {
                int e = tid + 512 * i;
                int n = e & 127, kl = e >> 7;
                Wf[n * G_WS + perm_k(kl)] =
                    __uint_as_float(tf32_of(w[(size_t)(kc * 128 + kl) * CD + n]));
            }
            __syncthreads();
#pragma unroll
            for (int ks = 0; ks < 8; ks++) {
                int kb = ks * 16;
                uint32_t au[4], av[4];
                lda16v(au, av, Af, G_AS, m0, kc * 128 + kb, lane);
#pragma unroll
                for (int g = 0; g < 4; g++) {
                    mma_k16_n16(&acc[ws][(g*2+0)*4], &acc[ws][(g*2+1)*4],
                                au, av, Wf, G_WS, wn * 64 + g * 16, kb, lane);
                }
            }
            __syncthreads();
        }
    }

    if (RU) {
        int r0 = m0 + (lane >> 2);
#pragma unroll
        for (int s = 0; s < NW; s++) {
            const float* bias = (s == 0) ? b0p : b1p;
            float* outp = (s == 0) ? out0 : out1;
#pragma unroll
            for (int t = 0; t < 8; t++) {
                int col = wn * 64 + t * 8 + 2 * (lane & 3);
                float bb0 = bias[col], bb1 = bias[col + 1];
#pragma unroll
                for (int half = 0; half < 2; half++) {
                    size_t r = rowBase + r0 + half * 8;
                    float v0 = 1.f / (1.f + expf(-(acc[s][t*4+half*2+0] + bb0)));
                    float v1 = 1.f / (1.f + expf(-(acc[s][t*4+half*2+1] + bb1)));
                    float2 o; o.x = v0; o.y = v1;
                    *reinterpret_cast<float2*>(&outp[r * 128 + col]) = o;
                }
            }
        }
    } else {
        // cand = tanh(acc + b); x = nf + (1-u)*normed + u*cand; write x, smem X
        float* X = sf;   // reuse Af region as [128][132]
        int r0 = m0 + (lane >> 2);
#pragma unroll
        for (int t = 0; t < 8; t++) {
            int col = wn * 64 + t * 8 + 2 * (lane & 3);
            float bb0 = b0p[col], bb1 = b0p[col + 1];
#pragma unroll
            for (int half = 0; half < 2; half++) {
                int rl = r0 + half * 8;
                size_t gi = (rowBase + rl) * 128 + col;
                float c0 = tanhf(acc[0][t*4+half*2+0] + bb0);
                float c1 = tanhf(acc[0][t*4+half*2+1] + bb1);
                float2 uv  = *reinterpret_cast<const float2*>(&uu[gi]);
                float2 nv  = *reinterpret_cast<const float2*>(&a1[gi]);
                float2 nfv = *reinterpret_cast<const float2*>(&nfp[gi]);
                float x0 = nfv.x + (1.f - uv.x) * nv.x + uv.x * c0;
                float x1 = nfv.y + (1.f - uv.y) * nv.y + uv.y * c1;
                float2 xo; xo.x = x0; xo.y = x1;
                *reinterpret_cast<float2*>(&out0[gi]) = xo;
                *reinterpret_cast<float2*>(&X[rl * 132 + col]) = xo;
            }
        }
        __syncthreads();
        // LN2 over X rows: 4 threads per row, 32 cols each
        {
            int row = tid >> 2, q = tid & 3;
            float vals[32];
            float s = 0.f;
#pragma unroll
            for (int i4 = 0; i4 < 8; i4++) {
                float4 v = *reinterpret_cast<const float4*>(&X[row * 132 + q * 32 + i4 * 4]);
                vals[i4*4+0] = v.x; vals[i4*4+1] = v.y;
                vals[i4*4+2] = v.z; vals[i4*4+3] = v.w;
                s += v.x + v.y + v.z + v.w;
            }
            s += __shfl_xor_sync(~0u, s, 1);
            s += __shfl_xor_sync(~0u, s, 2);
            float mean = s * (1.f / 128.f);
            float sq = 0.f;
#pragma unroll
            for (int i = 0; i < 32; i++) {
                float d = vals[i] - mean;
                sq += d * d;
            }
            sq += __shfl_xor_sync(~0u, sq, 1);
            sq += __shfl_xor_sync(~0u, sq, 2);
            float kq = rsqrtf(sq * (1.f / 128.f) + 1e-5f);
            size_t r = rowBase + row;
#pragma unroll
            for (int i4 = 0; i4 < 8; i4++) {
                int c0 = q * 32 + i4 * 4;
                float4 g4 = *reinterpret_cast<const float4*>(&g2[c0]);
                float4 b4 = *reinterpret_cast<const float4*>(&bb2[c0]);
                float4 o;
                o.x = (vals[i4*4+0] - mean) * kq * g4.x + b4.x;
                o.y = (vals[i4*4+1] - mean) * kq * g4.y + b4.y;
                o.z = (vals[i4*4+2] - mean) * kq * g4.z + b4.z;
                o.w = (vals[i4*4+3] - mean) * kq * g4.w + b4.w;
                *reinterpret_cast<float4*>(&out1[r * 128 + c0]) = o;
            }
        }
    }
}

// ---------------------------------------------------------------------------
// proj GEMM with fused count-normalization (small, scalar)
// ---------------------------------------------------------------------------
__global__ void __launch_bounds__(256) gemm_proj_k(
    const float* __restrict__ agg, const float* __restrict__ counts,
    const float* __restrict__ W, const float* __restrict__ bias,
    float* __restrict__ C)
{
    __shared__ float As[16][68];
    __shared__ float Bs[16][64];
    __shared__ float rcnt[64];

    const int tid = threadIdx.x;
    const int tx = tid & 15;
    const int ty = tid >> 4;
    const size_t rowBase = (size_t)blockIdx.y * 64;
    const int colBase = blockIdx.x * 64;

    if (tid < 64) rcnt[tid] = 1.f / fmaxf(counts[tid], 1.f);
    __syncthreads();

    float acc[4][4];
#pragma unroll
    for (int i = 0; i < 4; i++)
#pragma unroll
        for (int j = 0; j < 4; j++) acc[i][j] = 0.f;

    for (int k0 = 0; k0 < 32; k0 += 16) {
#pragma unroll
        for (int i = 0; i < 4; i++) {
            int e = tid + 256 * i;
            int r = e >> 4, c = e & 15;
            As[c][r] = agg[(rowBase + r) * 32 + k0 + c] * rcnt[r];
        }
#pragma unroll
        for (int i = 0; i < 4; i++) {
            int e = tid + 256 * i;
            int r = e >> 6, c = e & 63;
            Bs[r][c] = W[(size_t)(k0 + r) * CD + colBase + c];
        }
        __syncthreads();
#pragma unroll
        for (int k = 0; k < 16; k++) {
            float a[4], b[4];
#pragma unroll
            for (int i = 0; i < 4; i++) a[i] = As[k][ty + 16 * i];
#pragma unroll
            for (int j = 0; j < 4; j++) b[j] = Bs[k][tx + 16 * j];
#pragma unroll
            for (int i = 0; i < 4; i++)
#pragma unroll
                for (int j = 0; j < 4; j++)
                    acc[i][j] = fmaf(a[i], b[j], acc[i][j]);
        }
        __syncthreads();
    }

#pragma unroll
    for (int i = 0; i < 4; i++) {
        size_t r = rowBase + ty + 16 * i;
#pragma unroll
        for (int j = 0; j < 4; j++) {
            int c = colBase + tx + 16 * j;
            C[r * CD + c] = acc[i][j] + bias[c];
        }
    }
}

// ---------------------------------------------------------------------------
// LN1: one warp per row, float4 lanes
// ---------------------------------------------------------------------------
__global__ void ln_k(const float* __restrict__ in, const float* __restrict__ g,
                     const float* __restrict__ bb, float* __restrict__ out)
{
    const int w = threadIdx.x >> 5;
    const int lane = threadIdx.x & 31;
    const size_t row = (size_t)blockIdx.x * 8 + w;
    float4 v = *reinterpret_cast<const float4*>(&in[row * 128 + lane * 4]);
    float s = v.x + v.y + v.z + v.w;
#pragma unroll
    for (int o = 16; o > 0; o >>= 1) s += __shfl_xor_sync(~0u, s, o);
    float mean = s * (1.f / 128.f);
    float dx = v.x - mean, dy = v.y - mean, dz = v.z - mean, dw = v.w - mean;
    float q = dx * dx + dy * dy + dz * dz + dw * dw;
#pragma unroll
    for (int o = 16; o > 0; o >>= 1) q += __shfl_xor_sync(~0u, q, o);
    float kq = rsqrtf(q * (1.f / 128.f) + 1e-5f);
    float4 g4 = *reinterpret_cast<const float4*>(&g[lane * 4]);
    float4 b4 = *reinterpret_cast<const float4*>(&bb[lane * 4]);
    float4 o;
    o.x = dx * kq * g4.x + b4.x;
    o.y = dy * kq * g4.y + b4.y;
    o.z = dz * kq * g4.z + b4.z;
    o.w = dw * kq * g4.w + b4.w;
    *reinterpret_cast<float4*>(&out[row * 128 + lane * 4]) = o;
}

__global__ void counts_k(const int* __restrict__ tgt, float* __restrict__ counts)
{
    int e = threadIdx.x;
    if (e < CE) atomicAdd(&counts[tgt[e]], 1.f);
}

// ---------------------------------------------------------------------------
extern "C" void kernel_launch(void* const* d_in, const int* in_sizes, int n_in,
                              void* d_out, int out_size)
{
    const float* nf        = (const float*)d_in[0];
    const float* edge_attr = (const float*)d_in[1];
    const int*   src       = (const int*)  d_in[2];
    const int*   tgt       = (const int*)  d_in[3];
    const float* mask      = (const float*)d_in[4];
    const float* e_w1   = (const float*)d_in[6];
    const float* e_b1   = (const float*)d_in[7];
    const float* e_w2   = (const float*)d_in[8];
    const float* e_b2   = (const float*)d_in[9];
    const float* proj_w = (const float*)d_in[10];
    const float* proj_b = (const float*)d_in[11];
    const float* r_w    = (const float*)d_in[12];
    const float* r_b    = (const float*)d_in[13];
    const float* u_w    = (const float*)d_in[14];
    const float* u_b    = (const float*)d_in[15];
    const float* c_w    = (const float*)d_in[16];
    const float* c_b    = (const float*)d_in[17];
    const float* n1_g   = (const float*)d_in[18];
    const float* n1_b   = (const float*)d_in[19];
    const float* n2_g   = (const float*)d_in[20];
    const float* n2_b   = (const float*)d_in[21];
    const float* f_w1   = (const float*)d_in[22];
    const float* f_b1   = (const float*)d_in[23];
    const float* f_w2   = (const float*)d_in[24];
    const float* f_b2   = (const float*)d_in[25];

    float* out_x    = (float*)d_out;
    float* out_msgs = out_x + SZ_NORMED;

    float *p_normed, *p_agg, *p_counts, *p_proj, *p_r, *p_u, *p_x, *p_n2;
    cudaGetSymbolAddress((void**)&p_normed, g_normed);
    cudaGetSymbolAddress((void**)&p_agg,    g_agg);
    cudaGetSymbolAddress((void**)&p_counts, g_counts);
    cudaGetSymbolAddress((void**)&p_proj,   g_proj);
    cudaGetSymbolAddress((void**)&p_r,      g_r);
    cudaGetSymbolAddress((void**)&p_u,      g_u);
    cudaGetSymbolAddress((void**)&p_x,      g_x);
    cudaGetSymbolAddress((void**)&p_n2,     g_n2);

    cudaFuncSetAttribute(ffn_tc_k,  cudaFuncAttributeMaxDynamicSharedMemorySize, (int)FFN_SMEM);
    cudaFuncSetAttribute(edge_tc_k, cudaFuncAttributeMaxDynamicSharedMemorySize, (int)EDGE_SMEM);
    cudaFuncSetAttribute(gru_tc_k<true>,  cudaFuncAttributeMaxDynamicSharedMemorySize, (int)GRU_SMEM);
    cudaFuncSetAttribute(gru_tc_k<false>, cudaFuncAttributeMaxDynamicSharedMemorySize, (int)GRU_SMEM);

    cudaMemsetAsync(p_agg, 0, SZ_AGG * sizeof(float));
    cudaMemsetAsync(p_counts, 0, CN * sizeof(float));

    // 1. LN1
    ln_k<<<(unsigned)(MN / 8), 256>>>(nf, n1_g, n1_b, p_normed);

    // 2. counts
    counts_k<<<1, 128>>>(tgt, p_counts);

    // 3. edge pipeline (gather + MLP + mask + scatter)
    edge_tc_k<<<(unsigned)(ME / 128), 512, EDGE_SMEM>>>(
        p_normed, edge_attr, src, tgt, e_w1, e_b1, e_w2, e_b2, mask,
        out_msgs, p_agg);

    // 4. proj = (agg/cnt) @ proj_w + proj_b
    gemm_proj_k<<<dim3(2, (unsigned)(MN / 64)), 256>>>(
        p_agg, p_counts, proj_w, proj_b, p_proj);

    // 5. r,u = sigmoid([normed|proj] @ {r_w,u_w} + b)
    gru_tc_k<true><<<(unsigned)(MN / 128), 512, GRU_SMEM>>>(
        p_normed, nullptr, p_proj, r_w, r_b, u_w, u_b, p_r, p_u,
        nullptr, nullptr, nullptr, nullptr);

    // 6. cand GEMM + GRU combine + LN2 (fused): writes x and n2
    gru_tc_k<false><<<(unsigned)(MN / 128), 512, GRU_SMEM>>>(
        p_normed, p_r, p_proj, c_w, c_b, nullptr, nullptr, p_x, p_n2,
        p_u, nf, n2_g, n2_b);

    // 7. fused FFN
    ffn_tc_k<<<(unsigned)(MN / 128), 512, FFN_SMEM>>>(
        p_n2, f_w1, f_b1, f_w2, f_b2, p_x, out_x);
}

// round 11
// speedup vs baseline: 3.7100x; 1.7267x over previous
#include <cuda_runtime.h>
#include <cuda_fp16.h>
#include <math.h>
#include <stdint.h>

constexpr int CB  = 2048;
constexpr int CN  = 64;
constexpr int CE  = 126;
constexpr int CD  = 128;
constexpr int CED = 32;
constexpr int CF  = 2048;
constexpr int CK1 = 2*CD + CED;  // 288

constexpr size_t MN = (size_t)CB * CN;      // 131072
constexpr size_t ME = (size_t)CB * CE;      // 258048

constexpr size_t SZ_NORMED = MN * CD;
constexpr size_t SZ_AGG    = MN * CED;
constexpr size_t SZ_RUC    = MN * CD;

__device__ float g_normed[SZ_NORMED];
__device__ float g_agg   [SZ_AGG];
__device__ float g_counts[CN];
__device__ float g_proj  [SZ_RUC];
__device__ float g_r     [SZ_RUC];
__device__ float g_u     [SZ_RUC];
__device__ float g_x     [SZ_RUC];
__device__ float g_n2    [SZ_RUC];

// ---------------------------------------------------------------------------
// fp16 m16n8k16 mma helpers. A in SMEM [row][k] (half), B in SMEM [n][k].
// Fragment pairs are contiguous -> plain 32-bit LDS, no permutation.
// Word strides (half_stride/2) chosen conflict-free: 68, 132, 52 mod 32
// give distinct banks across the 8 lane-groups.
// ---------------------------------------------------------------------------
__device__ __forceinline__ void mma_f16(float* d, const uint32_t (&a)[4],
                                        const uint32_t (&b)[2])
{
    asm volatile(
        "mma.sync.aligned.m16n8k16.row.col.f32.f16.f16.f32 "
        "{%0,%1,%2,%3},{%4,%5,%6,%7},{%8,%9},{%0,%1,%2,%3};"
        : "+f"(d[0]), "+f"(d[1]), "+f"(d[2]), "+f"(d[3])
        : "r"(a[0]), "r"(a[1]), "r"(a[2]), "r"(a[3]), "r"(b[0]), "r"(b[1]));
}

// A fragment m16 x k16 at (m0, kb): 4 x LDS.32
__device__ __forceinline__ void lda_h(uint32_t (&a)[4], const __half* A, int S,
                                      int m0, int kb, int lane)
{
    int r = m0 + (lane >> 2);
    int c = kb + (lane & 3) * 2;
    a[0] = *reinterpret_cast<const uint32_t*>(&A[r * S + c]);
    a[1] = *reinterpret_cast<const uint32_t*>(&A[(r + 8) * S + c]);
    a[2] = *reinterpret_cast<const uint32_t*>(&A[r * S + c + 8]);
    a[3] = *reinterpret_cast<const uint32_t*>(&A[(r + 8) * S + c + 8]);
}

// B fragment k16 x n8 at (nb, kb), W stored [n][k]: 2 x LDS.32
__device__ __forceinline__ void ldb_h(uint32_t (&b)[2], const __half* W, int S,
                                      int nb, int kb, int lane)
{
    int n = nb + (lane >> 2);
    int c = kb + (lane & 3) * 2;
    b[0] = *reinterpret_cast<const uint32_t*>(&W[n * S + c]);
    b[1] = *reinterpret_cast<const uint32_t*>(&W[n * S + c + 8]);
}

// one k16 x n16 tile for one m16 A frag: 2 ldb + 2 mma
__device__ __forceinline__ void mma_k16_n16(float* d0, float* d1,
    const uint32_t (&a)[4], const __half* W, int S, int nb, int kb, int lane)
{
    uint32_t b[2];
    ldb_h(b, W, S, nb, kb, lane);     mma_f16(d0, a, b);
    ldb_h(b, W, S, nb + 8, kb, lane); mma_f16(d1, a, b);
}

// one k16 x n16 tile for TWO m16 A frags (B loaded once): 2 ldb + 4 mma
__device__ __forceinline__ void mma_k16_n16_m32(float* d00, float* d01,
    float* d10, float* d11,
    const uint32_t (&a0)[4], const uint32_t (&a1)[4],
    const __half* W, int S, int nb, int kb, int lane)
{
    uint32_t b[2];
    ldb_h(b, W, S, nb, kb, lane);     mma_f16(d00, a0, b); mma_f16(d10, a1, b);
    ldb_h(b, W, S, nb + 8, kb, lane); mma_f16(d01, a0, b); mma_f16(d11, a1, b);
}

__device__ __forceinline__ float gelu_f(float v) {
    return 0.5f * v * (1.f + erff(v * 0.70710678118654752f));
}

// ---------------------------------------------------------------------------
// fp16 fused FFN: out = xres + gelu(n2 @ W1 + b1) @ W2 + b2
// 128 rows/block, 512 thr, 16 chunks of 128 FFN cols, warps m32n32.
// SMEM: Af,Hf,Wf each 128x136 half = 104,448 B total -> 2 blocks/SM.
// ---------------------------------------------------------------------------
constexpr int F_S = 136;                                    // halfs; 68 words
constexpr size_t FFN_SMEM = (size_t)3 * 128 * F_S * 2;      // 104,448 B

__global__ void __launch_bounds__(512) ffn_tc_k(
    const float* __restrict__ n2, const float* __restrict__ w1,
    const float* __restrict__ b1, const float* __restrict__ w2,
    const float* __restrict__ b2, const float* __restrict__ xres,
    float* __restrict__ out)
{
    extern __shared__ __half sh[];
    __half* Af = sh;                 // [128][136]
    __half* Hf = Af + 128 * F_S;     // [128][136]
    __half* Wf = Hf + 128 * F_S;     // [128][136]

    const int tid  = threadIdx.x;
    const int lane = tid & 31;
    const int wrp  = tid >> 5;
    const int m0   = (wrp & 3) * 32;
    const int n0   = (wrp >> 2) * 32;
    const size_t rowBase = (size_t)blockIdx.x * 128;

    // A fill: 8192 half2 pairs
#pragma unroll
    for (int i = 0; i < 16; i++) {
        int p = tid + 512 * i;
        int r = p >> 6, c = (p & 63) * 2;
        float2 f = *reinterpret_cast<const float2*>(&n2[(rowBase + r) * 128 + c]);
        *reinterpret_cast<__half2*>(&Af[r * F_S + c]) = __floats2half2_rn(f.x, f.y);
    }

    float acc2[32];
#pragma unroll
    for (int i = 0; i < 32; i++) acc2[i] = 0.f;

    __syncthreads();

    for (int ch = 0; ch < 16; ch++) {
        // W1 chunk [k=128][n=128] -> Wf[n][k]
#pragma unroll
        for (int i = 0; i < 16; i++) {
            int p = tid + 512 * i;
            int n = p & 127, k = (p >> 7) * 2;
            float f0 = w1[(size_t)k * 2048 + ch * 128 + n];
            float f1 = w1[(size_t)(k + 1) * 2048 + ch * 128 + n];
            *reinterpret_cast<__half2*>(&Wf[n * F_S + k]) = __floats2half2_rn(f0, f1);
        }
        __syncthreads();

        // stage 1: acc1(m32 x n32) = A @ W1chunk
        float acc1[32];
#pragma unroll
        for (int i = 0; i < 32; i++) acc1[i] = 0.f;

#pragma unroll
        for (int ks = 0; ks < 8; ks++) {
            int kb = ks * 16;
            uint32_t a0[4], a1[4];
            lda_h(a0, Af, F_S, m0,      kb, lane);
            lda_h(a1, Af, F_S, m0 + 16, kb, lane);
#pragma unroll
            for (int nt = 0; nt < 2; nt++) {
                mma_k16_n16_m32(&acc1[(nt*2+0)*4], &acc1[(nt*2+1)*4],
                                &acc1[(4+nt*2+0)*4], &acc1[(4+nt*2+1)*4],
                                a0, a1, Wf, F_S, n0 + nt * 16, kb, lane);
            }
        }

        // h = gelu(acc1 + b1) -> Hf
        {
            int r0 = lane >> 2;
#pragma unroll
            for (int mh = 0; mh < 2; mh++)
#pragma unroll
            for (int j = 0; j < 4; j++) {
                int col = n0 + j * 8 + 2 * (lane & 3);
                float bb0 = b1[ch * 128 + col];
                float bb1 = b1[ch * 128 + col + 1];
#pragma unroll
                for (int half = 0; half < 2; half++) {
                    int r = m0 + mh * 16 + r0 + half * 8;
                    float v0 = gelu_f(acc1[(mh*4+j)*4 + half*2 + 0] + bb0);
                    float v1 = gelu_f(acc1[(mh*4+j)*4 + half*2 + 1] + bb1);
                    *reinterpret_cast<__half2*>(&Hf[r * F_S + col]) =
                        __floats2half2_rn(v0, v1);
                }
            }
        }
        __syncthreads();

        // W2 chunk [k=128][n=128] -> Wf[n][k]
#pragma unroll
        for (int i = 0; i < 16; i++) {
            int p = tid + 512 * i;
            int n = p & 127, k = (p >> 7) * 2;
            float f0 = w2[(size_t)(ch * 128 + k) * 128 + n];
            float f1 = w2[(size_t)(ch * 128 + k + 1) * 128 + n];
            *reinterpret_cast<__half2*>(&Wf[n * F_S + k]) = __floats2half2_rn(f0, f1);
        }
        __syncthreads();

        // stage 2: acc2(m32 x n32) += H @ W2chunk
#pragma unroll
        for (int ks = 0; ks < 8; ks++) {
            int kb = ks * 16;
            uint32_t a0[4], a1[4];
            lda_h(a0, Hf, F_S, m0,      kb, lane);
            lda_h(a1, Hf, F_S, m0 + 16, kb, lane);
#pragma unroll
            for (int nt = 0; nt < 2; nt++) {
                mma_k16_n16_m32(&acc2[(nt*2+0)*4], &acc2[(nt*2+1)*4],
                                &acc2[(4+nt*2+0)*4], &acc2[(4+nt*2+1)*4],
                                a0, a1, Wf, F_S, n0 + nt * 16, kb, lane);
            }
        }
        __syncthreads();
    }

    // epilogue: out = acc2 + b2 + xres
    {
        int r0 = lane >> 2;
#pragma unroll
        for (int mh = 0; mh < 2; mh++)
#pragma unroll
        for (int j = 0; j < 4; j++) {
            int col = n0 + j * 8 + 2 * (lane & 3);
            float bb0 = b2[col], bb1 = b2[col + 1];
#pragma unroll
            for (int half = 0; half < 2; half++) {
                size_t r = rowBase + m0 + mh * 16 + r0 + half * 8;
                float2 xr = *reinterpret_cast<const float2*>(&xres[r * 128 + col]);
                float2 o;
                o.x = acc2[(mh*4+j)*4 + half*2 + 0] + bb0 + xr.x;
                o.y = acc2[(mh*4+j)*4 + half*2 + 1] + bb1 + xr.y;
                *reinterpret_cast<float2*>(&out[r * 128 + col]) = o;
            }
        }
    }
}

// ---------------------------------------------------------------------------
// fp16 fused edge pipeline, 128 rows/block, 512 thr.
// phase1: Af/Wf [128][104] half; phase2 (aliased): Hf [128][136] + W2f [32][136]
// ---------------------------------------------------------------------------
constexpr int E_AS = 104;   // halfs; 52 words -> conflict-free
constexpr int E_HS = 136;
constexpr size_t EDGE_SMEM = (size_t)(2 * 128 * E_AS) * 2;   // 53,248 B

__global__ void __launch_bounds__(512) edge_tc_k(
    const float* __restrict__ normed, const float* __restrict__ edge_attr,
    const int* __restrict__ srcI, const int* __restrict__ tgtI,
    const float* __restrict__ e_w1, const float* __restrict__ e_b1,
    const float* __restrict__ e_w2, const float* __restrict__ e_b2,
    const float* __restrict__ mask,
    float* __restrict__ msgs_out, float* __restrict__ agg)
{
    extern __shared__ __half she[];
    __half* Af = she;
    __half* Wf = Af + 128 * E_AS;
    __half* Hf  = she;                  // aliased phase 2
    __half* W2f = Hf + 128 * E_HS;

    __shared__ int   srcb[128], tgtb[128], tgtn[128];
    __shared__ float mks[128];

    const int tid  = threadIdx.x;
    const int lane = tid & 31;
    const int wrp  = tid >> 5;
    const int wm   = wrp & 7;
    const int wn   = wrp >> 3;
    const int m0   = wm * 16;
    const size_t rowBase = (size_t)blockIdx.x * 128;

    if (tid < 128) {
        size_t row = rowBase + tid;
        int b = (int)(row / CE);
        int e = (int)(row - (size_t)b * CE);
        srcb[tid] = (b * CN + srcI[e]) * CD;
        tgtb[tid] = (b * CN + tgtI[e]) * CD;
        tgtn[tid] = b * CN + tgtI[e];
        mks[tid]  = mask[row];
    }
    __syncthreads();

    float acc1[32];
#pragma unroll
    for (int i = 0; i < 32; i++) acc1[i] = 0.f;

    for (int ch = 0; ch < 3; ch++) {
        const int k0 = ch * 96;
        // A gathered: 128 rows x 48 pairs
#pragma unroll
        for (int i = 0; i < 12; i++) {
            int p = tid + 512 * i;
            int r = p / 48, cp = p % 48;
            int c = 2 * cp;
            int gk = k0 + c;
            float f0, f1;
            if (gk < 128) {
                float2 f = *reinterpret_cast<const float2*>(&normed[srcb[r] + gk]);
                f0 = f.x; f1 = f.y;
            } else if (gk < 256) {
                float2 f = *reinterpret_cast<const float2*>(&normed[tgtb[r] + gk - 128]);
                f0 = f.x; f1 = f.y;
            } else {
                float2 f = *reinterpret_cast<const float2*>(
                    &edge_attr[(rowBase + r) * CED + gk - 256]);
                f0 = f.x; f1 = f.y;
            }
            *reinterpret_cast<__half2*>(&Af[r * E_AS + c]) = __floats2half2_rn(f0, f1);
        }
        // W1 chunk: 128 n x 48 k-pairs
#pragma unroll
        for (int i = 0; i < 12; i++) {
            int p = tid + 512 * i;
            int n = p & 127, k = (p >> 7) * 2;
            float f0 = e_w1[(size_t)(k0 + k) * CD + n];
            float f1 = e_w1[(size_t)(k0 + k + 1) * CD + n];
            *reinterpret_cast<__half2*>(&Wf[n * E_AS + k]) = __floats2half2_rn(f0, f1);
        }
        __syncthreads();
#pragma unroll
        for (int ks = 0; ks < 6; ks++) {
            int kb = ks * 16;
            uint32_t a[4];
            lda_h(a, Af, E_AS, m0, kb, lane);
#pragma unroll
            for (int g = 0; g < 4; g++) {
                mma_k16_n16(&acc1[(g*2+0)*4], &acc1[(g*2+1)*4],
                            a, Wf, E_AS, wn * 64 + g * 16, kb, lane);
            }
        }
        __syncthreads();
    }

    // h = relu(acc1 + b1) -> Hf (aliased; all phase-1 reads done)
    {
        int r0 = m0 + (lane >> 2);
#pragma unroll
        for (int t = 0; t < 8; t++) {
            int col = wn * 64 + t * 8 + 2 * (lane & 3);
            float bb0 = e_b1[col], bb1 = e_b1[col + 1];
#pragma unroll
            for (int half = 0; half < 2; half++) {
                int r = r0 + half * 8;
                float v0 = fmaxf(acc1[t * 4 + half * 2 + 0] + bb0, 0.f);
                float v1 = fmaxf(acc1[t * 4 + half * 2 + 1] + bb1, 0.f);
                *reinterpret_cast<__half2*>(&Hf[r * E_HS + col]) =
                    __floats2half2_rn(v0, v1);
            }
        }
    }
    // W2 [k=128][n=32] -> W2f[n][k]: 2048 pairs
#pragma unroll
    for (int i = 0; i < 4; i++) {
        int p = tid + 512 * i;
        int n = p & 31, k = (p >> 5) * 2;
        float f0 = e_w2[(size_t)k * CED + n];
        float f1 = e_w2[(size_t)(k + 1) * CED + n];
        *reinterpret_cast<__half2*>(&W2f[n * E_HS + k]) = __floats2half2_rn(f0, f1);
    }
    __syncthreads();

    float acc2[8];
#pragma unroll
    for (int i = 0; i < 8; i++) acc2[i] = 0.f;
#pragma unroll
    for (int ks = 0; ks < 8; ks++) {
        int kb = ks * 16;
        uint32_t a[4];
        lda_h(a, Hf, E_HS, m0, kb, lane);
        mma_k16_n16(&acc2[0], &acc2[4], a, W2f, E_HS, wn * 16, kb, lane);
    }

    {
        int r0 = m0 + (lane >> 2);
#pragma unroll
        for (int t = 0; t < 2; t++) {
            int col = wn * 16 + t * 8 + 2 * (lane & 3);
            float bb0 = e_b2[col], bb1 = e_b2[col + 1];
#pragma unroll
            for (int half = 0; half < 2; half++) {
                int r = r0 + half * 8;
                float mk = mks[r];
                float v0 = (acc2[t * 4 + half * 2 + 0] + bb0) * mk;
                float v1 = (acc2[t * 4 + half * 2 + 1] + bb1) * mk;
                size_t be = rowBase + r;
                msgs_out[be * 32 + col]     = v0;
                msgs_out[be * 32 + col + 1] = v1;
                float* ap = &agg[(size_t)tgtn[r] * CED + col];
                atomicAdd(ap, v0);
                atomicAdd(ap + 1, v1);
            }
        }
    }
}

// ---------------------------------------------------------------------------
// fp16 GRU GEMMs. RU=true: r,u (sigmoid). RU=false: cand + fused GRU-combine
// + LN2 epilogue (writes x and n2; cand never hits HBM).
// SMEM: Af [128][264] half + Wf [128][136] half = 102,400 B
// ---------------------------------------------------------------------------
constexpr int G_AS = 264;   // halfs; 132 words
constexpr int G_WS = 136;
constexpr size_t GRU_SMEM = (size_t)(128 * G_AS + 128 * G_WS) * 2;  // 102,400 B

template<bool RU>
__global__ void __launch_bounds__(512) gru_tc_k(
    const float* __restrict__ a1, const float* __restrict__ a2,
    const float* __restrict__ a3,
    const float* __restrict__ w0p, const float* __restrict__ b0p,
    const float* __restrict__ w1p, const float* __restrict__ b1p,
    float* __restrict__ out0, float* __restrict__ out1,
    const float* __restrict__ uu, const float* __restrict__ nfp,
    const float* __restrict__ g2, const float* __restrict__ bb2)
{
    extern __shared__ __half shg[];
    __half* Af = shg;                 // [128][264]
    __half* Wf = Af + 128 * G_AS;     // [128][136]

    const int tid  = threadIdx.x;
    const int lane = tid & 31;
    const int wrp  = tid >> 5;
    const int wm   = wrp & 7;
    const int wn   = wrp >> 3;
    const int m0   = wm * 16;
    const size_t rowBase = (size_t)blockIdx.x * 128;

    // A fill: 128 x 128 pairs (256 cols)
#pragma unroll
    for (int i = 0; i < 32; i++) {
        int p = tid + 512 * i;
        int r = p >> 7, cp = p & 127;
        int k = 2 * cp;
        size_t base = (rowBase + r) * 128;
        float f0, f1;
        if (k < 128) {
            float2 f = *reinterpret_cast<const float2*>(&a1[base + k]);
            f0 = f.x; f1 = f.y;
            if (!RU) {
                float2 g = *reinterpret_cast<const float2*>(&a2[base + k]);
                f0 *= g.x; f1 *= g.y;
            }
        } else {
            float2 f = *reinterpret_cast<const float2*>(&a3[base + k - 128]);
            f0 = f.x; f1 = f.y;
        }
        *reinterpret_cast<__half2*>(&Af[r * G_AS + k]) = __floats2half2_rn(f0, f1);
    }
    __syncthreads();

    constexpr int NW = RU ? 2 : 1;
    float acc[NW][32];
#pragma unroll
    for (int s = 0; s < NW; s++)
#pragma unroll
        for (int i = 0; i < 32; i++) acc[s][i] = 0.f;

    for (int ws = 0; ws < NW; ws++) {
        const float* w = (ws == 0) ? w0p : w1p;
        for (int kc = 0; kc < 2; kc++) {
#pragma unroll
            for (int i = 0; i < 16; i++) {
                int p = tid + 512 * i;
                int n = p & 127, k = (p >> 7) * 2;
                float f0 = w[(size_t)(kc * 128 + k) * CD + n];
                float f1 = w[(size_t)(kc * 128 + k + 1) * CD + n];
                *reinterpret_cast<__half2*>(&Wf[n * G_WS + k]) =
                    __floats2half2_rn(f0, f1);
            }
            __syncthreads();
#pragma unroll
            for (int ks = 0; ks < 8; ks++) {
                int kb = ks * 16;
                uint32_t a[4];
                lda_h(a, Af, G_AS, m0, kc * 128 + kb, lane);
#pragma unroll
                for (int g = 0; g < 4; g++) {
                    mma_k16_n16(&acc[ws][(g*2+0)*4], &acc[ws][(g*2+1)*4],
                                a, Wf, G_WS, wn * 64 + g * 16, kb, lane);
                }
            }
            __syncthreads();
        }
    }

    if (RU) {
        int r0 = m0 + (lane >> 2);
#pragma unroll
        for (int s = 0; s < NW; s++) {
            const float* bias = (s == 0) ? b0p : b1p;
            float* outp = (s == 0) ? out0 : out1;
#pragma unroll
            for (int t = 0; t < 8; t++) {
                int col = wn * 64 + t * 8 + 2 * (lane & 3);
                float bb0 = bias[col], bb1 = bias[col + 1];
#pragma unroll
                for (int half = 0; half < 2; half++) {
                    size_t r = rowBase + r0 + half * 8;
                    float v0 = 1.f / (1.f + expf(-(acc[s][t*4+half*2+0] + bb0)));
                    float v1 = 1.f / (1.f + expf(-(acc[s][t*4+half*2+1] + bb1)));
                    float2 o; o.x = v0; o.y = v1;
                    *reinterpret_cast<float2*>(&outp[r * 128 + col]) = o;
                }
            }
        }
    } else {
        // cand = tanh(acc + b); x = nf + (1-u)*normed + u*cand; write x, smem X
        float* X = reinterpret_cast<float*>(shg);   // [128][132] floats = 67,584 B
        int r0 = m0 + (lane >> 2);
#pragma unroll
        for (int t = 0; t < 8; t++) {
            int col = wn * 64 + t * 8 + 2 * (lane & 3);
            float bb0 = b0p[col], bb1 = b0p[col + 1];
#pragma unroll
            for (int half = 0; half < 2; half++) {
                int rl = r0 + half * 8;
                size_t gi = (rowBase + rl) * 128 + col;
                float c0 = tanhf(acc[0][t*4+half*2+0] + bb0);
                float c1 = tanhf(acc[0][t*4+half*2+1] + bb1);
                float2 uv  = *reinterpret_cast<const float2*>(&uu[gi]);
                float2 nv  = *reinterpret_cast<const float2*>(&a1[gi]);
                float2 nfv = *reinterpret_cast<const float2*>(&nfp[gi]);
                float x0 = nfv.x + (1.f - uv.x) * nv.x + uv.x * c0;
                float x1 = nfv.y + (1.f - uv.y) * nv.y + uv.y * c1;
                float2 xo; xo.x = x0; xo.y = x1;
                *reinterpret_cast<float2*>(&out0[gi]) = xo;
                *reinterpret_cast<float2*>(&X[rl * 132 + col]) = xo;
            }
        }
        __syncthreads();
        // LN2: 4 threads per row
        {
            int row = tid >> 2, q = tid & 3;
            float vals[32];
            float s = 0.f;
#pragma unroll
            for (int i4 = 0; i4 < 8; i4++) {
                float4 v = *reinterpret_cast<const float4*>(&X[row * 132 + q * 32 + i4 * 4]);
                vals[i4*4+0] = v.x; vals[i4*4+1] = v.y;
                vals[i4*4+2] = v.z; vals[i4*4+3] = v.w;
                s += v.x + v.y + v.z + v.w;
            }
            s += __shfl_xor_sync(~0u, s, 1);
            s += __shfl_xor_sync(~0u, s, 2);
            float mean = s * (1.f / 128.f);
            float sq = 0.f;
#pragma unroll
            for (int i = 0; i < 32; i++) {
                float d = vals[i] - mean;
                sq += d * d;
            }
            sq += __shfl_xor_sync(~0u, sq, 1);
            sq += __shfl_xor_sync(~0u, sq, 2);
            float kq = rsqrtf(sq * (1.f / 128.f) + 1e-5f);
            size_t r = rowBase + row;
#pragma unroll
            for (int i4 = 0; i4 < 8; i4++) {
                int c0 = q * 32 + i4 * 4;
                float4 g4 = *reinterpret_cast<const float4*>(&g2[c0]);
                float4 b4 = *reinterpret_cast<const float4*>(&bb2[c0]);
                float4 o;
                o.x = (vals[i4*4+0] - mean) * kq * g4.x + b4.x;
                o.y = (vals[i4*4+1] - mean) * kq * g4.y + b4.y;
                o.z = (vals[i4*4+2] - mean) * kq * g4.z + b4.z;
                o.w = (vals[i4*4+3] - mean) * kq * g4.w + b4.w;
                *reinterpret_cast<float4*>(&out1[r * 128 + c0]) = o;
            }
        }
    }
}

// ---------------------------------------------------------------------------
// proj GEMM with fused count-normalization (small, scalar)
// ---------------------------------------------------------------------------
__global__ void __launch_bounds__(256) gemm_proj_k(
    const float* __restrict__ agg, const float* __restrict__ counts,
    const float* __restrict__ W, const float* __restrict__ bias,
    float* __restrict__ C)
{
    __shared__ float As[16][68];
    __shared__ float Bs[16][64];
    __shared__ float rcnt[64];

    const int tid = threadIdx.x;
    const int tx = tid & 15;
    const int ty = tid >> 4;
    const size_t rowBase = (size_t)blockIdx.y * 64;
    const int colBase = blockIdx.x * 64;

    if (tid < 64) rcnt[tid] = 1.f / fmaxf(counts[tid], 1.f);
    __syncthreads();

    float acc[4][4];
#pragma unroll
    for (int i = 0; i < 4; i++)
#pragma unroll
        for (int j = 0; j < 4; j++) acc[i][j] = 0.f;

    for (int k0 = 0; k0 < 32; k0 += 16) {
#pragma unroll
        for (int i = 0; i < 4; i++) {
            int e = tid + 256 * i;
            int r = e >> 4, c = e & 15;
            As[c][r] = agg[(rowBase + r) * 32 + k0 + c] * rcnt[r];
        }
#pragma unroll
        for (int i = 0; i < 4; i++) {
            int e = tid + 256 * i;
            int r = e >> 6, c = e & 63;
            Bs[r][c] = W[(size_t)(k0 + r) * CD + colBase + c];
        }
        __syncthreads();
#pragma unroll
        for (int k = 0; k < 16; k++) {
            float a[4], b[4];
#pragma unroll
            for (int i = 0; i < 4; i++) a[i] = As[k][ty + 16 * i];
#pragma unroll
            for (int j = 0; j < 4; j++) b[j] = Bs[k][tx + 16 * j];
#pragma unroll
            for (int i = 0; i < 4; i++)
#pragma unroll
                for (int j = 0; j < 4; j++)
                    acc[i][j] = fmaf(a[i], b[j], acc[i][j]);
        }
        __syncthreads();
    }

#pragma unroll
    for (int i = 0; i < 4; i++) {
        size_t r = rowBase + ty + 16 * i;
#pragma unroll
        for (int j = 0; j < 4; j++) {
            int c = colBase + tx + 16 * j;
            C[r * CD + c] = acc[i][j] + bias[c];
        }
    }
}

// ---------------------------------------------------------------------------
// LN1 + counts
// ---------------------------------------------------------------------------
__global__ void ln_k(const float* __restrict__ in, const float* __restrict__ g,
                     const float* __restrict__ bb, float* __restrict__ out)
{
    const int w = threadIdx.x >> 5;
    const int lane = threadIdx.x & 31;
    const size_t row = (size_t)blockIdx.x * 8 + w;
    float4 v = *reinterpret_cast<const float4*>(&in[row * 128 + lane * 4]);
    float s = v.x + v.y + v.z + v.w;
#pragma unroll
    for (int o = 16; o > 0; o >>= 1) s += __shfl_xor_sync(~0u, s, o);
    float mean = s * (1.f / 128.f);
    float dx = v.x - mean, dy = v.y - mean, dz = v.z - mean, dw = v.w - mean;
    float q = dx * dx + dy * dy + dz * dz + dw * dw;
#pragma unroll
    for (int o = 16; o > 0; o >>= 1) q += __shfl_xor_sync(~0u, q, o);
    float kq = rsqrtf(q * (1.f / 128.f) + 1e-5f);
    float4 g4 = *reinterpret_cast<const float4*>(&g[lane * 4]);
    float4 b4 = *reinterpret_cast<const float4*>(&bb[lane * 4]);
    float4 o;
    o.x = dx * kq * g4.x + b4.x;
    o.y = dy * kq * g4.y + b4.y;
    o.z = dz * kq * g4.z + b4.z;
    o.w = dw * kq * g4.w + b4.w;
    *reinterpret_cast<float4*>(&out[row * 128 + lane * 4]) = o;
}

__global__ void counts_k(const int* __restrict__ tgt, float* __restrict__ counts)
{
    int e = threadIdx.x;
    if (e < CE) atomicAdd(&counts[tgt[e]], 1.f);
}

// ---------------------------------------------------------------------------
extern "C" void kernel_launch(void* const* d_in, const int* in_sizes, int n_in,
                              void* d_out, int out_size)
{
    const float* nf        = (const float*)d_in[0];
    const float* edge_attr = (const float*)d_in[1];
    const int*   src       = (const int*)  d_in[2];
    const int*   tgt       = (const int*)  d_in[3];
    const float* mask      = (const float*)d_in[4];
    const float* e_w1   = (const float*)d_in[6];
    const float* e_b1   = (const float*)d_in[7];
    const float* e_w2   = (const float*)d_in[8];
    const float* e_b2   = (const float*)d_in[9];
    const float* proj_w = (const float*)d_in[10];
    const float* proj_b = (const float*)d_in[11];
    const float* r_w    = (const float*)d_in[12];
    const float* r_b    = (const float*)d_in[13];
    const float* u_w    = (const float*)d_in[14];
    const float* u_b    = (const float*)d_in[15];
    const float* c_w    = (const float*)d_in[16];
    const float* c_b    = (const float*)d_in[17];
    const float* n1_g   = (const float*)d_in[18];
    const float* n1_b   = (const float*)d_in[19];
    const float* n2_g   = (const float*)d_in[20];
    const float* n2_b   = (const float*)d_in[21];
    const float* f_w1   = (const float*)d_in[22];
    const float* f_b1   = (const float*)d_in[23];
    const float* f_w2   = (const float*)d_in[24];
    const float* f_b2   = (const float*)d_in[25];

    float* out_x    = (float*)d_out;
    float* out_msgs = out_x + SZ_NORMED;

    float *p_normed, *p_agg, *p_counts, *p_proj, *p_r, *p_u, *p_x, *p_n2;
    cudaGetSymbolAddress((void**)&p_normed, g_normed);
    cudaGetSymbolAddress((void**)&p_agg,    g_agg);
    cudaGetSymbolAddress((void**)&p_counts, g_counts);
    cudaGetSymbolAddress((void**)&p_proj,   g_proj);
    cudaGetSymbolAddress((void**)&p_r,      g_r);
    cudaGetSymbolAddress((void**)&p_u,      g_u);
    cudaGetSymbolAddress((void**)&p_x,      g_x);
    cudaGetSymbolAddress((void**)&p_n2,     g_n2);

    cudaFuncSetAttribute(ffn_tc_k,  cudaFuncAttributeMaxDynamicSharedMemorySize, (int)FFN_SMEM);
    cudaFuncSetAttribute(edge_tc_k, cudaFuncAttributeMaxDynamicSharedMemorySize, (int)EDGE_SMEM);
    cudaFuncSetAttribute(gru_tc_k<true>,  cudaFuncAttributeMaxDynamicSharedMemorySize, (int)GRU_SMEM);
    cudaFuncSetAttribute(gru_tc_k<false>, cudaFuncAttributeMaxDynamicSharedMemorySize, (int)GRU_SMEM);

    cudaMemsetAsync(p_agg, 0, SZ_AGG * sizeof(float));
    cudaMemsetAsync(p_counts, 0, CN * sizeof(float));

    // 1. LN1
    ln_k<<<(unsigned)(MN / 8), 256>>>(nf, n1_g, n1_b, p_normed);

    // 2. counts
    counts_k<<<1, 128>>>(tgt, p_counts);

    // 3. edge pipeline (gather + MLP + mask + scatter)
    edge_tc_k<<<(unsigned)(ME / 128), 512, EDGE_SMEM>>>(
        p_normed, edge_attr, src, tgt, e_w1, e_b1, e_w2, e_b2, mask,
        out_msgs, p_agg);

    // 4. proj = (agg/cnt) @ proj_w + proj_b
    gemm_proj_k<<<dim3(2, (unsigned)(MN / 64)), 256>>>(
        p_agg, p_counts, proj_w, proj_b, p_proj);

    // 5. r,u = sigmoid([normed|proj] @ {r_w,u_w} + b)
    gru_tc_k<true><<<(unsigned)(MN / 128), 512, GRU_SMEM>>>(
        p_normed, nullptr, p_proj, r_w, r_b, u_w, u_b, p_r, p_u,
        nullptr, nullptr, nullptr, nullptr);

    // 6. cand GEMM + GRU combine + LN2 (fused): writes x and n2
    gru_tc_k<false><<<(unsigned)(MN / 128), 512, GRU_SMEM>>>(
        p_normed, p_r, p_proj, c_w, c_b, nullptr, nullptr, p_x, p_n2,
        p_u, nf, n2_g, n2_b);

    // 7. fused FFN
    ffn_tc_k<<<(unsigned)(MN / 128), 512, FFN_SMEM>>>(
        p_n2, f_w1, f_b1, f_w2, f_b2, p_x, out_x);
}

// round 12
// speedup vs baseline: 4.6164x; 1.2443x over previous
#include <cuda_runtime.h>
#include <cuda_fp16.h>
#include <math.h>
#include <stdint.h>

constexpr int CB  = 2048;
constexpr int CN  = 64;
constexpr int CE  = 126;
constexpr int CD  = 128;
constexpr int CED = 32;
constexpr int CF  = 2048;
constexpr int CK1 = 2*CD + CED;  // 288

constexpr size_t MN = (size_t)CB * CN;      // 131072
constexpr size_t ME = (size_t)CB * CE;      // 258048

constexpr size_t SZ_NORMED = MN * CD;
constexpr size_t SZ_AGG    = MN * CED;
constexpr size_t SZ_RUC    = MN * CD;

// fp32 scratch (elementwise consumers)
__device__ float g_normed[SZ_NORMED];
__device__ float g_agg   [SZ_AGG];
__device__ float g_counts[CN];
__device__ float g_u     [SZ_RUC];
__device__ float g_x     [SZ_RUC];
// fp16 scratch (GEMM-only consumers)
__device__ __half g_normed_h[SZ_NORMED];
__device__ __half g_proj_h [SZ_RUC];
__device__ __half g_r_h    [SZ_RUC];
__device__ __half g_n2_h   [SZ_RUC];
__device__ __half g_ea_h   [ME * CED];
// fp16 pre-transposed weights [n][k]
__device__ __half g_w1t [2048 * 128];
__device__ __half g_w2t [128 * 2048];
__device__ __half g_ew1t[128 * 288];
__device__ __half g_ew2t[32 * 128];
__device__ __half g_rwt [128 * 256];
__device__ __half g_uwt [128 * 256];
__device__ __half g_cwt [128 * 256];

// ---------------------------------------------------------------------------
// Prep kernels
// ---------------------------------------------------------------------------
__global__ void tr_h(const float* __restrict__ src, __half* __restrict__ dst,
                     int R, int C)
{
    int i = blockIdx.x * 256 + threadIdx.x;
    if (i < R * C) {
        int r = i / C, c = i % C;
        dst[(size_t)c * R + r] = __float2half(src[i]);
    }
}

__global__ void cvt_h8(const float* __restrict__ s, __half* __restrict__ d,
                       size_t n8)
{
    size_t i = (size_t)blockIdx.x * blockDim.x + threadIdx.x;
    if (i >= n8) return;
    size_t b = i * 8;
    float4 v0 = *reinterpret_cast<const float4*>(&s[b]);
    float4 v1 = *reinterpret_cast<const float4*>(&s[b + 4]);
    __half2* dp = reinterpret_cast<__half2*>(&d[b]);
    dp[0] = __floats2half2_rn(v0.x, v0.y);
    dp[1] = __floats2half2_rn(v0.z, v0.w);
    dp[2] = __floats2half2_rn(v1.x, v1.y);
    dp[3] = __floats2half2_rn(v1.z, v1.w);
}

// ---------------------------------------------------------------------------
// fp16 m16n8k16 mma helpers
// ---------------------------------------------------------------------------
__device__ __forceinline__ void mma_f16(float* d, const uint32_t (&a)[4],
                                        const uint32_t (&b)[2])
{
    asm volatile(
        "mma.sync.aligned.m16n8k16.row.col.f32.f16.f16.f32 "
        "{%0,%1,%2,%3},{%4,%5,%6,%7},{%8,%9},{%0,%1,%2,%3};"
        : "+f"(d[0]), "+f"(d[1]), "+f"(d[2]), "+f"(d[3])
        : "r"(a[0]), "r"(a[1]), "r"(a[2]), "r"(a[3]), "r"(b[0]), "r"(b[1]));
}

__device__ __forceinline__ void lda_h(uint32_t (&a)[4], const __half* A, int S,
                                      int m0, int kb, int lane)
{
    int r = m0 + (lane >> 2);
    int c = kb + (lane & 3) * 2;
    a[0] = *reinterpret_cast<const uint32_t*>(&A[r * S + c]);
    a[1] = *reinterpret_cast<const uint32_t*>(&A[(r + 8) * S + c]);
    a[2] = *reinterpret_cast<const uint32_t*>(&A[r * S + c + 8]);
    a[3] = *reinterpret_cast<const uint32_t*>(&A[(r + 8) * S + c + 8]);
}

__device__ __forceinline__ void ldb_h(uint32_t (&b)[2], const __half* W, int S,
                                      int nb, int kb, int lane)
{
    int n = nb + (lane >> 2);
    int c = kb + (lane & 3) * 2;
    b[0] = *reinterpret_cast<const uint32_t*>(&W[n * S + c]);
    b[1] = *reinterpret_cast<const uint32_t*>(&W[n * S + c + 8]);
}

__device__ __forceinline__ void mma_k16_n16(float* d0, float* d1,
    const uint32_t (&a)[4], const __half* W, int S, int nb, int kb, int lane)
{
    uint32_t b[2];
    ldb_h(b, W, S, nb, kb, lane);     mma_f16(d0, a, b);
    ldb_h(b, W, S, nb + 8, kb, lane); mma_f16(d1, a, b);
}

__device__ __forceinline__ void mma_k16_n16_m32(float* d00, float* d01,
    float* d10, float* d11,
    const uint32_t (&a0)[4], const uint32_t (&a1)[4],
    const __half* W, int S, int nb, int kb, int lane)
{
    uint32_t b[2];
    ldb_h(b, W, S, nb, kb, lane);     mma_f16(d00, a0, b); mma_f16(d10, a1, b);
    ldb_h(b, W, S, nb + 8, kb, lane); mma_f16(d01, a0, b); mma_f16(d11, a1, b);
}

__device__ __forceinline__ float gelu_f(float v) {
    return 0.5f * v * (1.f + erff(v * 0.70710678118654752f));
}

// ---------------------------------------------------------------------------
// fp16 fused FFN: out = xres + gelu(n2 @ W1 + b1) @ W2 + b2
// A/W fills are pure uint4 copies from pre-converted fp16.
// ---------------------------------------------------------------------------
constexpr int F_S = 136;
constexpr size_t FFN_SMEM = (size_t)3 * 128 * F_S * 2;      // 104,448 B

__global__ void __launch_bounds__(512) ffn_tc_k(
    const __half* __restrict__ n2h, const __half* __restrict__ w1t,
    const float* __restrict__ b1, const __half* __restrict__ w2t,
    const float* __restrict__ b2, const float* __restrict__ xres,
    float* __restrict__ out)
{
    extern __shared__ __half sh[];
    __half* Af = sh;
    __half* Hf = Af + 128 * F_S;
    __half* Wf = Hf + 128 * F_S;

    const int tid  = threadIdx.x;
    const int lane = tid & 31;
    const int wrp  = tid >> 5;
    const int m0   = (wrp & 3) * 32;
    const int n0   = (wrp >> 2) * 32;
    const size_t rowBase = (size_t)blockIdx.x * 128;

    // A fill: 2048 uint4
#pragma unroll
    for (int i = 0; i < 4; i++) {
        int p = tid + 512 * i;
        int r = p >> 4, c4 = p & 15;
        *reinterpret_cast<uint4*>(&Af[r * F_S + c4 * 8]) =
            *reinterpret_cast<const uint4*>(&n2h[(rowBase + r) * 128 + c4 * 8]);
    }

    float acc2[32];
#pragma unroll
    for (int i = 0; i < 32; i++) acc2[i] = 0.f;

    __syncthreads();

    for (int ch = 0; ch < 16; ch++) {
        // W1 chunk: rows = FFN cols ch*128.., 128 halfs each
#pragma unroll
        for (int i = 0; i < 4; i++) {
            int p = tid + 512 * i;
            int n = p >> 4, c4 = p & 15;
            *reinterpret_cast<uint4*>(&Wf[n * F_S + c4 * 8]) =
                *reinterpret_cast<const uint4*>(
                    &w1t[(size_t)(ch * 128 + n) * 128 + c4 * 8]);
        }
        __syncthreads();

        float acc1[32];
#pragma unroll
        for (int i = 0; i < 32; i++) acc1[i] = 0.f;

#pragma unroll
        for (int ks = 0; ks < 8; ks++) {
            int kb = ks * 16;
            uint32_t a0[4], a1[4];
            lda_h(a0, Af, F_S, m0,      kb, lane);
            lda_h(a1, Af, F_S, m0 + 16, kb, lane);
#pragma unroll
            for (int nt = 0; nt < 2; nt++) {
                mma_k16_n16_m32(&acc1[(nt*2+0)*4], &acc1[(nt*2+1)*4],
                                &acc1[(4+nt*2+0)*4], &acc1[(4+nt*2+1)*4],
                                a0, a1, Wf, F_S, n0 + nt * 16, kb, lane);
            }
        }

        // h = gelu(acc1 + b1) -> Hf
        {
            int r0 = lane >> 2;
#pragma unroll
            for (int mh = 0; mh < 2; mh++)
#pragma unroll
            for (int j = 0; j < 4; j++) {
                int col = n0 + j * 8 + 2 * (lane & 3);
                float bb0 = b1[ch * 128 + col];
                float bb1 = b1[ch * 128 + col + 1];
#pragma unroll
                for (int half = 0; half < 2; half++) {
                    int r = m0 + mh * 16 + r0 + half * 8;
                    float v0 = gelu_f(acc1[(mh*4+j)*4 + half*2 + 0] + bb0);
                    float v1 = gelu_f(acc1[(mh*4+j)*4 + half*2 + 1] + bb1);
                    *reinterpret_cast<__half2*>(&Hf[r * F_S + col]) =
                        __floats2half2_rn(v0, v1);
                }
            }
        }
        __syncthreads();

        // W2 chunk: w2t [128n][2048k], cols ch*128..
#pragma unroll
        for (int i = 0; i < 4; i++) {
            int p = tid + 512 * i;
            int n = p >> 4, c4 = p & 15;
            *reinterpret_cast<uint4*>(&Wf[n * F_S + c4 * 8]) =
                *reinterpret_cast<const uint4*>(
                    &w2t[(size_t)n * 2048 + ch * 128 + c4 * 8]);
        }
        __syncthreads();

#pragma unroll
        for (int ks = 0; ks < 8; ks++) {
            int kb = ks * 16;
            uint32_t a0[4], a1[4];
            lda_h(a0, Hf, F_S, m0,      kb, lane);
            lda_h(a1, Hf, F_S, m0 + 16, kb, lane);
#pragma unroll
            for (int nt = 0; nt < 2; nt++) {
                mma_k16_n16_m32(&acc2[(nt*2+0)*4], &acc2[(nt*2+1)*4],
                                &acc2[(4+nt*2+0)*4], &acc2[(4+nt*2+1)*4],
                                a0, a1, Wf, F_S, n0 + nt * 16, kb, lane);
            }
        }
        __syncthreads();
    }

    // epilogue: out = acc2 + b2 + xres
    {
        int r0 = lane >> 2;
#pragma unroll
        for (int mh = 0; mh < 2; mh++)
#pragma unroll
        for (int j = 0; j < 4; j++) {
            int col = n0 + j * 8 + 2 * (lane & 3);
            float bb0 = b2[col], bb1 = b2[col + 1];
#pragma unroll
            for (int half = 0; half < 2; half++) {
                size_t r = rowBase + m0 + mh * 16 + r0 + half * 8;
                float2 xr = *reinterpret_cast<const float2*>(&xres[r * 128 + col]);
                float2 o;
                o.x = acc2[(mh*4+j)*4 + half*2 + 0] + bb0 + xr.x;
                o.y = acc2[(mh*4+j)*4 + half*2 + 1] + bb1 + xr.y;
                *reinterpret_cast<float2*>(&out[r * 128 + col]) = o;
            }
        }
    }
}

// ---------------------------------------------------------------------------
// fp16 fused edge pipeline
// ---------------------------------------------------------------------------
constexpr int E_AS = 104;
constexpr int E_HS = 136;
constexpr size_t EDGE_SMEM = (size_t)(2 * 128 * E_AS) * 2;   // 53,248 B

__global__ void __launch_bounds__(512) edge_tc_k(
    const __half* __restrict__ nrm_h, const __half* __restrict__ ea_h,
    const int* __restrict__ srcI, const int* __restrict__ tgtI,
    const __half* __restrict__ ew1t, const float* __restrict__ e_b1,
    const __half* __restrict__ ew2t, const float* __restrict__ e_b2,
    const float* __restrict__ mask,
    float* __restrict__ msgs_out, float* __restrict__ agg)
{
    extern __shared__ __half she[];
    __half* Af = she;
    __half* Wf = Af + 128 * E_AS;
    __half* Hf  = she;                  // aliased phase 2
    __half* W2f = Hf + 128 * E_HS;

    __shared__ int   srcb[128], tgtb[128], tgtn[128];
    __shared__ float mks[128];

    const int tid  = threadIdx.x;
    const int lane = tid & 31;
    const int wrp  = tid >> 5;
    const int wm   = wrp & 7;
    const int wn   = wrp >> 3;
    const int m0   = wm * 16;
    const size_t rowBase = (size_t)blockIdx.x * 128;

    if (tid < 128) {
        size_t row = rowBase + tid;
        int b = (int)(row / CE);
        int e = (int)(row - (size_t)b * CE);
        srcb[tid] = (b * CN + srcI[e]) * CD;
        tgtb[tid] = (b * CN + tgtI[e]) * CD;
        tgtn[tid] = b * CN + tgtI[e];
        mks[tid]  = mask[row];
    }
    __syncthreads();

    float acc1[32];
#pragma unroll
    for (int i = 0; i < 32; i++) acc1[i] = 0.f;

    for (int ch = 0; ch < 3; ch++) {
        const int k0 = ch * 96;
        // A gathered: 128 rows x 12 uint4 (8-half groups never straddle sources)
#pragma unroll
        for (int i = 0; i < 3; i++) {
            int p = tid + 512 * i;
            int r = p / 12, j = p % 12;
            int gk = k0 + j * 8;
            uint4 v;
            if (gk < 128)
                v = *reinterpret_cast<const uint4*>(&nrm_h[srcb[r] + gk]);
            else if (gk < 256)
                v = *reinterpret_cast<const uint4*>(&nrm_h[tgtb[r] + gk - 128]);
            else
                v = *reinterpret_cast<const uint4*>(
                        &ea_h[(rowBase + r) * CED + gk - 256]);
            *reinterpret_cast<uint4*>(&Af[r * E_AS + j * 8]) = v;
        }
        // W1 chunk: ew1t [128n][288k], cols k0..k0+95
#pragma unroll
        for (int i = 0; i < 3; i++) {
            int p = tid + 512 * i;
            int n = p / 12, j = p % 12;
            *reinterpret_cast<uint4*>(&Wf[n * E_AS + j * 8]) =
                *reinterpret_cast<const uint4*>(&ew1t[(size_t)n * 288 + k0 + j * 8]);
        }
        __syncthreads();
#pragma unroll
        for (int ks = 0; ks < 6; ks++) {
            int kb = ks * 16;
            uint32_t a[4];
            lda_h(a, Af, E_AS, m0, kb, lane);
#pragma unroll
            for (int g = 0; g < 4; g++) {
                mma_k16_n16(&acc1[(g*2+0)*4], &acc1[(g*2+1)*4],
                            a, Wf, E_AS, wn * 64 + g * 16, kb, lane);
            }
        }
        __syncthreads();
    }

    // h = relu(acc1 + b1) -> Hf
    {
        int r0 = m0 + (lane >> 2);
#pragma unroll
        for (int t = 0; t < 8; t++) {
            int col = wn * 64 + t * 8 + 2 * (lane & 3);
            float bb0 = e_b1[col], bb1 = e_b1[col + 1];
#pragma unroll
            for (int half = 0; half < 2; half++) {
                int r = r0 + half * 8;
                float v0 = fmaxf(acc1[t * 4 + half * 2 + 0] + bb0, 0.f);
                float v1 = fmaxf(acc1[t * 4 + half * 2 + 1] + bb1, 0.f);
                *reinterpret_cast<__half2*>(&Hf[r * E_HS + col]) =
                    __floats2half2_rn(v0, v1);
            }
        }
    }
    // W2: ew2t [32n][128k] -> 512 uint4, 1 per thread
    {
        int n = tid >> 4, c4 = tid & 15;
        *reinterpret_cast<uint4*>(&W2f[n * E_HS + c4 * 8]) =
            *reinterpret_cast<const uint4*>(&ew2t[(size_t)n * 128 + c4 * 8]);
    }
    __syncthreads();

    float acc2[8];
#pragma unroll
    for (int i = 0; i < 8; i++) acc2[i] = 0.f;
#pragma unroll
    for (int ks = 0; ks < 8; ks++) {
        int kb = ks * 16;
        uint32_t a[4];
        lda_h(a, Hf, E_HS, m0, kb, lane);
        mma_k16_n16(&acc2[0], &acc2[4], a, W2f, E_HS, wn * 16, kb, lane);
    }

    {
        int r0 = m0 + (lane >> 2);
#pragma unroll
        for (int t = 0; t < 2; t++) {
            int col = wn * 16 + t * 8 + 2 * (lane & 3);
            float bb0 = e_b2[col], bb1 = e_b2[col + 1];
#pragma unroll
            for (int half = 0; half < 2; half++) {
                int r = r0 + half * 8;
                float mk = mks[r];
                float v0 = (acc2[t * 4 + half * 2 + 0] + bb0) * mk;
                float v1 = (acc2[t * 4 + half * 2 + 1] + bb1) * mk;
                size_t be = rowBase + r;
                msgs_out[be * 32 + col]     = v0;
                msgs_out[be * 32 + col + 1] = v1;
                float* ap = &agg[(size_t)tgtn[r] * CED + col];
                atomicAdd(ap, v0);
                atomicAdd(ap + 1, v1);
            }
        }
    }
}

// ---------------------------------------------------------------------------
// fp16 GRU GEMMs. RU: outputs r (half) + u (float). !RU: cand + GRU combine
// + LN2 -> x (float) + n2 (half).
// ---------------------------------------------------------------------------
constexpr int G_AS = 264;
constexpr int G_WS = 136;
constexpr size_t GRU_SMEM = (size_t)(128 * G_AS + 128 * G_WS) * 2;  // 102,400 B

template<bool RU>
__global__ void __launch_bounds__(512) gru_tc_k(
    const __half* __restrict__ a1h, const __half* __restrict__ rh,
    const __half* __restrict__ a3h,
    const __half* __restrict__ w0t, const float* __restrict__ b0p,
    const __half* __restrict__ w1t_, const float* __restrict__ b1p,
    void* out0v, void* out1v,
    const float* __restrict__ uu, const float* __restrict__ nfp,
    const float* __restrict__ nrm32,
    const float* __restrict__ g2, const float* __restrict__ bb2)
{
    extern __shared__ __half shg[];
    __half* Af = shg;
    __half* Wf = Af + 128 * G_AS;

    const int tid  = threadIdx.x;
    const int lane = tid & 31;
    const int wrp  = tid >> 5;
    const int wm   = wrp & 7;
    const int wn   = wrp >> 3;
    const int m0   = wm * 16;
    const size_t rowBase = (size_t)blockIdx.x * 128;

    // A fill: 4096 uint4 (8 per thread)
#pragma unroll
    for (int i = 0; i < 8; i++) {
        int p = tid + 512 * i;
        int r = p >> 5, q = p & 31;
        uint4 v;
        if (q < 16) {
            v = *reinterpret_cast<const uint4*>(&a1h[(rowBase + r) * 128 + q * 8]);
            if (!RU) {
                uint4 rv = *reinterpret_cast<const uint4*>(
                    &rh[(rowBase + r) * 128 + q * 8]);
                __half2* vp = reinterpret_cast<__half2*>(&v);
                const __half2* rp = reinterpret_cast<const __half2*>(&rv);
                vp[0] = __hmul2(vp[0], rp[0]);
                vp[1] = __hmul2(vp[1], rp[1]);
                vp[2] = __hmul2(vp[2], rp[2]);
                vp[3] = __hmul2(vp[3], rp[3]);
            }
        } else {
            v = *reinterpret_cast<const uint4*>(
                &a3h[(rowBase + r) * 128 + (q - 16) * 8]);
        }
        *reinterpret_cast<uint4*>(&Af[r * G_AS + q * 8]) = v;
    }
    __syncthreads();

    constexpr int NW = RU ? 2 : 1;
    float acc[NW][32];
#pragma unroll
    for (int s = 0; s < NW; s++)
#pragma unroll
        for (int i = 0; i < 32; i++) acc[s][i] = 0.f;

    for (int ws = 0; ws < NW; ws++) {
        const __half* wt = (ws == 0) ? w0t : w1t_;
        for (int kc = 0; kc < 2; kc++) {
            // W chunk: wt [128n][256k], cols kc*128..
#pragma unroll
            for (int i = 0; i < 4; i++) {
                int p = tid + 512 * i;
                int n = p >> 4, c4 = p & 15;
                *reinterpret_cast<uint4*>(&Wf[n * G_WS + c4 * 8]) =
                    *reinterpret_cast<const uint4*>(
                        &wt[(size_t)n * 256 + kc * 128 + c4 * 8]);
            }
            __syncthreads();
#pragma unroll
            for (int ks = 0; ks < 8; ks++) {
                int kb = ks * 16;
                uint32_t a[4];
                lda_h(a, Af, G_AS, m0, kc * 128 + kb, lane);
#pragma unroll
                for (int g = 0; g < 4; g++) {
                    mma_k16_n16(&acc[ws][(g*2+0)*4], &acc[ws][(g*2+1)*4],
                                a, Wf, G_WS, wn * 64 + g * 16, kb, lane);
                }
            }
            __syncthreads();
        }
    }

    if (RU) {
        __half* r_out = (__half*)out0v;
        float*  u_out = (float*)out1v;
        int r0 = m0 + (lane >> 2);
#pragma unroll
        for (int t = 0; t < 8; t++) {
            int col = wn * 64 + t * 8 + 2 * (lane & 3);
            float rb0 = b0p[col], rb1 = b0p[col + 1];
            float ub0 = b1p[col], ub1 = b1p[col + 1];
#pragma unroll
            for (int half = 0; half < 2; half++) {
                size_t r = rowBase + r0 + half * 8;
                float rv0 = 1.f / (1.f + expf(-(acc[0][t*4+half*2+0] + rb0)));
                float rv1 = 1.f / (1.f + expf(-(acc[0][t*4+half*2+1] + rb1)));
                float uv0 = 1.f / (1.f + expf(-(acc[1][t*4+half*2+0] + ub0)));
                float uv1 = 1.f / (1.f + expf(-(acc[1][t*4+half*2+1] + ub1)));
                *reinterpret_cast<__half2*>(&r_out[r * 128 + col]) =
                    __floats2half2_rn(rv0, rv1);
                float2 o; o.x = uv0; o.y = uv1;
                *reinterpret_cast<float2*>(&u_out[r * 128 + col]) = o;
            }
        }
    } else {
        float*  x_out  = (float*)out0v;
        __half* n2_out = (__half*)out1v;
        float* X = reinterpret_cast<float*>(shg);   // [128][132] floats
        int r0 = m0 + (lane >> 2);
#pragma unroll
        for (int t = 0; t < 8; t++) {
            int col = wn * 64 + t * 8 + 2 * (lane & 3);
            float bb0 = b0p[col], bb1 = b0p[col + 1];
#pragma unroll
            for (int half = 0; half < 2; half++) {
                int rl = r0 + half * 8;
                size_t gi = (rowBase + rl) * 128 + col;
                float c0 = tanhf(acc[0][t*4+half*2+0] + bb0);
                float c1 = tanhf(acc[0][t*4+half*2+1] + bb1);
                float2 uv  = *reinterpret_cast<const float2*>(&uu[gi]);
                float2 nv  = *reinterpret_cast<const float2*>(&nrm32[gi]);
                float2 nfv = *reinterpret_cast<const float2*>(&nfp[gi]);
                float x0 = nfv.x + (1.f - uv.x) * nv.x + uv.x * c0;
                float x1 = nfv.y + (1.f - uv.y) * nv.y + uv.y * c1;
                float2 xo; xo.x = x0; xo.y = x1;
                *reinterpret_cast<float2*>(&x_out[gi]) = xo;
                *reinterpret_cast<float2*>(&X[rl * 132 + col]) = xo;
            }
        }
        __syncthreads();
        // LN2: 4 threads per row
        {
            int row = tid >> 2, q = tid & 3;
            float vals[32];
            float s = 0.f;
#pragma unroll
            for (int i4 = 0; i4 < 8; i4++) {
                float4 v = *reinterpret_cast<const float4*>(&X[row * 132 + q * 32 + i4 * 4]);
                vals[i4*4+0] = v.x; vals[i4*4+1] = v.y;
                vals[i4*4+2] = v.z; vals[i4*4+3] = v.w;
                s += v.x + v.y + v.z + v.w;
            }
            s += __shfl_xor_sync(~0u, s, 1);
            s += __shfl_xor_sync(~0u, s, 2);
            float mean = s * (1.f / 128.f);
            float sq = 0.f;
#pragma unroll
            for (int i = 0; i < 32; i++) {
                float d = vals[i] - mean;
                sq += d * d;
            }
            sq += __shfl_xor_sync(~0u, sq, 1);
            sq += __shfl_xor_sync(~0u, sq, 2);
            float kq = rsqrtf(sq * (1.f / 128.f) + 1e-5f);
            size_t r = rowBase + row;
#pragma unroll
            for (int i4 = 0; i4 < 8; i4++) {
                int c0 = q * 32 + i4 * 4;
                float4 g4 = *reinterpret_cast<const float4*>(&g2[c0]);
                float4 b4 = *reinterpret_cast<const float4*>(&bb2[c0]);
                float o0 = (vals[i4*4+0] - mean) * kq * g4.x + b4.x;
                float o1 = (vals[i4*4+1] - mean) * kq * g4.y + b4.y;
                float o2 = (vals[i4*4+2] - mean) * kq * g4.z + b4.z;
                float o3 = (vals[i4*4+3] - mean) * kq * g4.w + b4.w;
                __half2* np = reinterpret_cast<__half2*>(&n2_out[r * 128 + c0]);
                np[0] = __floats2half2_rn(o0, o1);
                np[1] = __floats2half2_rn(o2, o3);
            }
        }
    }
}

// ---------------------------------------------------------------------------
// proj GEMM with fused count-normalization; fp16 output
// ---------------------------------------------------------------------------
__global__ void __launch_bounds__(256) gemm_proj_k(
    const float* __restrict__ agg, const float* __restrict__ counts,
    const float* __restrict__ W, const float* __restrict__ bias,
    __half* __restrict__ C)
{
    __shared__ float As[16][68];
    __shared__ float Bs[16][64];
    __shared__ float rcnt[64];

    const int tid = threadIdx.x;
    const int tx = tid & 15;
    const int ty = tid >> 4;
    const size_t rowBase = (size_t)blockIdx.y * 64;
    const int colBase = blockIdx.x * 64;

    if (tid < 64) rcnt[tid] = 1.f / fmaxf(counts[tid], 1.f);
    __syncthreads();

    float acc[4][4];
#pragma unroll
    for (int i = 0; i < 4; i++)
#pragma unroll
        for (int j = 0; j < 4; j++) acc[i][j] = 0.f;

    for (int k0 = 0; k0 < 32; k0 += 16) {
#pragma unroll
        for (int i = 0; i < 4; i++) {
            int e = tid + 256 * i;
            int r = e >> 4, c = e & 15;
            As[c][r] = agg[(rowBase + r) * 32 + k0 + c] * rcnt[r];
        }
#pragma unroll
        for (int i = 0; i < 4; i++) {
            int e = tid + 256 * i;
            int r = e >> 6, c = e & 63;
            Bs[r][c] = W[(size_t)(k0 + r) * CD + colBase + c];
        }
        __syncthreads();
#pragma unroll
        for (int k = 0; k < 16; k++) {
            float a[4], b[4];
#pragma unroll
            for (int i = 0; i < 4; i++) a[i] = As[k][ty + 16 * i];
#pragma unroll
            for (int j = 0; j < 4; j++) b[j] = Bs[k][tx + 16 * j];
#pragma unroll
            for (int i = 0; i < 4; i++)
#pragma unroll
                for (int j = 0; j < 4; j++)
                    acc[i][j] = fmaf(a[i], b[j], acc[i][j]);
        }
        __syncthreads();
    }

#pragma unroll
    for (int i = 0; i < 4; i++) {
        size_t r = rowBase + ty + 16 * i;
#pragma unroll
        for (int j = 0; j < 4; j++) {
            int c = colBase + tx + 16 * j;
            C[r * CD + c] = __float2half(acc[i][j] + bias[c]);
        }
    }
}

// ---------------------------------------------------------------------------
// LN1 (dual fp32 + fp16 output) + counts
// ---------------------------------------------------------------------------
__global__ void ln_k(const float* __restrict__ in, const float* __restrict__ g,
                     const float* __restrict__ bb, float* __restrict__ out,
                     __half* __restrict__ out_h)
{
    const int w = threadIdx.x >> 5;
    const int lane = threadIdx.x & 31;
    const size_t row = (size_t)blockIdx.x * 8 + w;
    float4 v = *reinterpret_cast<const float4*>(&in[row * 128 + lane * 4]);
    float s = v.x + v.y + v.z + v.w;
#pragma unroll
    for (int o = 16; o > 0; o >>= 1) s += __shfl_xor_sync(~0u, s, o);
    float mean = s * (1.f / 128.f);
    float dx = v.x - mean, dy = v.y - mean, dz = v.z - mean, dw = v.w - mean;
    float q = dx * dx + dy * dy + dz * dz + dw * dw;
#pragma unroll
    for (int o = 16; o > 0; o >>= 1) q += __shfl_xor_sync(~0u, q, o);
    float kq = rsqrtf(q * (1.f / 128.f) + 1e-5f);
    float4 g4 = *reinterpret_cast<const float4*>(&g[lane * 4]);
    float4 b4 = *reinterpret_cast<const float4*>(&bb[lane * 4]);
    float o0 = dx * kq * g4.x + b4.x;
    float o1 = dy * kq * g4.y + b4.y;
    float o2 = dz * kq * g4.z + b4.z;
    float o3 = dw * kq * g4.w + b4.w;
    float4 o; o.x = o0; o.y = o1; o.z = o2; o.w = o3;
    *reinterpret_cast<float4*>(&out[row * 128 + lane * 4]) = o;
    __half2* hp = reinterpret_cast<__half2*>(&out_h[row * 128 + lane * 4]);
    hp[0] = __floats2half2_rn(o0, o1);
    hp[1] = __floats2half2_rn(o2, o3);
}

__global__ void counts_k(const int* __restrict__ tgt, float* __restrict__ counts)
{
    int e = threadIdx.x;
    if (e < CE) atomicAdd(&counts[tgt[e]], 1.f);
}

// ---------------------------------------------------------------------------
extern "C" void kernel_launch(void* const* d_in, const int* in_sizes, int n_in,
                              void* d_out, int out_size)
{
    const float* nf        = (const float*)d_in[0];
    const float* edge_attr = (const float*)d_in[1];
    const int*   src       = (const int*)  d_in[2];
    const int*   tgt       = (const int*)  d_in[3];
    const float* mask      = (const float*)d_in[4];
    const float* e_w1   = (const float*)d_in[6];
    const float* e_b1   = (const float*)d_in[7];
    const float* e_w2   = (const float*)d_in[8];
    const float* e_b2   = (const float*)d_in[9];
    const float* proj_w = (const float*)d_in[10];
    const float* proj_b = (const float*)d_in[11];
    const float* r_w    = (const float*)d_in[12];
    const float* r_b    = (const float*)d_in[13];
    const float* u_w    = (const float*)d_in[14];
    const float* u_b    = (const float*)d_in[15];
    const float* c_w    = (const float*)d_in[16];
    const float* c_b    = (const float*)d_in[17];
    const float* n1_g   = (const float*)d_in[18];
    const float* n1_b   = (const float*)d_in[19];
    const float* n2_g   = (const float*)d_in[20];
    const float* n2_b   = (const float*)d_in[21];
    const float* f_w1   = (const float*)d_in[22];
    const float* f_b1   = (const float*)d_in[23];
    const float* f_w2   = (const float*)d_in[24];
    const float* f_b2   = (const float*)d_in[25];

    float* out_x    = (float*)d_out;
    float* out_msgs = out_x + SZ_NORMED;

    float *p_normed, *p_agg, *p_counts, *p_u, *p_x;
    __half *p_nh, *p_projh, *p_rh, *p_n2h, *p_eah;
    __half *p_w1t, *p_w2t, *p_ew1t, *p_ew2t, *p_rwt, *p_uwt, *p_cwt;
    cudaGetSymbolAddress((void**)&p_normed, g_normed);
    cudaGetSymbolAddress((void**)&p_agg,    g_agg);
    cudaGetSymbolAddress((void**)&p_counts, g_counts);
    cudaGetSymbolAddress((void**)&p_u,      g_u);
    cudaGetSymbolAddress((void**)&p_x,      g_x);
    cudaGetSymbolAddress((void**)&p_nh,     g_normed_h);
    cudaGetSymbolAddress((void**)&p_projh,  g_proj_h);
    cudaGetSymbolAddress((void**)&p_rh,     g_r_h);
    cudaGetSymbolAddress((void**)&p_n2h,    g_n2_h);
    cudaGetSymbolAddress((void**)&p_eah,    g_ea_h);
    cudaGetSymbolAddress((void**)&p_w1t,    g_w1t);
    cudaGetSymbolAddress((void**)&p_w2t,    g_w2t);
    cudaGetSymbolAddress((void**)&p_ew1t,   g_ew1t);
    cudaGetSymbolAddress((void**)&p_ew2t,   g_ew2t);
    cudaGetSymbolAddress((void**)&p_rwt,    g_rwt);
    cudaGetSymbolAddress((void**)&p_uwt,    g_uwt);
    cudaGetSymbolAddress((void**)&p_cwt,    g_cwt);

    cudaFuncSetAttribute(ffn_tc_k,  cudaFuncAttributeMaxDynamicSharedMemorySize, (int)FFN_SMEM);
    cudaFuncSetAttribute(edge_tc_k, cudaFuncAttributeMaxDynamicSharedMemorySize, (int)EDGE_SMEM);
    cudaFuncSetAttribute(gru_tc_k<true>,  cudaFuncAttributeMaxDynamicSharedMemorySize, (int)GRU_SMEM);
    cudaFuncSetAttribute(gru_tc_k<false>, cudaFuncAttributeMaxDynamicSharedMemorySize, (int)GRU_SMEM);

    cudaMemsetAsync(p_agg, 0, SZ_AGG * sizeof(float));
    cudaMemsetAsync(p_counts, 0, CN * sizeof(float));

    // prep: weight transposes + edge_attr conversion
    tr_h<<<(128*2048 + 255)/256, 256>>>(f_w1, p_w1t, 128, 2048);
    tr_h<<<(2048*128 + 255)/256, 256>>>(f_w2, p_w2t, 2048, 128);
    tr_h<<<(288*128 + 255)/256, 256>>>(e_w1, p_ew1t, 288, 128);
    tr_h<<<(128*32 + 255)/256, 256>>>(e_w2, p_ew2t, 128, 32);
    tr_h<<<(256*128 + 255)/256, 256>>>(r_w, p_rwt, 256, 128);
    tr_h<<<(256*128 + 255)/256, 256>>>(u_w, p_uwt, 256, 128);
    tr_h<<<(256*128 + 255)/256, 256>>>(c_w, p_cwt, 256, 128);
    cvt_h8<<<(unsigned)((ME * CED / 8 + 255) / 256), 256>>>(edge_attr, p_eah, ME * CED / 8);

    // 1. LN1 (fp32 + fp16 outputs)
    ln_k<<<(unsigned)(MN / 8), 256>>>(nf, n1_g, n1_b, p_normed, p_nh);

    // 2. counts
    counts_k<<<1, 128>>>(tgt, p_counts);

    // 3. edge pipeline
    edge_tc_k<<<(unsigned)(ME / 128), 512, EDGE_SMEM>>>(
        p_nh, p_eah, src, tgt, p_ew1t, e_b1, p_ew2t, e_b2, mask,
        out_msgs, p_agg);

    // 4. proj = (agg/cnt) @ proj_w + proj_b  (fp16 out)
    gemm_proj_k<<<dim3(2, (unsigned)(MN / 64)), 256>>>(
        p_agg, p_counts, proj_w, proj_b, p_projh);

    // 5. r (fp16), u (fp32)
    gru_tc_k<true><<<(unsigned)(MN / 128), 512, GRU_SMEM>>>(
        p_nh, nullptr, p_projh, p_rwt, r_b, p_uwt, u_b,
        p_rh, p_u, nullptr, nullptr, nullptr, nullptr, nullptr);

    // 6. cand + GRU combine + LN2 -> x (fp32), n2 (fp16)
    gru_tc_k<false><<<(unsigned)(MN / 128), 512, GRU_SMEM>>>(
        p_nh, p_rh, p_projh, p_cwt, c_b, nullptr, nullptr,
        p_x, p_n2h, p_u, nf, p_normed, n2_g, n2_b);

    // 7. fused FFN
    ffn_tc_k<<<(unsigned)(MN / 128), 512, FFN_SMEM>>>(
        p_n2h, p_w1t, f_b1, p_w2t, f_b2, p_x, out_x);
}

// round 13
// speedup vs baseline: 4.8276x; 1.0458x over previous
#include <cuda_runtime.h>
#include <cuda_fp16.h>
#include <math.h>
#include <stdint.h>

constexpr int CB  = 2048;
constexpr int CN  = 64;
constexpr int CE  = 126;
constexpr int CD  = 128;
constexpr int CED = 32;
constexpr int CF  = 2048;

constexpr size_t MN = (size_t)CB * CN;      // 131072
constexpr size_t ME = (size_t)CB * CE;      // 258048

constexpr size_t SZ_NORMED = MN * CD;
constexpr size_t SZ_AGG    = MN * CED;
constexpr size_t SZ_RUC    = MN * CD;

// fp32 scratch
__device__ float g_normed[SZ_NORMED];
__device__ float g_agg   [SZ_AGG];
__device__ float g_counts[CN];
__device__ float g_u     [SZ_RUC];
__device__ float g_x     [SZ_RUC];
// fp16 scratch
__device__ __half g_normed_h[SZ_NORMED];
__device__ __half g_r_h    [SZ_RUC];
__device__ __half g_n2_h   [SZ_RUC];
__device__ __half g_ea_h   [ME * CED];
// fp16 pre-transposed weights [n][k]
__device__ __half g_w1t [2048 * 128];
__device__ __half g_w2t [128 * 2048];
__device__ __half g_ew1t[128 * 288];
__device__ __half g_ew2t[32 * 128];
__device__ __half g_rwt [128 * 256];
__device__ __half g_uwt [128 * 256];
__device__ __half g_cwt [128 * 256];
__device__ __half g_pwt [128 * 32];

// ---------------------------------------------------------------------------
// Prep kernels
// ---------------------------------------------------------------------------
// Tiled transpose fp32 [R][C] -> fp16 [C][R]. R, C multiples of 32.
__global__ void tr_h(const float* __restrict__ src, __half* __restrict__ dst,
                     int R, int C)
{
    __shared__ __half t[32][40];
    int cb = blockIdx.x * 32, rb = blockIdx.y * 32;
    int tx = threadIdx.x, ty = threadIdx.y;   // 32 x 8
#pragma unroll
    for (int i = 0; i < 4; i++) {
        int r = rb + ty + i * 8;
        t[ty + i * 8][tx] = __float2half(src[(size_t)r * C + cb + tx]);
    }
    __syncthreads();
#pragma unroll
    for (int i = 0; i < 4; i++) {
        int c = cb + ty + i * 8;
        dst[(size_t)c * R + rb + tx] = t[tx][ty + i * 8];
    }
}

__global__ void cvt_h8(const float* __restrict__ s, __half* __restrict__ d,
                       size_t n8)
{
    size_t i = (size_t)blockIdx.x * blockDim.x + threadIdx.x;
    if (i >= n8) return;
    size_t b = i * 8;
    float4 v0 = *reinterpret_cast<const float4*>(&s[b]);
    float4 v1 = *reinterpret_cast<const float4*>(&s[b + 4]);
    __half2* dp = reinterpret_cast<__half2*>(&d[b]);
    dp[0] = __floats2half2_rn(v0.x, v0.y);
    dp[1] = __floats2half2_rn(v0.z, v0.w);
    dp[2] = __floats2half2_rn(v1.x, v1.y);
    dp[3] = __floats2half2_rn(v1.z, v1.w);
}

// ---------------------------------------------------------------------------
// fp16 m16n8k16 mma helpers
// ---------------------------------------------------------------------------
__device__ __forceinline__ void mma_f16(float* d, const uint32_t (&a)[4],
                                        const uint32_t (&b)[2])
{
    asm volatile(
        "mma.sync.aligned.m16n8k16.row.col.f32.f16.f16.f32 "
        "{%0,%1,%2,%3},{%4,%5,%6,%7},{%8,%9},{%0,%1,%2,%3};"
        : "+f"(d[0]), "+f"(d[1]), "+f"(d[2]), "+f"(d[3])
        : "r"(a[0]), "r"(a[1]), "r"(a[2]), "r"(a[3]), "r"(b[0]), "r"(b[1]));
}

__device__ __forceinline__ void lda_h(uint32_t (&a)[4], const __half* A, int S,
                                      int m0, int kb, int lane)
{
    int r = m0 + (lane >> 2);
    int c = kb + (lane & 3) * 2;
    a[0] = *reinterpret_cast<const uint32_t*>(&A[r * S + c]);
    a[1] = *reinterpret_cast<const uint32_t*>(&A[(r + 8) * S + c]);
    a[2] = *reinterpret_cast<const uint32_t*>(&A[r * S + c + 8]);
    a[3] = *reinterpret_cast<const uint32_t*>(&A[(r + 8) * S + c + 8]);
}

__device__ __forceinline__ void ldb_h(uint32_t (&b)[2], const __half* W, int S,
                                      int nb, int kb, int lane)
{
    int n = nb + (lane >> 2);
    int c = kb + (lane & 3) * 2;
    b[0] = *reinterpret_cast<const uint32_t*>(&W[n * S + c]);
    b[1] = *reinterpret_cast<const uint32_t*>(&W[n * S + c + 8]);
}

__device__ __forceinline__ void mma_k16_n16(float* d0, float* d1,
    const uint32_t (&a)[4], const __half* W, int S, int nb, int kb, int lane)
{
    uint32_t b[2];
    ldb_h(b, W, S, nb, kb, lane);     mma_f16(d0, a, b);
    ldb_h(b, W, S, nb + 8, kb, lane); mma_f16(d1, a, b);
}

__device__ __forceinline__ void mma_k16_n16_m32(float* d00, float* d01,
    float* d10, float* d11,
    const uint32_t (&a0)[4], const uint32_t (&a1)[4],
    const __half* W, int S, int nb, int kb, int lane)
{
    uint32_t b[2];
    ldb_h(b, W, S, nb, kb, lane);     mma_f16(d00, a0, b); mma_f16(d10, a1, b);
    ldb_h(b, W, S, nb + 8, kb, lane); mma_f16(d01, a0, b); mma_f16(d11, a1, b);
}

__device__ __forceinline__ float gelu_f(float v) {
    return 0.5f * v * (1.f + erff(v * 0.70710678118654752f));
}

// ---------------------------------------------------------------------------
// fp16 fused FFN (unchanged from R12)
// ---------------------------------------------------------------------------
constexpr int F_S = 136;
constexpr size_t FFN_SMEM = (size_t)3 * 128 * F_S * 2;      // 104,448 B

__global__ void __launch_bounds__(512) ffn_tc_k(
    const __half* __restrict__ n2h, const __half* __restrict__ w1t,
    const float* __restrict__ b1, const __half* __restrict__ w2t,
    const float* __restrict__ b2, const float* __restrict__ xres,
    float* __restrict__ out)
{
    extern __shared__ __half sh[];
    __half* Af = sh;
    __half* Hf = Af + 128 * F_S;
    __half* Wf = Hf + 128 * F_S;

    const int tid  = threadIdx.x;
    const int lane = tid & 31;
    const int wrp  = tid >> 5;
    const int m0   = (wrp & 3) * 32;
    const int n0   = (wrp >> 2) * 32;
    const size_t rowBase = (size_t)blockIdx.x * 128;

#pragma unroll
    for (int i = 0; i < 4; i++) {
        int p = tid + 512 * i;
        int r = p >> 4, c4 = p & 15;
        *reinterpret_cast<uint4*>(&Af[r * F_S + c4 * 8]) =
            *reinterpret_cast<const uint4*>(&n2h[(rowBase + r) * 128 + c4 * 8]);
    }

    float acc2[32];
#pragma unroll
    for (int i = 0; i < 32; i++) acc2[i] = 0.f;

    __syncthreads();

    for (int ch = 0; ch < 16; ch++) {
#pragma unroll
        for (int i = 0; i < 4; i++) {
            int p = tid + 512 * i;
            int n = p >> 4, c4 = p & 15;
            *reinterpret_cast<uint4*>(&Wf[n * F_S + c4 * 8]) =
                *reinterpret_cast<const uint4*>(
                    &w1t[(size_t)(ch * 128 + n) * 128 + c4 * 8]);
        }
        __syncthreads();

        float acc1[32];
#pragma unroll
        for (int i = 0; i < 32; i++) acc1[i] = 0.f;

#pragma unroll
        for (int ks = 0; ks < 8; ks++) {
            int kb = ks * 16;
            uint32_t a0[4], a1[4];
            lda_h(a0, Af, F_S, m0,      kb, lane);
            lda_h(a1, Af, F_S, m0 + 16, kb, lane);
#pragma unroll
            for (int nt = 0; nt < 2; nt++) {
                mma_k16_n16_m32(&acc1[(nt*2+0)*4], &acc1[(nt*2+1)*4],
                                &acc1[(4+nt*2+0)*4], &acc1[(4+nt*2+1)*4],
                                a0, a1, Wf, F_S, n0 + nt * 16, kb, lane);
            }
        }

        {
            int r0 = lane >> 2;
#pragma unroll
            for (int mh = 0; mh < 2; mh++)
#pragma unroll
            for (int j = 0; j < 4; j++) {
                int col = n0 + j * 8 + 2 * (lane & 3);
                float bb0 = b1[ch * 128 + col];
                float bb1 = b1[ch * 128 + col + 1];
#pragma unroll
                for (int half = 0; half < 2; half++) {
                    int r = m0 + mh * 16 + r0 + half * 8;
                    float v0 = gelu_f(acc1[(mh*4+j)*4 + half*2 + 0] + bb0);
                    float v1 = gelu_f(acc1[(mh*4+j)*4 + half*2 + 1] + bb1);
                    *reinterpret_cast<__half2*>(&Hf[r * F_S + col]) =
                        __floats2half2_rn(v0, v1);
                }
            }
        }
        __syncthreads();

#pragma unroll
        for (int i = 0; i < 4; i++) {
            int p = tid + 512 * i;
            int n = p >> 4, c4 = p & 15;
            *reinterpret_cast<uint4*>(&Wf[n * F_S + c4 * 8]) =
                *reinterpret_cast<const uint4*>(
                    &w2t[(size_t)n * 2048 + ch * 128 + c4 * 8]);
        }
        __syncthreads();

#pragma unroll
        for (int ks = 0; ks < 8; ks++) {
            int kb = ks * 16;
            uint32_t a0[4], a1[4];
            lda_h(a0, Hf, F_S, m0,      kb, lane);
            lda_h(a1, Hf, F_S, m0 + 16, kb, lane);
#pragma unroll
            for (int nt = 0; nt < 2; nt++) {
                mma_k16_n16_m32(&acc2[(nt*2+0)*4], &acc2[(nt*2+1)*4],
                                &acc2[(4+nt*2+0)*4], &acc2[(4+nt*2+1)*4],
                                a0, a1, Wf, F_S, n0 + nt * 16, kb, lane);
            }
        }
        __syncthreads();
    }

    {
        int r0 = lane >> 2;
#pragma unroll
        for (int mh = 0; mh < 2; mh++)
#pragma unroll
        for (int j = 0; j < 4; j++) {
            int col = n0 + j * 8 + 2 * (lane & 3);
            float bb0 = b2[col], bb1 = b2[col + 1];
#pragma unroll
            for (int half = 0; half < 2; half++) {
                size_t r = rowBase + m0 + mh * 16 + r0 + half * 8;
                float2 xr = *reinterpret_cast<const float2*>(&xres[r * 128 + col]);
                float2 o;
                o.x = acc2[(mh*4+j)*4 + half*2 + 0] + bb0 + xr.x;
                o.y = acc2[(mh*4+j)*4 + half*2 + 1] + bb1 + xr.y;
                *reinterpret_cast<float2*>(&out[r * 128 + col]) = o;
            }
        }
    }
}

// ---------------------------------------------------------------------------
// fp16 fused edge pipeline (unchanged from R12)
// ---------------------------------------------------------------------------
constexpr int E_AS = 104;
constexpr int E_HS = 136;
constexpr size_t EDGE_SMEM = (size_t)(2 * 128 * E_AS) * 2;   // 53,248 B

__global__ void __launch_bounds__(512) edge_tc_k(
    const __half* __restrict__ nrm_h, const __half* __restrict__ ea_h,
    const int* __restrict__ srcI, const int* __restrict__ tgtI,
    const __half* __restrict__ ew1t, const float* __restrict__ e_b1,
    const __half* __restrict__ ew2t, const float* __restrict__ e_b2,
    const float* __restrict__ mask,
    float* __restrict__ msgs_out, float* __restrict__ agg)
{
    extern __shared__ __half she[];
    __half* Af = she;
    __half* Wf = Af + 128 * E_AS;
    __half* Hf  = she;
    __half* W2f = Hf + 128 * E_HS;

    __shared__ int   srcb[128], tgtb[128], tgtn[128];
    __shared__ float mks[128];

    const int tid  = threadIdx.x;
    const int lane = tid & 31;
    const int wrp  = tid >> 5;
    const int wm   = wrp & 7;
    const int wn   = wrp >> 3;
    const int m0   = wm * 16;
    const size_t rowBase = (size_t)blockIdx.x * 128;

    if (tid < 128) {
        size_t row = rowBase + tid;
        int b = (int)(row / CE);
        int e = (int)(row - (size_t)b * CE);
        srcb[tid] = (b * CN + srcI[e]) * CD;
        tgtb[tid] = (b * CN + tgtI[e]) * CD;
        tgtn[tid] = b * CN + tgtI[e];
        mks[tid]  = mask[row];
    }
    __syncthreads();

    float acc1[32];
#pragma unroll
    for (int i = 0; i < 32; i++) acc1[i] = 0.f;

    for (int ch = 0; ch < 3; ch++) {
        const int k0 = ch * 96;
#pragma unroll
        for (int i = 0; i < 3; i++) {
            int p = tid + 512 * i;
            int r = p / 12, j = p % 12;
            int gk = k0 + j * 8;
            uint4 v;
            if (gk < 128)
                v = *reinterpret_cast<const uint4*>(&nrm_h[srcb[r] + gk]);
            else if (gk < 256)
                v = *reinterpret_cast<const uint4*>(&nrm_h[tgtb[r] + gk - 128]);
            else
                v = *reinterpret_cast<const uint4*>(
                        &ea_h[(rowBase + r) * CED + gk - 256]);
            *reinterpret_cast<uint4*>(&Af[r * E_AS + j * 8]) = v;
        }
#pragma unroll
        for (int i = 0; i < 3; i++) {
            int p = tid + 512 * i;
            int n = p / 12, j = p % 12;
            *reinterpret_cast<uint4*>(&Wf[n * E_AS + j * 8]) =
                *reinterpret_cast<const uint4*>(&ew1t[(size_t)n * 288 + k0 + j * 8]);
        }
        __syncthreads();
#pragma unroll
        for (int ks = 0; ks < 6; ks++) {
            int kb = ks * 16;
            uint32_t a[4];
            lda_h(a, Af, E_AS, m0, kb, lane);
#pragma unroll
            for (int g = 0; g < 4; g++) {
                mma_k16_n16(&acc1[(g*2+0)*4], &acc1[(g*2+1)*4],
                            a, Wf, E_AS, wn * 64 + g * 16, kb, lane);
            }
        }
        __syncthreads();
    }

    {
        int r0 = m0 + (lane >> 2);
#pragma unroll
        for (int t = 0; t < 8; t++) {
            int col = wn * 64 + t * 8 + 2 * (lane & 3);
            float bb0 = e_b1[col], bb1 = e_b1[col + 1];
#pragma unroll
            for (int half = 0; half < 2; half++) {
                int r = r0 + half * 8;
                float v0 = fmaxf(acc1[t * 4 + half * 2 + 0] + bb0, 0.f);
                float v1 = fmaxf(acc1[t * 4 + half * 2 + 1] + bb1, 0.f);
                *reinterpret_cast<__half2*>(&Hf[r * E_HS + col]) =
                    __floats2half2_rn(v0, v1);
            }
        }
    }
    {
        int n = tid >> 4, c4 = tid & 15;
        *reinterpret_cast<uint4*>(&W2f[n * E_HS + c4 * 8]) =
            *reinterpret_cast<const uint4*>(&ew2t[(size_t)n * 128 + c4 * 8]);
    }
    __syncthreads();

    float acc2[8];
#pragma unroll
    for (int i = 0; i < 8; i++) acc2[i] = 0.f;
#pragma unroll
    for (int ks = 0; ks < 8; ks++) {
        int kb = ks * 16;
        uint32_t a[4];
        lda_h(a, Hf, E_HS, m0, kb, lane);
        mma_k16_n16(&acc2[0], &acc2[4], a, W2f, E_HS, wn * 16, kb, lane);
    }

    {
        int r0 = m0 + (lane >> 2);
#pragma unroll
        for (int t = 0; t < 2; t++) {
            int col = wn * 16 + t * 8 + 2 * (lane & 3);
            float bb0 = e_b2[col], bb1 = e_b2[col + 1];
#pragma unroll
            for (int half = 0; half < 2; half++) {
                int r = r0 + half * 8;
                float mk = mks[r];
                float v0 = (acc2[t * 4 + half * 2 + 0] + bb0) * mk;
                float v1 = (acc2[t * 4 + half * 2 + 1] + bb1) * mk;
                size_t be = rowBase + r;
                msgs_out[be * 32 + col]     = v0;
                msgs_out[be * 32 + col + 1] = v1;
                float* ap = &agg[(size_t)tgtn[r] * CED + col];
                atomicAdd(ap, v0);
                atomicAdd(ap + 1, v1);
            }
        }
    }
}

// ---------------------------------------------------------------------------
// fp16 GRU GEMMs with fused proj pre-pass (proj never hits HBM).
// RU: outputs r (half) + u (float). !RU: cand + GRU combine + LN2.
// ---------------------------------------------------------------------------
constexpr int G_AS = 264;
constexpr int G_WS = 136;
constexpr int P_S  = 40;    // Aa/PW stride (halfs); 20 words -> conflict-free
constexpr size_t GRU_SMEM = (size_t)(128 * G_AS + 128 * G_WS) * 2;  // 102,400 B

template<bool RU>
__global__ void __launch_bounds__(512) gru_tc_k(
    const __half* __restrict__ a1h, const __half* __restrict__ rh,
    const float* __restrict__ agg, const float* __restrict__ counts,
    const __half* __restrict__ pwt, const float* __restrict__ proj_b,
    const __half* __restrict__ w0t, const float* __restrict__ b0p,
    const __half* __restrict__ w1t_, const float* __restrict__ b1p,
    void* out0v, void* out1v,
    const float* __restrict__ uu, const float* __restrict__ nfp,
    const float* __restrict__ nrm32,
    const float* __restrict__ g2, const float* __restrict__ bb2)
{
    extern __shared__ __half shg[];
    __half* Af = shg;                 // [128][264]
    __half* Wf = Af + 128 * G_AS;     // [128][136]; pre-pass aliases Aa/PW here
    __half* Aa = Wf;                  // [128][40]
    __half* PW = Wf + 128 * P_S;      // [128][40]
    __shared__ float rcnt_s[64];

    const int tid  = threadIdx.x;
    const int lane = tid & 31;
    const int wrp  = tid >> 5;
    const int wm   = wrp & 7;
    const int wn   = wrp >> 3;
    const int m0   = wm * 16;
    const size_t rowBase = (size_t)blockIdx.x * 128;

    // Af first half: [normed] (or [r*normed])
#pragma unroll
    for (int i = 0; i < 4; i++) {
        int p = tid + 512 * i;
        int r = p >> 4, q = p & 15;
        uint4 v = *reinterpret_cast<const uint4*>(&a1h[(rowBase + r) * 128 + q * 8]);
        if (!RU) {
            uint4 rv = *reinterpret_cast<const uint4*>(&rh[(rowBase + r) * 128 + q * 8]);
            __half2* vp = reinterpret_cast<__half2*>(&v);
            const __half2* rp = reinterpret_cast<const __half2*>(&rv);
            vp[0] = __hmul2(vp[0], rp[0]);
            vp[1] = __hmul2(vp[1], rp[1]);
            vp[2] = __hmul2(vp[2], rp[2]);
            vp[3] = __hmul2(vp[3], rp[3]);
        }
        *reinterpret_cast<uint4*>(&Af[r * G_AS + q * 8]) = v;
    }
    if (tid < 64) rcnt_s[tid] = 1.f / fmaxf(counts[tid], 1.f);
    __syncthreads();

    // Aa = agg * rcnt (fp16), PW = proj_w^T
#pragma unroll
    for (int i = 0; i < 8; i++) {
        int p = tid + 512 * i;
        int r = p >> 5, c = p & 31;
        Aa[r * P_S + c] =
            __float2half(agg[(rowBase + r) * 32 + c] * rcnt_s[r & 63]);
    }
#pragma unroll
    for (int i = 0; i < 8; i++) {
        int p = tid + 512 * i;
        int n = p >> 5, k = p & 31;
        PW[n * P_S + k] = pwt[n * 32 + k];
    }
    __syncthreads();

    // proj pre-pass: proj(128x128) = Aa @ PW^T, K=32 -> Af second half
    {
        float accp[32];
#pragma unroll
        for (int i = 0; i < 32; i++) accp[i] = 0.f;
#pragma unroll
        for (int ks = 0; ks < 2; ks++) {
            int kb = ks * 16;
            uint32_t a[4];
            lda_h(a, Aa, P_S, m0, kb, lane);
#pragma unroll
            for (int g = 0; g < 4; g++) {
                mma_k16_n16(&accp[(g*2+0)*4], &accp[(g*2+1)*4],
                            a, PW, P_S, wn * 64 + g * 16, kb, lane);
            }
        }
        int r0 = m0 + (lane >> 2);
#pragma unroll
        for (int t = 0; t < 8; t++) {
            int col = wn * 64 + t * 8 + 2 * (lane & 3);
            float pb0 = proj_b[col], pb1 = proj_b[col + 1];
#pragma unroll
            for (int half = 0; half < 2; half++) {
                int r = r0 + half * 8;
                float v0 = accp[t * 4 + half * 2 + 0] + pb0;
                float v1 = accp[t * 4 + half * 2 + 1] + pb1;
                *reinterpret_cast<__half2*>(&Af[r * G_AS + 128 + col]) =
                    __floats2half2_rn(v0, v1);
            }
        }
    }
    __syncthreads();

    constexpr int NW = RU ? 2 : 1;
    float acc[NW][32];
#pragma unroll
    for (int s = 0; s < NW; s++)
#pragma unroll
        for (int i = 0; i < 32; i++) acc[s][i] = 0.f;

    for (int ws = 0; ws < NW; ws++) {
        const __half* wt = (ws == 0) ? w0t : w1t_;
        for (int kc = 0; kc < 2; kc++) {
#pragma unroll
            for (int i = 0; i < 4; i++) {
                int p = tid + 512 * i;
                int n = p >> 4, c4 = p & 15;
                *reinterpret_cast<uint4*>(&Wf[n * G_WS + c4 * 8]) =
                    *reinterpret_cast<const uint4*>(
                        &wt[(size_t)n * 256 + kc * 128 + c4 * 8]);
            }
            __syncthreads();
#pragma unroll
            for (int ks = 0; ks < 8; ks++) {
                int kb = ks * 16;
                uint32_t a[4];
                lda_h(a, Af, G_AS, m0, kc * 128 + kb, lane);
#pragma unroll
                for (int g = 0; g < 4; g++) {
                    mma_k16_n16(&acc[ws][(g*2+0)*4], &acc[ws][(g*2+1)*4],
                                a, Wf, G_WS, wn * 64 + g * 16, kb, lane);
                }
            }
            __syncthreads();
        }
    }

    if (RU) {
        __half* r_out = (__half*)out0v;
        float*  u_out = (float*)out1v;
        int r0 = m0 + (lane >> 2);
#pragma unroll
        for (int t = 0; t < 8; t++) {
            int col = wn * 64 + t * 8 + 2 * (lane & 3);
            float rb0 = b0p[col], rb1 = b0p[col + 1];
            float ub0 = b1p[col], ub1 = b1p[col + 1];
#pragma unroll
            for (int half = 0; half < 2; half++) {
                size_t r = rowBase + r0 + half * 8;
                float rv0 = 1.f / (1.f + expf(-(acc[0][t*4+half*2+0] + rb0)));
                float rv1 = 1.f / (1.f + expf(-(acc[0][t*4+half*2+1] + rb1)));
                float uv0 = 1.f / (1.f + expf(-(acc[1][t*4+half*2+0] + ub0)));
                float uv1 = 1.f / (1.f + expf(-(acc[1][t*4+half*2+1] + ub1)));
                *reinterpret_cast<__half2*>(&r_out[r * 128 + col]) =
                    __floats2half2_rn(rv0, rv1);
                float2 o; o.x = uv0; o.y = uv1;
                *reinterpret_cast<float2*>(&u_out[r * 128 + col]) = o;
            }
        }
    } else {
        float*  x_out  = (float*)out0v;
        __half* n2_out = (__half*)out1v;
        float* X = reinterpret_cast<float*>(shg);   // [128][132] floats
        int r0 = m0 + (lane >> 2);
#pragma unroll
        for (int t = 0; t < 8; t++) {
            int col = wn * 64 + t * 8 + 2 * (lane & 3);
            float bb0 = b0p[col], bb1 = b0p[col + 1];
#pragma unroll
            for (int half = 0; half < 2; half++) {
                int rl = r0 + half * 8;
                size_t gi = (rowBase + rl) * 128 + col;
                float c0 = tanhf(acc[0][t*4+half*2+0] + bb0);
                float c1 = tanhf(acc[0][t*4+half*2+1] + bb1);
                float2 uv  = *reinterpret_cast<const float2*>(&uu[gi]);
                float2 nv  = *reinterpret_cast<const float2*>(&nrm32[gi]);
                float2 nfv = *reinterpret_cast<const float2*>(&nfp[gi]);
                float x0 = nfv.x + (1.f - uv.x) * nv.x + uv.x * c0;
                float x1 = nfv.y + (1.f - uv.y) * nv.y + uv.y * c1;
                float2 xo; xo.x = x0; xo.y = x1;
                *reinterpret_cast<float2*>(&x_out[gi]) = xo;
                *reinterpret_cast<float2*>(&X[rl * 132 + col]) = xo;
            }
        }
        __syncthreads();
        {
            int row = tid >> 2, q = tid & 3;
            float vals[32];
            float s = 0.f;
#pragma unroll
            for (int i4 = 0; i4 < 8; i4++) {
                float4 v = *reinterpret_cast<const float4*>(&X[row * 132 + q * 32 + i4 * 4]);
                vals[i4*4+0] = v.x; vals[i4*4+1] = v.y;
                vals[i4*4+2] = v.z; vals[i4*4+3] = v.w;
                s += v.x + v.y + v.z + v.w;
            }
            s += __shfl_xor_sync(~0u, s, 1);
            s += __shfl_xor_sync(~0u, s, 2);
            float mean = s * (1.f / 128.f);
            float sq = 0.f;
#pragma unroll
            for (int i = 0; i < 32; i++) {
                float d = vals[i] - mean;
                sq += d * d;
            }
            sq += __shfl_xor_sync(~0u, sq, 1);
            sq += __shfl_xor_sync(~0u, sq, 2);
            float kq = rsqrtf(sq * (1.f / 128.f) + 1e-5f);
            size_t r = rowBase + row;
#pragma unroll
            for (int i4 = 0; i4 < 8; i4++) {
                int c0 = q * 32 + i4 * 4;
                float4 g4 = *reinterpret_cast<const float4*>(&g2[c0]);
                float4 b4 = *reinterpret_cast<const float4*>(&bb2[c0]);
                float o0 = (vals[i4*4+0] - mean) * kq * g4.x + b4.x;
                float o1 = (vals[i4*4+1] - mean) * kq * g4.y + b4.y;
                float o2 = (vals[i4*4+2] - mean) * kq * g4.z + b4.z;
                float o3 = (vals[i4*4+3] - mean) * kq * g4.w + b4.w;
                __half2* np = reinterpret_cast<__half2*>(&n2_out[r * 128 + c0]);
                np[0] = __floats2half2_rn(o0, o1);
                np[1] = __floats2half2_rn(o2, o3);
            }
        }
    }
}

// ---------------------------------------------------------------------------
// LN1 (dual fp32 + fp16 output) + fused counts (block 0)
// ---------------------------------------------------------------------------
__global__ void ln_k(const float* __restrict__ in, const float* __restrict__ g,
                     const float* __restrict__ bb, float* __restrict__ out,
                     __half* __restrict__ out_h,
                     const int* __restrict__ tgt, float* __restrict__ counts)
{
    if (blockIdx.x == 0 && threadIdx.x < CE)
        atomicAdd(&counts[tgt[threadIdx.x]], 1.f);

    const int w = threadIdx.x >> 5;
    const int lane = threadIdx.x & 31;
    const size_t row = (size_t)blockIdx.x * 8 + w;
    float4 v = *reinterpret_cast<const float4*>(&in[row * 128 + lane * 4]);
    float s = v.x + v.y + v.z + v.w;
#pragma unroll
    for (int o = 16; o > 0; o >>= 1) s += __shfl_xor_sync(~0u, s, o);
    float mean = s * (1.f / 128.f);
    float dx = v.x - mean, dy = v.y - mean, dz = v.z - mean, dw = v.w - mean;
    float q = dx * dx + dy * dy + dz * dz + dw * dw;
#pragma unroll
    for (int o = 16; o > 0; o >>= 1) q += __shfl_xor_sync(~0u, q, o);
    float kq = rsqrtf(q * (1.f / 128.f) + 1e-5f);
    float4 g4 = *reinterpret_cast<const float4*>(&g[lane * 4]);
    float4 b4 = *reinterpret_cast<const float4*>(&bb[lane * 4]);
    float o0 = dx * kq * g4.x + b4.x;
    float o1 = dy * kq * g4.y + b4.y;
    float o2 = dz * kq * g4.z + b4.z;
    float o3 = dw * kq * g4.w + b4.w;
    float4 o; o.x = o0; o.y = o1; o.z = o2; o.w = o3;
    *reinterpret_cast<float4*>(&out[row * 128 + lane * 4]) = o;
    __half2* hp = reinterpret_cast<__half2*>(&out_h[row * 128 + lane * 4]);
    hp[0] = __floats2half2_rn(o0, o1);
    hp[1] = __floats2half2_rn(o2, o3);
}

// ---------------------------------------------------------------------------
extern "C" void kernel_launch(void* const* d_in, const int* in_sizes, int n_in,
                              void* d_out, int out_size)
{
    const float* nf        = (const float*)d_in[0];
    const float* edge_attr = (const float*)d_in[1];
    const int*   src       = (const int*)  d_in[2];
    const int*   tgt       = (const int*)  d_in[3];
    const float* mask      = (const float*)d_in[4];
    const float* e_w1   = (const float*)d_in[6];
    const float* e_b1   = (const float*)d_in[7];
    const float* e_w2   = (const float*)d_in[8];
    const float* e_b2   = (const float*)d_in[9];
    const float* proj_w = (const float*)d_in[10];
    const float* proj_b = (const float*)d_in[11];
    const float* r_w    = (const float*)d_in[12];
    const float* r_b    = (const float*)d_in[13];
    const float* u_w    = (const float*)d_in[14];
    const float* u_b    = (const float*)d_in[15];
    const float* c_w    = (const float*)d_in[16];
    const float* c_b    = (const float*)d_in[17];
    const float* n1_g   = (const float*)d_in[18];
    const float* n1_b   = (const float*)d_in[19];
    const float* n2_g   = (const float*)d_in[20];
    const float* n2_b   = (const float*)d_in[21];
    const float* f_w1   = (const float*)d_in[22];
    const float* f_b1   = (const float*)d_in[23];
    const float* f_w2   = (const float*)d_in[24];
    const float* f_b2   = (const float*)d_in[25];

    float* out_x    = (float*)d_out;
    float* out_msgs = out_x + SZ_NORMED;

    float *p_normed, *p_agg, *p_counts, *p_u, *p_x;
    __half *p_nh, *p_rh, *p_n2h, *p_eah;
    __half *p_w1t, *p_w2t, *p_ew1t, *p_ew2t, *p_rwt, *p_uwt, *p_cwt, *p_pwt;
    cudaGetSymbolAddress((void**)&p_normed, g_normed);
    cudaGetSymbolAddress((void**)&p_agg,    g_agg);
    cudaGetSymbolAddress((void**)&p_counts, g_counts);
    cudaGetSymbolAddress((void**)&p_u,      g_u);
    cudaGetSymbolAddress((void**)&p_x,      g_x);
    cudaGetSymbolAddress((void**)&p_nh,     g_normed_h);
    cudaGetSymbolAddress((void**)&p_rh,     g_r_h);
    cudaGetSymbolAddress((void**)&p_n2h,    g_n2_h);
    cudaGetSymbolAddress((void**)&p_eah,    g_ea_h);
    cudaGetSymbolAddress((void**)&p_w1t,    g_w1t);
    cudaGetSymbolAddress((void**)&p_w2t,    g_w2t);
    cudaGetSymbolAddress((void**)&p_ew1t,   g_ew1t);
    cudaGetSymbolAddress((void**)&p_ew2t,   g_ew2t);
    cudaGetSymbolAddress((void**)&p_rwt,    g_rwt);
    cudaGetSymbolAddress((void**)&p_uwt,    g_uwt);
    cudaGetSymbolAddress((void**)&p_cwt,    g_cwt);
    cudaGetSymbolAddress((void**)&p_pwt,    g_pwt);

    cudaFuncSetAttribute(ffn_tc_k,  cudaFuncAttributeMaxDynamicSharedMemorySize, (int)FFN_SMEM);
    cudaFuncSetAttribute(edge_tc_k, cudaFuncAttributeMaxDynamicSharedMemorySize, (int)EDGE_SMEM);
    cudaFuncSetAttribute(gru_tc_k<true>,  cudaFuncAttributeMaxDynamicSharedMemorySize, (int)GRU_SMEM);
    cudaFuncSetAttribute(gru_tc_k<false>, cudaFuncAttributeMaxDynamicSharedMemorySize, (int)GRU_SMEM);

    cudaMemsetAsync(p_agg, 0, SZ_AGG * sizeof(float));
    cudaMemsetAsync(p_counts, 0, CN * sizeof(float));

    // prep: tiled transposes (all dims multiples of 32) + edge_attr cvt
    dim3 tb(32, 8);
    tr_h<<<dim3(64, 4),  tb>>>(f_w1,   p_w1t,  128, 2048);
    tr_h<<<dim3(4, 64),  tb>>>(f_w2,   p_w2t,  2048, 128);
    tr_h<<<dim3(4, 9),   tb>>>(e_w1,   p_ew1t, 288, 128);
    tr_h<<<dim3(1, 4),   tb>>>(e_w2,   p_ew2t, 128, 32);
    tr_h<<<dim3(4, 8),   tb>>>(r_w,    p_rwt,  256, 128);
    tr_h<<<dim3(4, 8),   tb>>>(u_w,    p_uwt,  256, 128);
    tr_h<<<dim3(4, 8),   tb>>>(c_w,    p_cwt,  256, 128);
    tr_h<<<dim3(4, 1),   tb>>>(proj_w, p_pwt,  32, 128);
    cvt_h8<<<(unsigned)((ME * CED / 8 + 255) / 256), 256>>>(edge_attr, p_eah, ME * CED / 8);

    // 1. LN1 + counts
    ln_k<<<(unsigned)(MN / 8), 256>>>(nf, n1_g, n1_b, p_normed, p_nh, tgt, p_counts);

    // 2. edge pipeline
    edge_tc_k<<<(unsigned)(ME / 128), 512, EDGE_SMEM>>>(
        p_nh, p_eah, src, tgt, p_ew1t, e_b1, p_ew2t, e_b2, mask,
        out_msgs, p_agg);

    // 3. r (fp16), u (fp32)  [proj fused]
    gru_tc_k<true><<<(unsigned)(MN / 128), 512, GRU_SMEM>>>(
        p_nh, nullptr, p_agg, p_counts, p_pwt, proj_b,
        p_rwt, r_b, p_uwt, u_b, p_rh, p_u,
        nullptr, nullptr, nullptr, nullptr, nullptr);

    // 4. cand + GRU combine + LN2 -> x (fp32), n2 (fp16)  [proj fused]
    gru_tc_k<false><<<(unsigned)(MN / 128), 512, GRU_SMEM>>>(
        p_nh, p_rh, p_agg, p_counts, p_pwt, proj_b,
        p_cwt, c_b, nullptr, nullptr, p_x, p_n2h,
        p_u, nf, p_normed, n2_g, n2_b);

    // 5. fused FFN
    ffn_tc_k<<<(unsigned)(MN / 128), 512, FFN_SMEM>>>(
        p_n2h, p_w1t, f_b1, p_w2t, f_b2, p_x, out_x);
}